// round 2
// baseline (speedup 1.0000x reference)
#include <cuda_runtime.h>
#include <math.h>

#define BSZ 8
#define PP  16384          // points per batch
#define NPT (BSZ*PP)       // 131072
#define TOKD 768
#define MT  128
#define KNN 16
#define IHD 256

// ---------------- scratch (device globals; no allocation allowed) ----------------
__device__ float g_h1[(size_t)NPT*256];
__device__ float g_h2[(size_t)NPT*512];
__device__ float g_h3[(size_t)NPT*768];
__device__ float g_pf[(size_t)NPT*768];
__device__ float g_zin[(size_t)NPT*772];
__device__ float g_z1[(size_t)NPT*256];
__device__ float g_imp[NPT];
__device__ int   g_sel[BSZ*MT];
__device__ float g_pooled[(size_t)BSZ*MT*768];
__device__ float g_t1[(size_t)BSZ*MT*768];

// ---------------- packed f32x2 helpers ----------------
__device__ __forceinline__ void ffma2(unsigned long long &d,
                                      unsigned long long a,
                                      unsigned long long b) {
    asm("fma.rn.f32x2 %0, %1, %2, %0;" : "+l"(d) : "l"(a), "l"(b));
}
__device__ __forceinline__ unsigned long long dup2(float v) {
    unsigned long long r;
    unsigned u = __float_as_uint(v);
    asm("mov.b64 %0, {%1, %1};" : "=l"(r) : "r"(u));
    return r;
}
__device__ __forceinline__ float2 unpk(unsigned long long v) {
    float2 f;
    asm("mov.b64 {%0, %1}, %2;" : "=f"(f.x), "=f"(f.y) : "l"(v));
    return f;
}

// ---------------- FFMA2 tiled SGEMM: C = act(A @ W + bias) ----------------
// A: N x Kin (row-major), W: Kin x Kout (row-major), C: N x Kout
#define GBM 128
#define GBN 128
#define GBK 16
#define ASTR (2*GBM + 4)                 // duplicated-A row stride (floats)
#define SGEMM_SMEM ((2*GBK*ASTR + 2*GBK*GBN) * 4)   // 49664 bytes

extern __shared__ float smem_dyn[];

__global__ __launch_bounds__(256) void sgemm_bias_act(
    const float* __restrict__ A, const float* __restrict__ W,
    const float* __restrict__ bias, float* __restrict__ C,
    int N, int Kin, int Kout, int doRelu)
{
    float* As = smem_dyn;                     // [2][GBK][ASTR]  (values duplicated)
    float* Ws = smem_dyn + 2*GBK*ASTR;        // [2][GBK][GBN]
    const int bRow = blockIdx.y * GBM;
    const int bCol = blockIdx.x * GBN;
    const int tid  = threadIdx.x;
    const int tr = (tid >> 4) * 4;            // rows tr..tr+3 and tr+64..tr+67
    const int tc = (tid & 15) * 4;            // cols tc..tc+3 and tc+64..tc+67

    unsigned long long acc[8][4];
#pragma unroll
    for (int i = 0; i < 8; i++)
#pragma unroll
        for (int j = 0; j < 4; j++) acc[i][j] = 0ull;

    const int T = (Kin + GBK - 1) / GBK;
    float pa[8], pw[8];

    // ---- load tile 0 into regs ----
    {
        const int k0 = 0;
#pragma unroll
        for (int l = 0; l < 8; l++) {
            int e = tid + l * 256;
            int ar = e >> 4, ak = e & 15;
            int gk = k0 + ak;
            pa[l] = (gk < Kin) ? A[(size_t)(bRow + ar) * Kin + gk] : 0.f;
        }
#pragma unroll
        for (int l = 0; l < 8; l++) {
            int e = tid + l * 256;
            int wk = e >> 7, wc = e & 127;
            int gk = k0 + wk;
            pw[l] = (gk < Kin) ? W[(size_t)gk * Kout + bCol + wc] : 0.f;
        }
    }
    // ---- store tile 0 to smem buf 0 ----
    {
        float* Ab = As;
        float* Wb = Ws;
#pragma unroll
        for (int l = 0; l < 8; l++) {
            int e = tid + l * 256;
            int ar = e >> 4, ak = e & 15;
            *(unsigned long long*)&Ab[ak * ASTR + 2 * ar] = dup2(pa[l]);
        }
#pragma unroll
        for (int l = 0; l < 8; l++) {
            int e = tid + l * 256;
            int wk = e >> 7, wc = e & 127;
            Wb[wk * GBN + wc] = pw[l];
        }
    }
    __syncthreads();

    for (int t = 0; t < T; t++) {
        // prefetch tile t+1 into regs
        if (t + 1 < T) {
            const int k0 = (t + 1) * GBK;
#pragma unroll
            for (int l = 0; l < 8; l++) {
                int e = tid + l * 256;
                int ar = e >> 4, ak = e & 15;
                int gk = k0 + ak;
                pa[l] = (gk < Kin) ? A[(size_t)(bRow + ar) * Kin + gk] : 0.f;
            }
#pragma unroll
            for (int l = 0; l < 8; l++) {
                int e = tid + l * 256;
                int wk = e >> 7, wc = e & 127;
                int gk = k0 + wk;
                pw[l] = (gk < Kin) ? W[(size_t)gk * Kout + bCol + wc] : 0.f;
            }
        }
        // compute from buf t&1
        {
            const float* Ab = As + (t & 1) * GBK * ASTR;
            const float* Wb = Ws + (t & 1) * GBK * GBN;
#pragma unroll
            for (int kk = 0; kk < GBK; kk++) {
                ulonglong2 a01 = *(const ulonglong2*)&Ab[kk * ASTR + 2 * tr];
                ulonglong2 a23 = *(const ulonglong2*)&Ab[kk * ASTR + 2 * tr + 4];
                ulonglong2 a45 = *(const ulonglong2*)&Ab[kk * ASTR + 2 * tr + 128];
                ulonglong2 a67 = *(const ulonglong2*)&Ab[kk * ASTR + 2 * tr + 132];
                ulonglong2 w01 = *(const ulonglong2*)&Wb[kk * GBN + tc];
                ulonglong2 w23 = *(const ulonglong2*)&Wb[kk * GBN + tc + 64];
                unsigned long long av[8] = {a01.x, a01.y, a23.x, a23.y,
                                            a45.x, a45.y, a67.x, a67.y};
                unsigned long long wv[4] = {w01.x, w01.y, w23.x, w23.y};
#pragma unroll
                for (int i = 0; i < 8; i++)
#pragma unroll
                    for (int j = 0; j < 4; j++)
                        ffma2(acc[i][j], av[i], wv[j]);
            }
        }
        // store tile t+1 to other buffer
        if (t + 1 < T) {
            float* Ab = As + ((t + 1) & 1) * GBK * ASTR;
            float* Wb = Ws + ((t + 1) & 1) * GBK * GBN;
#pragma unroll
            for (int l = 0; l < 8; l++) {
                int e = tid + l * 256;
                int ar = e >> 4, ak = e & 15;
                *(unsigned long long*)&Ab[ak * ASTR + 2 * ar] = dup2(pa[l]);
            }
#pragma unroll
            for (int l = 0; l < 8; l++) {
                int e = tid + l * 256;
                int wk = e >> 7, wc = e & 127;
                Wb[wk * GBN + wc] = pw[l];
            }
            __syncthreads();
        }
    }

    // ---- epilogue ----
    float4 bias0 = *(const float4*)&bias[bCol + tc];
    float4 bias1 = *(const float4*)&bias[bCol + tc + 64];
#pragma unroll
    for (int i = 0; i < 8; i++) {
        int gr = bRow + tr + ((i < 4) ? i : (60 + i));
        if (gr >= N) continue;
        float2 p0 = unpk(acc[i][0]);
        float2 p1 = unpk(acc[i][1]);
        float2 p2 = unpk(acc[i][2]);
        float2 p3 = unpk(acc[i][3]);
        float4 v0 = make_float4(p0.x + bias0.x, p0.y + bias0.y,
                                p1.x + bias0.z, p1.y + bias0.w);
        float4 v1 = make_float4(p2.x + bias1.x, p2.y + bias1.y,
                                p3.x + bias1.z, p3.y + bias1.w);
        if (doRelu) {
            v0.x = fmaxf(v0.x, 0.f); v0.y = fmaxf(v0.y, 0.f);
            v0.z = fmaxf(v0.z, 0.f); v0.w = fmaxf(v0.w, 0.f);
            v1.x = fmaxf(v1.x, 0.f); v1.y = fmaxf(v1.y, 0.f);
            v1.z = fmaxf(v1.z, 0.f); v1.w = fmaxf(v1.w, 0.f);
        }
        *(float4*)&C[(size_t)gr * Kout + bCol + tc]      = v0;
        *(float4*)&C[(size_t)gr * Kout + bCol + tc + 64] = v1;
    }
}

// ---------------- concat [pf | coords4] -> zin (N x 772) ----------------
__global__ void concat_kernel(const float* __restrict__ pf,
                              const float* __restrict__ coords,
                              float* __restrict__ zin, size_t total)
{
    size_t i = (size_t)blockIdx.x * blockDim.x + threadIdx.x;
    if (i >= total) return;
    size_t n = i / 772;
    int    c = (int)(i - n * 772);
    zin[i] = (c < 768) ? pf[n * 768 + c]
                       : coords[n * 5 + 1 + (c - 768)];
}

// ---------------- fused LN + z@iw2 relu + @iw3 importance (f32x2) ----------------
#define IPTS 16
#define ZSTR 20
__global__ __launch_bounds__(256) void importance_kernel(
    const float* __restrict__ z1, const float* __restrict__ iw2,
    const float* __restrict__ ib2, const float* __restrict__ iw3,
    const float* __restrict__ ib3, const float* __restrict__ ln_g,
    const float* __restrict__ ln_b, float* __restrict__ imp)
{
    __shared__ float znt[IHD][ZSTR];   // transposed: [channel][point]
    __shared__ float red[IPTS][8];
    const int base = blockIdx.x * IPTS;
    const int tid  = threadIdx.x;
    const int w    = tid >> 5;
    const int lane = tid & 31;

    // LayerNorm: warp w handles points 2w and 2w+1
#pragma unroll
    for (int pp = 0; pp < 2; pp++) {
        int p = w * 2 + pp;
        float vals[8];
        float s = 0.f, s2 = 0.f;
#pragma unroll
        for (int j = 0; j < 8; j++) {
            float v = z1[(size_t)(base + p) * IHD + lane + j * 32];
            vals[j] = v; s += v; s2 += v * v;
        }
#pragma unroll
        for (int off = 16; off > 0; off >>= 1) {
            s  += __shfl_xor_sync(0xFFFFFFFFu, s,  off);
            s2 += __shfl_xor_sync(0xFFFFFFFFu, s2, off);
        }
        float mu  = s * (1.f / IHD);
        float var = s2 * (1.f / IHD) - mu * mu;
        float inv = rsqrtf(var + 1e-5f);
#pragma unroll
        for (int j = 0; j < 8; j++) {
            int c = lane + j * 32;
            znt[c][p] = (vals[j] - mu) * inv * ln_g[c] + ln_b[c];
        }
    }
    __syncthreads();

    // z2[t] for all IPTS points via packed f32x2; acc2[j] = points (2j, 2j+1)
    unsigned long long acc2[8];
    {
        float bv = ib2[tid];
        unsigned long long d = dup2(bv);
#pragma unroll
        for (int j = 0; j < 8; j++) acc2[j] = d;
    }
#pragma unroll 8
    for (int k = 0; k < IHD; k++) {
        unsigned long long wd = dup2(iw2[k * IHD + tid]);
        const ulonglong2* zp = (const ulonglong2*)&znt[k][0];  // 80B row stride, 16B aligned
        ulonglong2 z0 = zp[0], z1v = zp[1], z2v = zp[2], z3v = zp[3];
        ffma2(acc2[0], z0.x,  wd); ffma2(acc2[1], z0.y,  wd);
        ffma2(acc2[2], z1v.x, wd); ffma2(acc2[3], z1v.y, wd);
        ffma2(acc2[4], z2v.x, wd); ffma2(acc2[5], z2v.y, wd);
        ffma2(acc2[6], z3v.x, wd); ffma2(acc2[7], z3v.y, wd);
    }
    float w3v = iw3[tid];
#pragma unroll
    for (int p = 0; p < IPTS; p++) {
        float2 pr = unpk(acc2[p >> 1]);
        float v = (p & 1) ? pr.y : pr.x;
        v = fmaxf(v, 0.f) * w3v;
#pragma unroll
        for (int off = 16; off > 0; off >>= 1)
            v += __shfl_xor_sync(0xFFFFFFFFu, v, off);
        if (lane == 0) red[p][w] = v;
    }
    __syncthreads();
    if (tid < IPTS) {
        float s = 0.f;
#pragma unroll
        for (int ww = 0; ww < 8; ww++) s += red[tid][ww];
        imp[base + tid] = s + ib3[0];
    }
}

// ---------------- per-batch top-128 + sort by t + emit cents/masks ----------------
__global__ __launch_bounds__(1024) void topk_kernel(
    const float* __restrict__ imp, const float* __restrict__ coords,
    const float* __restrict__ noise, const float* __restrict__ log_temp,
    int* __restrict__ sel_out, float* __restrict__ out_cents,
    float* __restrict__ out_masks)
{
    extern __shared__ float pert[];     // PP floats
    __shared__ float rv[1024];
    __shared__ int   ri[1024];
    __shared__ float selT[MT];
    __shared__ int   selI[MT];
    const int b   = blockIdx.x;
    const int tid = threadIdx.x;

    float temp = fmaxf(expf(log_temp[0]), 0.1f);
    float itemp = 1.f / temp;
    for (int i = tid; i < PP; i += 1024)
        pert[i] = (imp[b * PP + i] + noise[b * PP + i]) * itemp;
    __syncthreads();

    for (int s = 0; s < MT; s++) {
        float best = -INFINITY; int bi = 0x7FFFFFFF;
        for (int i = tid; i < PP; i += 1024) {
            float v = pert[i];
            if (v > best) { best = v; bi = i; }
        }
        rv[tid] = best; ri[tid] = bi;
        __syncthreads();
        for (int off = 512; off > 0; off >>= 1) {
            if (tid < off) {
                float ov = rv[tid + off]; int oi = ri[tid + off];
                if (ov > rv[tid] || (ov == rv[tid] && oi < ri[tid])) {
                    rv[tid] = ov; ri[tid] = oi;
                }
            }
            __syncthreads();
        }
        if (tid == 0) {
            int idx = ri[0];
            selI[s] = idx;
            selT[s] = coords[((size_t)b * PP + idx) * 5 + 4];
            pert[idx] = -INFINITY;
        }
        __syncthreads();
    }

    // bitonic sort 128 selected by t ascending
    for (int kk = 2; kk <= MT; kk <<= 1) {
        for (int j = kk >> 1; j > 0; j >>= 1) {
            if (tid < MT) {
                int ixj = tid ^ j;
                if (ixj > tid) {
                    bool up = ((tid & kk) == 0);
                    float a = selT[tid], c = selT[ixj];
                    if ((a > c) == up) {
                        selT[tid] = c; selT[ixj] = a;
                        int t0 = selI[tid]; selI[tid] = selI[ixj]; selI[ixj] = t0;
                    }
                }
            }
            __syncthreads();
        }
    }

    if (tid < MT) {
        int idx = selI[tid];
        sel_out[b * MT + tid] = idx;
#pragma unroll
        for (int c = 0; c < 4; c++)
            out_cents[((size_t)b * MT + tid) * 4 + c] =
                coords[((size_t)b * PP + idx) * 5 + 1 + c];
        out_masks[b * MT + tid] = 1.0f;
    }
}

// ---------------- per-centroid 16-NN + max-pool of pf ----------------
__global__ __launch_bounds__(256) void knn_pool_kernel(
    const int* __restrict__ sel, const float* __restrict__ coords,
    const float* __restrict__ pf, float* __restrict__ pooled)
{
    extern __shared__ float d2[];   // PP floats
    __shared__ float rv[256];
    __shared__ int   ri[256];
    __shared__ int   knn[KNN];
    const int g   = blockIdx.x;     // b*MT + r
    const int b   = g >> 7;
    const int tid = threadIdx.x;

    int ci = sel[g];
    const float* cp = &coords[((size_t)b * PP + ci) * 5 + 1];
    float cx = cp[0], cy = cp[1], cz = cp[2], ct = cp[3];

    for (int i = tid; i < PP; i += 256) {
        const float* p = &coords[((size_t)b * PP + i) * 5 + 1];
        float dx = p[0] - cx, dy = p[1] - cy, dz = p[2] - cz, dt = p[3] - ct;
        d2[i] = dx * dx + dy * dy + dz * dz + dt * dt;
    }
    __syncthreads();

    for (int s = 0; s < KNN; s++) {
        float best = INFINITY; int bi = 0x7FFFFFFF;
        for (int i = tid; i < PP; i += 256) {
            float v = d2[i];
            if (v < best) { best = v; bi = i; }
        }
        rv[tid] = best; ri[tid] = bi;
        __syncthreads();
        for (int off = 128; off > 0; off >>= 1) {
            if (tid < off) {
                float ov = rv[tid + off]; int oi = ri[tid + off];
                if (ov < rv[tid] || (ov == rv[tid] && oi < ri[tid])) {
                    rv[tid] = ov; ri[tid] = oi;
                }
            }
            __syncthreads();
        }
        if (tid == 0) { knn[s] = ri[0]; d2[ri[0]] = INFINITY; }
        __syncthreads();
    }

    for (int j = tid; j < TOKD; j += 256) {
        float m = -INFINITY;
#pragma unroll
        for (int s = 0; s < KNN; s++)
            m = fmaxf(m, pf[((size_t)b * PP + knn[s]) * TOKD + j]);
        pooled[(size_t)g * TOKD + j] = m;
    }
}

// ---------------- launch ----------------
extern "C" void kernel_launch(void* const* d_in, const int* in_sizes, int n_in,
                              void* d_out, int out_size)
{
    const float* coords   = (const float*)d_in[0];
    const float* feats    = (const float*)d_in[1];
    const float* log_temp = (const float*)d_in[2];
    const float* w1 = (const float*)d_in[3];  const float* b1 = (const float*)d_in[4];
    const float* w2 = (const float*)d_in[5];  const float* b2 = (const float*)d_in[6];
    const float* w3 = (const float*)d_in[7];  const float* b3 = (const float*)d_in[8];
    const float* w4 = (const float*)d_in[9];  const float* b4 = (const float*)d_in[10];
    const float* iw1 = (const float*)d_in[11]; const float* ib1 = (const float*)d_in[12];
    const float* ln_g = (const float*)d_in[13]; const float* ln_b = (const float*)d_in[14];
    const float* iw2 = (const float*)d_in[15]; const float* ib2 = (const float*)d_in[16];
    const float* iw3 = (const float*)d_in[17]; const float* ib3 = (const float*)d_in[18];
    const float* nw1 = (const float*)d_in[19]; const float* nb1 = (const float*)d_in[20];
    const float* nw2 = (const float*)d_in[21]; const float* nb2 = (const float*)d_in[22];
    const float* noise = (const float*)d_in[23];

    float* out        = (float*)d_out;
    float* out_tokens = out;
    float* out_cents  = out + (size_t)BSZ * MT * TOKD;
    float* out_masks  = out_cents + (size_t)BSZ * MT * 4;

    float *h1, *h2, *h3, *pf, *zin, *z1, *imp, *pooled, *t1;
    int* sel;
    cudaGetSymbolAddress((void**)&h1,  g_h1);
    cudaGetSymbolAddress((void**)&h2,  g_h2);
    cudaGetSymbolAddress((void**)&h3,  g_h3);
    cudaGetSymbolAddress((void**)&pf,  g_pf);
    cudaGetSymbolAddress((void**)&zin, g_zin);
    cudaGetSymbolAddress((void**)&z1,  g_z1);
    cudaGetSymbolAddress((void**)&imp, g_imp);
    cudaGetSymbolAddress((void**)&sel, g_sel);
    cudaGetSymbolAddress((void**)&pooled, g_pooled);
    cudaGetSymbolAddress((void**)&t1,  g_t1);

    cudaFuncSetAttribute(sgemm_bias_act,
        cudaFuncAttributeMaxDynamicSharedMemorySize, SGEMM_SMEM);
    cudaFuncSetAttribute(topk_kernel,
        cudaFuncAttributeMaxDynamicSharedMemorySize, PP * sizeof(float));
    cudaFuncSetAttribute(knn_pool_kernel,
        cudaFuncAttributeMaxDynamicSharedMemorySize, PP * sizeof(float));

    dim3 blk(256);
    // 1-4: point MLP
    sgemm_bias_act<<<dim3(256/GBN, NPT/GBM), blk, SGEMM_SMEM>>>(
        feats, w1, b1, h1, NPT, 6, 256, 1);
    sgemm_bias_act<<<dim3(512/GBN, NPT/GBM), blk, SGEMM_SMEM>>>(
        h1, w2, b2, h2, NPT, 256, 512, 1);
    sgemm_bias_act<<<dim3(768/GBN, NPT/GBM), blk, SGEMM_SMEM>>>(
        h2, w3, b3, h3, NPT, 512, 768, 1);
    sgemm_bias_act<<<dim3(768/GBN, NPT/GBM), blk, SGEMM_SMEM>>>(
        h3, w4, b4, pf, NPT, 768, 768, 0);
    // 5: concat
    {
        size_t total = (size_t)NPT * 772;
        concat_kernel<<<(unsigned)((total + 255) / 256), 256>>>(pf, coords, zin, total);
    }
    // 6: importance layer 1
    sgemm_bias_act<<<dim3(256/GBN, NPT/GBM), blk, SGEMM_SMEM>>>(
        zin, iw1, ib1, z1, NPT, 772, 256, 1);
    // 7: fused LN + mlp + importance score
    importance_kernel<<<NPT / IPTS, 256>>>(z1, iw2, ib2, iw3, ib3, ln_g, ln_b, imp);
    // 8: per-batch top-128 + sort by t + cents/masks out
    topk_kernel<<<BSZ, 1024, PP * sizeof(float)>>>(
        imp, coords, noise, log_temp, sel, out_cents, out_masks);
    // 9: knn + max pool
    knn_pool_kernel<<<BSZ * MT, 256, PP * sizeof(float)>>>(sel, coords, pf, pooled);
    // 10-11: token MLP (rows already in output order)
    sgemm_bias_act<<<dim3(768/GBN, (BSZ*MT)/GBM), blk, SGEMM_SMEM>>>(
        pooled, nw1, nb1, t1, BSZ * MT, 768, 768, 1);
    sgemm_bias_act<<<dim3(768/GBN, (BSZ*MT)/GBM), blk, SGEMM_SMEM>>>(
        t1, nw2, nb2, out_tokens, BSZ * MT, 768, 768, 0);
}

// round 5
// speedup vs baseline: 2.6679x; 2.6679x over previous
#include <cuda_runtime.h>
#include <cuda_bf16.h>
#include <math.h>
#include <stdint.h>

#define BSZ 8
#define PP  16384
#define NPT (BSZ*PP)       // 131072
#define TOKD 768
#define MT  128
#define KNN 16
#define IHD 256
#define ZK  832            // zin padded K (772 -> 13*64)

typedef __nv_bfloat16 bf16;

// ---------------- scratch (device globals) ----------------
__device__ bf16  g_h1h[(size_t)NPT*256];
__device__ bf16  g_h1l[(size_t)NPT*256];
__device__ bf16  g_h2h[(size_t)NPT*512];
__device__ bf16  g_h2l[(size_t)NPT*512];
__device__ bf16  g_h3h[(size_t)NPT*768];
__device__ bf16  g_h3l[(size_t)NPT*768];
__device__ bf16  g_zinh[(size_t)NPT*ZK];
__device__ bf16  g_zinl[(size_t)NPT*ZK];
__device__ float g_pf[(size_t)NPT*768];
__device__ float g_z1[(size_t)NPT*256];
__device__ float g_imp[NPT];
__device__ int   g_sel[BSZ*MT];
__device__ float g_pooled[(size_t)BSZ*MT*768];
__device__ float g_t1[(size_t)BSZ*MT*768];
// transposed split weights: layout [Kout][Kpad]
__device__ bf16  g_w2h[512*256],  g_w2l[512*256];
__device__ bf16  g_w3h[768*512],  g_w3l[768*512];
__device__ bf16  g_w4h[768*768],  g_w4l[768*768];
__device__ bf16  g_iw1h[256*ZK],  g_iw1l[256*ZK];

// ---------------- PTX helpers (baseline ISA only) ----------------
__device__ __forceinline__ uint32_t smem_u32(const void* p) {
    uint32_t a;
    asm("{ .reg .u64 t; cvta.to.shared.u64 t, %1; cvt.u32.u64 %0, t; }"
        : "=r"(a) : "l"(p));
    return a;
}
__device__ __forceinline__ void cp16(uint32_t dst, const void* src) {
    asm volatile("cp.async.cg.shared.global [%0], [%1], 16;"
        :: "r"(dst), "l"(src) : "memory");
}
__device__ __forceinline__ void cp_commit() {
    asm volatile("cp.async.commit_group;" ::: "memory");
}
__device__ __forceinline__ void cp_wait1() {
    asm volatile("cp.async.wait_group 1;" ::: "memory");
}
__device__ __forceinline__ void cp_wait0() {
    asm volatile("cp.async.wait_group 0;" ::: "memory");
}
__device__ __forceinline__ void ldsm4(uint32_t* r, uint32_t a) {
    asm volatile("ldmatrix.sync.aligned.m8n8.x4.shared.b16 {%0,%1,%2,%3}, [%4];"
        : "=r"(r[0]), "=r"(r[1]), "=r"(r[2]), "=r"(r[3]) : "r"(a));
}
__device__ __forceinline__ void mma16816(float* d, const uint32_t* a, const uint32_t* b) {
    asm volatile("mma.sync.aligned.m16n8k16.row.col.f32.bf16.bf16.f32 "
        "{%0,%1,%2,%3}, {%4,%5,%6,%7}, {%8,%9}, {%0,%1,%2,%3};"
        : "+f"(d[0]), "+f"(d[1]), "+f"(d[2]), "+f"(d[3])
        : "r"(a[0]), "r"(a[1]), "r"(a[2]), "r"(a[3]), "r"(b[0]), "r"(b[1]));
}
__device__ __forceinline__ void split_bf16(float v, bf16& h, bf16& l) {
    h = __float2bfloat16(v);
    l = __float2bfloat16(v - __bfloat162float(h));
}

// ---------------- mma.sync split-bf16 GEMM ----------------
// C[N x Kout] = act((Ah+Al)[N x Kpad] @ ((Bh+Bl)[Kout x Kpad])^T + bias)
// drop Al*Bl term (error ~2^-18)
#define TILE_B   16384          // one 128x64 bf16 tile, SW128-swizzled
#define STAGE_B  (4*TILE_B)     // Ah, Al, Bh, Bl
#define MMA_SMEM (1024 + 2*STAGE_B)

extern __shared__ char smem_dyn_c[];

// issue cp.async for one 128x64 tile (K-chunk kc) with SW128 swizzle
__device__ __forceinline__ void tile_cp(const bf16* __restrict__ src, int rowBase,
                                        int Kstride, int kc, uint32_t dstBase, int tid)
{
#pragma unroll
    for (int j = 0; j < 4; j++) {
        int i = tid + j * 256;
        int r = i >> 3, ck = i & 7;
        const bf16* s = src + (size_t)(rowBase + r) * Kstride + kc * 64 + ck * 8;
        uint32_t off = (uint32_t)(r * 128 + ((ck * 16) ^ ((r & 7) << 4)));
        cp16(dstBase + off, s);
    }
}

__global__ __launch_bounds__(256)
void mma_gemm(const bf16* __restrict__ Ah, const bf16* __restrict__ Al,
              const bf16* __restrict__ Bh, const bf16* __restrict__ Bl,
              const float* __restrict__ bias,
              float* __restrict__ Cf, bf16* __restrict__ Ch, bf16* __restrict__ Cl,
              int Kpad, int Kout, int doRelu)
{
    char* smem = smem_dyn_c;
    const uint32_t sbase = smem_u32(smem);
    float* Sb = (float*)smem;                    // 128 bias floats (first 512B)
    const uint32_t tiles0 = sbase + 1024;
    const int tid  = threadIdx.x;
    const int wid  = tid >> 5;
    const int lane = tid & 31;
    const int wm   = wid >> 2;                   // 0..1  (64 rows each)
    const int wn   = wid & 3;                    // 0..3  (32 cols each)
    const int bRow = blockIdx.y * 128;
    const int bCol = blockIdx.x * 128;

    if (tid < 128) Sb[tid] = bias[bCol + tid];

    // per-lane ldmatrix byte offsets (within a tile)
    uint32_t aOff[4], bOff[2];
    {
        int khalfA = ((lane >> 4) & 1) * 16;     // bytes
#pragma unroll
        for (int mf = 0; mf < 4; mf++) {
            int r = wm * 64 + mf * 16 + ((lane >> 3) & 1) * 8 + (lane & 7);
            aOff[mf] = (uint32_t)(r * 128 + (khalfA ^ ((r & 7) << 4)));
        }
        int khalfB = ((lane >> 3) & 1) * 16;
#pragma unroll
        for (int nb = 0; nb < 2; nb++) {
            int r = wn * 32 + nb * 16 + ((lane >> 4) & 1) * 8 + (lane & 7);
            bOff[nb] = (uint32_t)(r * 128 + (khalfB ^ ((r & 7) << 4)));
        }
    }

    float acc[4][4][4];
#pragma unroll
    for (int i = 0; i < 4; i++)
#pragma unroll
        for (int j = 0; j < 4; j++)
#pragma unroll
            for (int c = 0; c < 4; c++) acc[i][j][c] = 0.f;

    const int T = Kpad / 64;

    // prologue: stage 0 <- chunk 0
    tile_cp(Ah, bRow, Kpad, 0, tiles0,             tid);
    tile_cp(Al, bRow, Kpad, 0, tiles0 + TILE_B,    tid);
    tile_cp(Bh, bCol, Kpad, 0, tiles0 + 2*TILE_B,  tid);
    tile_cp(Bl, bCol, Kpad, 0, tiles0 + 3*TILE_B,  tid);
    cp_commit();

    for (int t = 0; t < T; t++) {
        __syncthreads();   // prev compute done before overwriting its buffer
        if (t + 1 < T) {
            uint32_t st = tiles0 + ((t + 1) & 1) * STAGE_B;
            tile_cp(Ah, bRow, Kpad, t + 1, st,            tid);
            tile_cp(Al, bRow, Kpad, t + 1, st + TILE_B,   tid);
            tile_cp(Bh, bCol, Kpad, t + 1, st + 2*TILE_B, tid);
            tile_cp(Bl, bCol, Kpad, t + 1, st + 3*TILE_B, tid);
            cp_commit();
            cp_wait1();
        } else {
            cp_wait0();
        }
        __syncthreads();

        const uint32_t st = tiles0 + (t & 1) * STAGE_B;
        const uint32_t tAh = st, tAl = st + TILE_B, tBh = st + 2*TILE_B, tBl = st + 3*TILE_B;

        // 3 passes: (Ah,Bh), (Ah,Bl), (Al,Bh)
#pragma unroll
        for (int pass = 0; pass < 3; pass++) {
            const uint32_t At = (pass == 2) ? tAl : tAh;
            const uint32_t Bt = (pass == 1) ? tBl : tBh;
#pragma unroll
            for (int ks = 0; ks < 4; ks++) {
                const uint32_t kx = (uint32_t)(ks << 5);
                uint32_t af[4][4], bfr[2][4];
#pragma unroll
                for (int mf = 0; mf < 4; mf++) ldsm4(af[mf], At + (aOff[mf] ^ kx));
#pragma unroll
                for (int nb = 0; nb < 2; nb++) ldsm4(bfr[nb], Bt + (bOff[nb] ^ kx));
#pragma unroll
                for (int mf = 0; mf < 4; mf++)
#pragma unroll
                    for (int nf = 0; nf < 4; nf++)
                        mma16816(acc[mf][nf], af[mf], &bfr[nf >> 1][(nf & 1) * 2]);
            }
        }
    }

    // ---- epilogue ----
#pragma unroll
    for (int mf = 0; mf < 4; mf++) {
        int r0 = bRow + wm * 64 + mf * 16 + (lane >> 2);
#pragma unroll
        for (int nf = 0; nf < 4; nf++) {
            int cloc = wn * 32 + nf * 8 + (lane & 3) * 2;
            int c0 = bCol + cloc;
            float b0 = Sb[cloc], b1 = Sb[cloc + 1];
            float v0 = acc[mf][nf][0] + b0;
            float v1 = acc[mf][nf][1] + b1;
            float v2 = acc[mf][nf][2] + b0;
            float v3 = acc[mf][nf][3] + b1;
            if (doRelu) {
                v0 = fmaxf(v0, 0.f); v1 = fmaxf(v1, 0.f);
                v2 = fmaxf(v2, 0.f); v3 = fmaxf(v3, 0.f);
            }
            size_t o0 = (size_t)r0 * Kout + c0;
            size_t o1 = (size_t)(r0 + 8) * Kout + c0;
            if (Cf) {
                *(float2*)&Cf[o0] = make_float2(v0, v1);
                *(float2*)&Cf[o1] = make_float2(v2, v3);
            }
            if (Ch) {
                bf16 h0, l0, h1, l1;
                split_bf16(v0, h0, l0); split_bf16(v1, h1, l1);
                __nv_bfloat162 hp, lp;
                hp.x = h0; hp.y = h1; lp.x = l0; lp.y = l1;
                *(__nv_bfloat162*)&Ch[o0] = hp;
                *(__nv_bfloat162*)&Cl[o0] = lp;
                split_bf16(v2, h0, l0); split_bf16(v3, h1, l1);
                hp.x = h0; hp.y = h1; lp.x = l0; lp.y = l1;
                *(__nv_bfloat162*)&Ch[o1] = hp;
                *(__nv_bfloat162*)&Cl[o1] = lp;
            }
        }
    }
}

// ---------------- weight split (transpose + pad + bf16 hi/lo) ----------------
__global__ void w_split(const float* __restrict__ W, bf16* __restrict__ hi,
                        bf16* __restrict__ lo, int Kin, int Kout, int Kpad)
{
    int id = blockIdx.x * 256 + threadIdx.x;
    if (id >= Kout * Kpad) return;
    int n = id / Kpad, k = id - n * Kpad;
    float v = (k < Kin) ? W[(size_t)k * Kout + n] : 0.f;
    bf16 h, l; split_bf16(v, h, l);
    hi[id] = h; lo[id] = l;
}

// ---------------- layer 1: feats(6) -> h1(256) relu, split ----------------
__global__ void h1_kernel(const float* __restrict__ feats, const float* __restrict__ w1,
                          const float* __restrict__ b1, bf16* __restrict__ hh,
                          bf16* __restrict__ hl)
{
    int id = blockIdx.x * 256 + threadIdx.x;    // NPT*256 total
    int p = id >> 8, j = id & 255;
    const float* f = feats + (size_t)p * 6;
    float acc = b1[j];
#pragma unroll
    for (int k = 0; k < 6; k++) acc = fmaf(f[k], w1[k * 256 + j], acc);
    acc = fmaxf(acc, 0.f);
    bf16 h, l; split_bf16(acc, h, l);
    hh[id] = h; hl[id] = l;
}

// ---------------- zin = [pf | coords4 | pad] split ----------------
__global__ void zin_split(const float* __restrict__ pf, const float* __restrict__ coords,
                          bf16* __restrict__ zh, bf16* __restrict__ zl)
{
    int id = blockIdx.x * 256 + threadIdx.x;    // NPT*ZK total
    int n = id / ZK, c = id - n * ZK;
    float v;
    if (c < 768)      v = pf[(size_t)n * 768 + c];
    else if (c < 772) v = coords[(size_t)n * 5 + 1 + (c - 768)];
    else              v = 0.f;
    bf16 h, l; split_bf16(v, h, l);
    zh[id] = h; zl[id] = l;
}

// ---------------- fused LN + z@iw2 relu + @iw3 importance (fp32) ----------------
#define IPTS 16
__global__ __launch_bounds__(256) void importance_kernel(
    const float* __restrict__ z1, const float* __restrict__ iw2,
    const float* __restrict__ ib2, const float* __restrict__ iw3,
    const float* __restrict__ ib3, const float* __restrict__ ln_g,
    const float* __restrict__ ln_b, float* __restrict__ imp)
{
    __shared__ float zn[IPTS][IHD];
    __shared__ float red[IPTS][8];
    const int base = blockIdx.x * IPTS;
    const int tid  = threadIdx.x;
    const int w    = tid >> 5;
    const int lane = tid & 31;

#pragma unroll
    for (int pp = 0; pp < 2; pp++) {
        int p = w * 2 + pp;
        float vals[8];
        float s = 0.f, s2 = 0.f;
#pragma unroll
        for (int j = 0; j < 8; j++) {
            float v = z1[(size_t)(base + p) * IHD + lane + j * 32];
            vals[j] = v; s += v; s2 += v * v;
        }
#pragma unroll
        for (int off = 16; off > 0; off >>= 1) {
            s  += __shfl_xor_sync(0xFFFFFFFFu, s,  off);
            s2 += __shfl_xor_sync(0xFFFFFFFFu, s2, off);
        }
        float mu  = s * (1.f / IHD);
        float var = s2 * (1.f / IHD) - mu * mu;
        float inv = rsqrtf(var + 1e-5f);
#pragma unroll
        for (int j = 0; j < 8; j++) {
            int c = lane + j * 32;
            zn[p][c] = (vals[j] - mu) * inv * ln_g[c] + ln_b[c];
        }
    }
    __syncthreads();

    float acc[IPTS];
#pragma unroll
    for (int p = 0; p < IPTS; p++) acc[p] = ib2[tid];
    for (int k = 0; k < IHD; k++) {
        float wv = iw2[k * IHD + tid];
#pragma unroll
        for (int p = 0; p < IPTS; p++) acc[p] += zn[p][k] * wv;
    }
    float w3v = iw3[tid];
#pragma unroll
    for (int p = 0; p < IPTS; p++) {
        float v = fmaxf(acc[p], 0.f) * w3v;
#pragma unroll
        for (int off = 16; off > 0; off >>= 1)
            v += __shfl_xor_sync(0xFFFFFFFFu, v, off);
        if (lane == 0) red[p][w] = v;
    }
    __syncthreads();
    if (tid < IPTS) {
        float s = 0.f;
#pragma unroll
        for (int ww = 0; ww < 8; ww++) s += red[tid][ww];
        imp[base + tid] = s + ib3[0];
    }
}

// ---------------- per-batch top-128 + sort by t + emit cents/masks ----------------
__global__ __launch_bounds__(1024) void topk_kernel(
    const float* __restrict__ imp, const float* __restrict__ coords,
    const float* __restrict__ noise, const float* __restrict__ log_temp,
    int* __restrict__ sel_out, float* __restrict__ out_cents,
    float* __restrict__ out_masks)
{
    extern __shared__ float pert[];
    __shared__ float rv[1024];
    __shared__ int   ri[1024];
    __shared__ float selT[MT];
    __shared__ int   selI[MT];
    const int b   = blockIdx.x;
    const int tid = threadIdx.x;

    float temp = fmaxf(expf(log_temp[0]), 0.1f);
    float itemp = 1.f / temp;
    for (int i = tid; i < PP; i += 1024)
        pert[i] = (imp[b * PP + i] + noise[b * PP + i]) * itemp;
    __syncthreads();

    for (int s = 0; s < MT; s++) {
        float best = -INFINITY; int bi = 0x7FFFFFFF;
        for (int i = tid; i < PP; i += 1024) {
            float v = pert[i];
            if (v > best) { best = v; bi = i; }
        }
        rv[tid] = best; ri[tid] = bi;
        __syncthreads();
        for (int off = 512; off > 0; off >>= 1) {
            if (tid < off) {
                float ov = rv[tid + off]; int oi = ri[tid + off];
                if (ov > rv[tid] || (ov == rv[tid] && oi < ri[tid])) {
                    rv[tid] = ov; ri[tid] = oi;
                }
            }
            __syncthreads();
        }
        if (tid == 0) {
            int idx = ri[0];
            selI[s] = idx;
            selT[s] = coords[((size_t)b * PP + idx) * 5 + 4];
            pert[idx] = -INFINITY;
        }
        __syncthreads();
    }

    for (int kk = 2; kk <= MT; kk <<= 1) {
        for (int j = kk >> 1; j > 0; j >>= 1) {
            if (tid < MT) {
                int ixj = tid ^ j;
                if (ixj > tid) {
                    bool up = ((tid & kk) == 0);
                    float a = selT[tid], c = selT[ixj];
                    if ((a > c) == up) {
                        selT[tid] = c; selT[ixj] = a;
                        int t0 = selI[tid]; selI[tid] = selI[ixj]; selI[ixj] = t0;
                    }
                }
            }
            __syncthreads();
        }
    }

    if (tid < MT) {
        int idx = selI[tid];
        sel_out[b * MT + tid] = idx;
#pragma unroll
        for (int c = 0; c < 4; c++)
            out_cents[((size_t)b * MT + tid) * 4 + c] =
                coords[((size_t)b * PP + idx) * 5 + 1 + c];
        out_masks[b * MT + tid] = 1.0f;
    }
}

// ---------------- per-centroid 16-NN + max-pool of pf ----------------
__global__ __launch_bounds__(256) void knn_pool_kernel(
    const int* __restrict__ sel, const float* __restrict__ coords,
    const float* __restrict__ pf, float* __restrict__ pooled)
{
    extern __shared__ float d2[];
    __shared__ float rv[256];
    __shared__ int   ri[256];
    __shared__ int   knn[KNN];
    const int g   = blockIdx.x;
    const int b   = g >> 7;
    const int tid = threadIdx.x;

    int ci = sel[g];
    const float* cp = &coords[((size_t)b * PP + ci) * 5 + 1];
    float cx = cp[0], cy = cp[1], cz = cp[2], ct = cp[3];

    for (int i = tid; i < PP; i += 256) {
        const float* p = &coords[((size_t)b * PP + i) * 5 + 1];
        float dx = p[0] - cx, dy = p[1] - cy, dz = p[2] - cz, dt = p[3] - ct;
        d2[i] = dx * dx + dy * dy + dz * dz + dt * dt;
    }
    __syncthreads();

    for (int s = 0; s < KNN; s++) {
        float best = INFINITY; int bi = 0x7FFFFFFF;
        for (int i = tid; i < PP; i += 256) {
            float v = d2[i];
            if (v < best) { best = v; bi = i; }
        }
        rv[tid] = best; ri[tid] = bi;
        __syncthreads();
        for (int off = 128; off > 0; off >>= 1) {
            if (tid < off) {
                float ov = rv[tid + off]; int oi = ri[tid + off];
                if (ov < rv[tid] || (ov == rv[tid] && oi < ri[tid])) {
                    rv[tid] = ov; ri[tid] = oi;
                }
            }
            __syncthreads();
        }
        if (tid == 0) { knn[s] = ri[0]; d2[ri[0]] = INFINITY; }
        __syncthreads();
    }

    for (int j = tid; j < TOKD; j += 256) {
        float m = -INFINITY;
#pragma unroll
        for (int s = 0; s < KNN; s++)
            m = fmaxf(m, pf[((size_t)b * PP + knn[s]) * TOKD + j]);
        pooled[(size_t)g * TOKD + j] = m;
    }
}

// ---------------- fp32 SGEMM for the small token MLP ----------------
#define GBM 128
#define GBN 128
#define GBK 8
#define GTM 8
#define GTN 8
__global__ __launch_bounds__(256) void sgemm_bias_act(
    const float* __restrict__ A, const float* __restrict__ W,
    const float* __restrict__ bias, float* __restrict__ C,
    int N, int Kin, int Kout, int doRelu)
{
    __shared__ float As[GBK][GBM];
    __shared__ float Ws[GBK][GBN];
    const int bRow = blockIdx.y * GBM;
    const int bCol = blockIdx.x * GBN;
    const int tid  = threadIdx.x;
    const int tr = (tid / 16) * GTM;
    const int tc = (tid % 16) * GTN;

    float acc[GTM][GTN];
#pragma unroll
    for (int i = 0; i < GTM; i++)
#pragma unroll
        for (int j = 0; j < GTN; j++) acc[i][j] = 0.f;

    for (int k0 = 0; k0 < Kin; k0 += GBK) {
#pragma unroll
        for (int l = 0; l < 4; l++) {
            int e  = tid + l * 256;
            int ar = e >> 3, ak = e & 7;
            int gr = bRow + ar, gk = k0 + ak;
            As[ak][ar] = (gk < Kin && gr < N) ? A[(size_t)gr * Kin + gk] : 0.f;
        }
#pragma unroll
        for (int l = 0; l < 4; l++) {
            int e  = tid + l * 256;
            int wk = e >> 7, wc = e & 127;
            int gk = k0 + wk, gc = bCol + wc;
            Ws[wk][wc] = (gk < Kin && gc < Kout) ? W[(size_t)gk * Kout + gc] : 0.f;
        }
        __syncthreads();
#pragma unroll
        for (int kk = 0; kk < GBK; kk++) {
            float ra[GTM], rb[GTN];
#pragma unroll
            for (int i = 0; i < GTM; i++) ra[i] = As[kk][tr + i];
#pragma unroll
            for (int j = 0; j < GTN; j++) rb[j] = Ws[kk][tc + j];
#pragma unroll
            for (int i = 0; i < GTM; i++)
#pragma unroll
                for (int j = 0; j < GTN; j++) acc[i][j] += ra[i] * rb[j];
        }
        __syncthreads();
    }

#pragma unroll
    for (int i = 0; i < GTM; i++) {
        int gr = bRow + tr + i;
        if (gr >= N) continue;
#pragma unroll
        for (int j = 0; j < GTN; j++) {
            int gc = bCol + tc + j;
            if (gc >= Kout) continue;
            float v = acc[i][j] + bias[gc];
            if (doRelu) v = fmaxf(v, 0.f);
            C[(size_t)gr * Kout + gc] = v;
        }
    }
}

// ---------------- launch ----------------
extern "C" void kernel_launch(void* const* d_in, const int* in_sizes, int n_in,
                              void* d_out, int out_size)
{
    const float* coords   = (const float*)d_in[0];
    const float* feats    = (const float*)d_in[1];
    const float* log_temp = (const float*)d_in[2];
    const float* w1 = (const float*)d_in[3];  const float* b1 = (const float*)d_in[4];
    const float* w2 = (const float*)d_in[5];  const float* b2 = (const float*)d_in[6];
    const float* w3 = (const float*)d_in[7];  const float* b3 = (const float*)d_in[8];
    const float* w4 = (const float*)d_in[9];  const float* b4 = (const float*)d_in[10];
    const float* iw1 = (const float*)d_in[11]; const float* ib1 = (const float*)d_in[12];
    const float* ln_g = (const float*)d_in[13]; const float* ln_b = (const float*)d_in[14];
    const float* iw2 = (const float*)d_in[15]; const float* ib2 = (const float*)d_in[16];
    const float* iw3 = (const float*)d_in[17]; const float* ib3 = (const float*)d_in[18];
    const float* nw1 = (const float*)d_in[19]; const float* nb1 = (const float*)d_in[20];
    const float* nw2 = (const float*)d_in[21]; const float* nb2 = (const float*)d_in[22];
    const float* noise = (const float*)d_in[23];

    float* out        = (float*)d_out;
    float* out_tokens = out;
    float* out_cents  = out + (size_t)BSZ * MT * TOKD;
    float* out_masks  = out_cents + (size_t)BSZ * MT * 4;

    bf16 *h1h,*h1l,*h2h,*h2l,*h3h,*h3l,*zinh,*zinl;
    bf16 *w2h,*w2l,*w3h,*w3l,*w4h,*w4l,*iw1h,*iw1l;
    float *pf,*z1,*imp,*pooled,*t1;
    int* sel;
    cudaGetSymbolAddress((void**)&h1h, g_h1h);  cudaGetSymbolAddress((void**)&h1l, g_h1l);
    cudaGetSymbolAddress((void**)&h2h, g_h2h);  cudaGetSymbolAddress((void**)&h2l, g_h2l);
    cudaGetSymbolAddress((void**)&h3h, g_h3h);  cudaGetSymbolAddress((void**)&h3l, g_h3l);
    cudaGetSymbolAddress((void**)&zinh, g_zinh); cudaGetSymbolAddress((void**)&zinl, g_zinl);
    cudaGetSymbolAddress((void**)&w2h, g_w2h);  cudaGetSymbolAddress((void**)&w2l, g_w2l);
    cudaGetSymbolAddress((void**)&w3h, g_w3h);  cudaGetSymbolAddress((void**)&w3l, g_w3l);
    cudaGetSymbolAddress((void**)&w4h, g_w4h);  cudaGetSymbolAddress((void**)&w4l, g_w4l);
    cudaGetSymbolAddress((void**)&iw1h, g_iw1h); cudaGetSymbolAddress((void**)&iw1l, g_iw1l);
    cudaGetSymbolAddress((void**)&pf,  g_pf);
    cudaGetSymbolAddress((void**)&z1,  g_z1);
    cudaGetSymbolAddress((void**)&imp, g_imp);
    cudaGetSymbolAddress((void**)&sel, g_sel);
    cudaGetSymbolAddress((void**)&pooled, g_pooled);
    cudaGetSymbolAddress((void**)&t1,  g_t1);

    cudaFuncSetAttribute(mma_gemm,
        cudaFuncAttributeMaxDynamicSharedMemorySize, MMA_SMEM);
    cudaFuncSetAttribute(topk_kernel,
        cudaFuncAttributeMaxDynamicSharedMemorySize, PP * sizeof(float));
    cudaFuncSetAttribute(knn_pool_kernel,
        cudaFuncAttributeMaxDynamicSharedMemorySize, PP * sizeof(float));

    // weight prep
    w_split<<<(512*256 + 255)/256, 256>>>(w2,  w2h,  w2l,  256, 512, 256);
    w_split<<<(768*512 + 255)/256, 256>>>(w3,  w3h,  w3l,  512, 768, 512);
    w_split<<<(768*768 + 255)/256, 256>>>(w4,  w4h,  w4l,  768, 768, 768);
    w_split<<<(256*ZK  + 255)/256, 256>>>(iw1, iw1h, iw1l, 772, 256, ZK);

    // layer 1 (K=6, direct)
    h1_kernel<<<NPT, 256>>>(feats, w1, b1, h1h, h1l);

    // layers 2-4 on tensor cores (mma.sync)
    mma_gemm<<<dim3(4, NPT/128), 256, MMA_SMEM>>>(h1h, h1l, w2h, w2l, b2,
        nullptr, h2h, h2l, 256, 512, 1);
    mma_gemm<<<dim3(6, NPT/128), 256, MMA_SMEM>>>(h2h, h2l, w3h, w3l, b3,
        nullptr, h3h, h3l, 512, 768, 1);
    mma_gemm<<<dim3(6, NPT/128), 256, MMA_SMEM>>>(h3h, h3l, w4h, w4l, b4,
        pf, nullptr, nullptr, 768, 768, 0);

    // zin concat + split
    zin_split<<<(int)(((size_t)NPT*ZK + 255)/256), 256>>>(pf, coords, zinh, zinl);

    // importance layer 1 on tensor cores -> z1 fp32
    mma_gemm<<<dim3(2, NPT/128), 256, MMA_SMEM>>>(zinh, zinl, iw1h, iw1l, ib1,
        z1, nullptr, nullptr, ZK, 256, 1);

    // fused LN + mlp + importance score
    importance_kernel<<<NPT / IPTS, 256>>>(z1, iw2, ib2, iw3, ib3, ln_g, ln_b, imp);
    // top-128 + sort + cents/masks
    topk_kernel<<<BSZ, 1024, PP * sizeof(float)>>>(
        imp, coords, noise, log_temp, sel, out_cents, out_masks);
    // knn + max pool
    knn_pool_kernel<<<BSZ * MT, 256, PP * sizeof(float)>>>(sel, coords, pf, pooled);
    // token MLP (fp32)
    sgemm_bias_act<<<dim3(768/GBN, (BSZ*MT)/GBM), dim3(256)>>>(
        pooled, nw1, nb1, t1, BSZ * MT, 768, 768, 1);
    sgemm_bias_act<<<dim3(768/GBN, (BSZ*MT)/GBM), dim3(256)>>>(
        t1, nw2, nb2, out_tokens, BSZ * MT, 768, 768, 0);
}

// round 6
// speedup vs baseline: 3.5100x; 1.3157x over previous
#include <cuda_runtime.h>
#include <cuda_bf16.h>
#include <math.h>
#include <stdint.h>

#define BSZ 8
#define PP  16384
#define NPT (BSZ*PP)       // 131072
#define TOKD 768
#define MT  128
#define KNN 16
#define IHD 256
#define ZK  832            // zin padded K (772 -> 13*64)

typedef __nv_bfloat16 bf16;

// ---------------- scratch (device globals) ----------------
__device__ bf16  g_h1h[(size_t)NPT*256];     // also reused as zn_hi after LN
__device__ bf16  g_h1l[(size_t)NPT*256];     // also reused as zn_lo
__device__ bf16  g_h2h[(size_t)NPT*512];
__device__ bf16  g_h2l[(size_t)NPT*512];
__device__ bf16  g_h3h[(size_t)NPT*768];
__device__ bf16  g_h3l[(size_t)NPT*768];
__device__ bf16  g_zinh[(size_t)NPT*ZK];
__device__ bf16  g_zinl[(size_t)NPT*ZK];
__device__ float g_pf[(size_t)NPT*768];
__device__ float g_z1[(size_t)NPT*256];
__device__ float g_z2[(size_t)NPT*256];
__device__ float g_imp[NPT];
__device__ int   g_sel[BSZ*MT];
__device__ bf16  g_ph[(size_t)BSZ*MT*768], g_pl[(size_t)BSZ*MT*768];
__device__ bf16  g_t1h[(size_t)BSZ*MT*768], g_t1l[(size_t)BSZ*MT*768];
// transposed split weights: layout [Kout][Kpad]
__device__ bf16  g_w2h[512*256],  g_w2l[512*256];
__device__ bf16  g_w3h[768*512],  g_w3l[768*512];
__device__ bf16  g_w4h[768*768],  g_w4l[768*768];
__device__ bf16  g_iw1h[256*ZK],  g_iw1l[256*ZK];
__device__ bf16  g_iw2h[256*256], g_iw2l[256*256];
__device__ bf16  g_nw1h[768*768], g_nw1l[768*768];
__device__ bf16  g_nw2h[768*768], g_nw2l[768*768];

// ---------------- PTX helpers (baseline ISA only) ----------------
__device__ __forceinline__ uint32_t smem_u32(const void* p) {
    uint32_t a;
    asm("{ .reg .u64 t; cvta.to.shared.u64 t, %1; cvt.u32.u64 %0, t; }"
        : "=r"(a) : "l"(p));
    return a;
}
__device__ __forceinline__ void cp16(uint32_t dst, const void* src) {
    asm volatile("cp.async.cg.shared.global [%0], [%1], 16;"
        :: "r"(dst), "l"(src) : "memory");
}
__device__ __forceinline__ void cp_commit() {
    asm volatile("cp.async.commit_group;" ::: "memory");
}
__device__ __forceinline__ void cp_wait1() {
    asm volatile("cp.async.wait_group 1;" ::: "memory");
}
__device__ __forceinline__ void cp_wait0() {
    asm volatile("cp.async.wait_group 0;" ::: "memory");
}
__device__ __forceinline__ void ldsm4(uint32_t* r, uint32_t a) {
    asm volatile("ldmatrix.sync.aligned.m8n8.x4.shared.b16 {%0,%1,%2,%3}, [%4];"
        : "=r"(r[0]), "=r"(r[1]), "=r"(r[2]), "=r"(r[3]) : "r"(a));
}
__device__ __forceinline__ void mma16816(float* d, const uint32_t* a, const uint32_t* b) {
    asm volatile("mma.sync.aligned.m16n8k16.row.col.f32.bf16.bf16.f32 "
        "{%0,%1,%2,%3}, {%4,%5,%6,%7}, {%8,%9}, {%0,%1,%2,%3};"
        : "+f"(d[0]), "+f"(d[1]), "+f"(d[2]), "+f"(d[3])
        : "r"(a[0]), "r"(a[1]), "r"(a[2]), "r"(a[3]), "r"(b[0]), "r"(b[1]));
}
__device__ __forceinline__ void split_bf16(float v, bf16& h, bf16& l) {
    h = __float2bfloat16(v);
    l = __float2bfloat16(v - __bfloat162float(h));
}

// ---------------- mma.sync split-bf16 GEMM ----------------
#define TILE_B   16384          // one 128x64 bf16 tile, SW128-swizzled
#define STAGE_B  (4*TILE_B)     // Ah, Al, Bh, Bl
#define MMA_SMEM (1024 + 2*STAGE_B)

extern __shared__ char smem_dyn_c[];

__device__ __forceinline__ void tile_cp(const bf16* __restrict__ src, int rowBase,
                                        int Kstride, int kc, uint32_t dstBase, int tid)
{
#pragma unroll
    for (int j = 0; j < 4; j++) {
        int i = tid + j * 256;
        int r = i >> 3, ck = i & 7;
        const bf16* s = src + (size_t)(rowBase + r) * Kstride + kc * 64 + ck * 8;
        uint32_t off = (uint32_t)(r * 128 + ((ck * 16) ^ ((r & 7) << 4)));
        cp16(dstBase + off, s);
    }
}

__global__ __launch_bounds__(256)
void mma_gemm(const bf16* __restrict__ Ah, const bf16* __restrict__ Al,
              const bf16* __restrict__ Bh, const bf16* __restrict__ Bl,
              const float* __restrict__ bias,
              float* __restrict__ Cf, bf16* __restrict__ Ch, bf16* __restrict__ Cl,
              int strideC, int Kpad, int Kout, int doRelu)
{
    char* smem = smem_dyn_c;
    const uint32_t sbase = smem_u32(smem);
    float* Sb = (float*)smem;
    const uint32_t tiles0 = sbase + 1024;
    const int tid  = threadIdx.x;
    const int wid  = tid >> 5;
    const int lane = tid & 31;
    const int wm   = wid >> 2;
    const int wn   = wid & 3;
    const int bRow = blockIdx.y * 128;
    const int bCol = blockIdx.x * 128;

    if (tid < 128) Sb[tid] = bias[bCol + tid];

    uint32_t aOff[4], bOff[2];
    {
        int khalfA = ((lane >> 4) & 1) * 16;
#pragma unroll
        for (int mf = 0; mf < 4; mf++) {
            int r = wm * 64 + mf * 16 + ((lane >> 3) & 1) * 8 + (lane & 7);
            aOff[mf] = (uint32_t)(r * 128 + (khalfA ^ ((r & 7) << 4)));
        }
        int khalfB = ((lane >> 3) & 1) * 16;
#pragma unroll
        for (int nb = 0; nb < 2; nb++) {
            int r = wn * 32 + nb * 16 + ((lane >> 4) & 1) * 8 + (lane & 7);
            bOff[nb] = (uint32_t)(r * 128 + (khalfB ^ ((r & 7) << 4)));
        }
    }

    float acc[4][4][4];
#pragma unroll
    for (int i = 0; i < 4; i++)
#pragma unroll
        for (int j = 0; j < 4; j++)
#pragma unroll
            for (int c = 0; c < 4; c++) acc[i][j][c] = 0.f;

    const int T = Kpad / 64;

    tile_cp(Ah, bRow, Kpad, 0, tiles0,             tid);
    tile_cp(Al, bRow, Kpad, 0, tiles0 + TILE_B,    tid);
    tile_cp(Bh, bCol, Kpad, 0, tiles0 + 2*TILE_B,  tid);
    tile_cp(Bl, bCol, Kpad, 0, tiles0 + 3*TILE_B,  tid);
    cp_commit();

    for (int t = 0; t < T; t++) {
        __syncthreads();
        if (t + 1 < T) {
            uint32_t st = tiles0 + ((t + 1) & 1) * STAGE_B;
            tile_cp(Ah, bRow, Kpad, t + 1, st,            tid);
            tile_cp(Al, bRow, Kpad, t + 1, st + TILE_B,   tid);
            tile_cp(Bh, bCol, Kpad, t + 1, st + 2*TILE_B, tid);
            tile_cp(Bl, bCol, Kpad, t + 1, st + 3*TILE_B, tid);
            cp_commit();
            cp_wait1();
        } else {
            cp_wait0();
        }
        __syncthreads();

        const uint32_t st = tiles0 + (t & 1) * STAGE_B;
        const uint32_t tAh = st, tAl = st + TILE_B, tBh = st + 2*TILE_B, tBl = st + 3*TILE_B;

#pragma unroll
        for (int pass = 0; pass < 3; pass++) {
            const uint32_t At = (pass == 2) ? tAl : tAh;
            const uint32_t Bt = (pass == 1) ? tBl : tBh;
#pragma unroll
            for (int ks = 0; ks < 4; ks++) {
                const uint32_t kx = (uint32_t)(ks << 5);
                uint32_t af[4][4], bfr[2][4];
#pragma unroll
                for (int mf = 0; mf < 4; mf++) ldsm4(af[mf], At + (aOff[mf] ^ kx));
#pragma unroll
                for (int nb = 0; nb < 2; nb++) ldsm4(bfr[nb], Bt + (bOff[nb] ^ kx));
#pragma unroll
                for (int mf = 0; mf < 4; mf++)
#pragma unroll
                    for (int nf = 0; nf < 4; nf++)
                        mma16816(acc[mf][nf], af[mf], &bfr[nf >> 1][(nf & 1) * 2]);
            }
        }
    }

    // ---- epilogue ----
#pragma unroll
    for (int mf = 0; mf < 4; mf++) {
        int r0 = bRow + wm * 64 + mf * 16 + (lane >> 2);
#pragma unroll
        for (int nf = 0; nf < 4; nf++) {
            int cloc = wn * 32 + nf * 8 + (lane & 3) * 2;
            int c0 = bCol + cloc;
            float b0 = Sb[cloc], b1 = Sb[cloc + 1];
            float v0 = acc[mf][nf][0] + b0;
            float v1 = acc[mf][nf][1] + b1;
            float v2 = acc[mf][nf][2] + b0;
            float v3 = acc[mf][nf][3] + b1;
            if (doRelu) {
                v0 = fmaxf(v0, 0.f); v1 = fmaxf(v1, 0.f);
                v2 = fmaxf(v2, 0.f); v3 = fmaxf(v3, 0.f);
            }
            if (Cf) {
                size_t o0 = (size_t)r0 * Kout + c0;
                size_t o1 = (size_t)(r0 + 8) * Kout + c0;
                *(float2*)&Cf[o0] = make_float2(v0, v1);
                *(float2*)&Cf[o1] = make_float2(v2, v3);
            }
            if (Ch) {
                size_t o0 = (size_t)r0 * strideC + c0;
                size_t o1 = (size_t)(r0 + 8) * strideC + c0;
                bf16 h0, l0, h1, l1;
                split_bf16(v0, h0, l0); split_bf16(v1, h1, l1);
                __nv_bfloat162 hp, lp;
                hp.x = h0; hp.y = h1; lp.x = l0; lp.y = l1;
                *(__nv_bfloat162*)&Ch[o0] = hp;
                *(__nv_bfloat162*)&Cl[o0] = lp;
                split_bf16(v2, h0, l0); split_bf16(v3, h1, l1);
                hp.x = h0; hp.y = h1; lp.x = l0; lp.y = l1;
                *(__nv_bfloat162*)&Ch[o1] = hp;
                *(__nv_bfloat162*)&Cl[o1] = lp;
            }
        }
    }
}

// ---------------- weight split (transpose + pad + bf16 hi/lo) ----------------
__global__ void w_split(const float* __restrict__ W, bf16* __restrict__ hi,
                        bf16* __restrict__ lo, int Kin, int Kout, int Kpad)
{
    int id = blockIdx.x * 256 + threadIdx.x;
    if (id >= Kout * Kpad) return;
    int n = id / Kpad, k = id - n * Kpad;
    float v = (k < Kin) ? W[(size_t)k * Kout + n] : 0.f;
    bf16 h, l; split_bf16(v, h, l);
    hi[id] = h; lo[id] = l;
}

// ---------------- layer 1: feats(6) -> h1(256) relu, split ----------------
__global__ void h1_kernel(const float* __restrict__ feats, const float* __restrict__ w1,
                          const float* __restrict__ b1, bf16* __restrict__ hh,
                          bf16* __restrict__ hl)
{
    int id = blockIdx.x * 256 + threadIdx.x;
    int p = id >> 8, j = id & 255;
    const float* f = feats + (size_t)p * 6;
    float acc = b1[j];
#pragma unroll
    for (int k = 0; k < 6; k++) acc = fmaf(f[k], w1[k * 256 + j], acc);
    acc = fmaxf(acc, 0.f);
    bf16 h, l; split_bf16(acc, h, l);
    hh[id] = h; hl[id] = l;
}

// ---------------- zin tail: cols 768..831 = coords4 | 0 ----------------
__global__ void zin_tail(const float* __restrict__ coords,
                         bf16* __restrict__ zh, bf16* __restrict__ zl)
{
    int id = blockIdx.x * 256 + threadIdx.x;     // NPT*64
    int n = id >> 6, c = 768 + (id & 63);
    float v = (c < 772) ? coords[(size_t)n * 5 + 1 + (c - 768)] : 0.f;
    bf16 h, l; split_bf16(v, h, l);
    zh[(size_t)n * ZK + c] = h; zl[(size_t)n * ZK + c] = l;
}

// ---------------- LayerNorm + split: z1 fp32 -> zn hi/lo bf16 ----------------
__global__ __launch_bounds__(256) void ln_split(
    const float* __restrict__ z1, const float* __restrict__ ln_g,
    const float* __restrict__ ln_b, bf16* __restrict__ zh, bf16* __restrict__ zl)
{
    const int tid = threadIdx.x, w = tid >> 5, lane = tid & 31;
    const int p = blockIdx.x * 8 + w;
    float vals[8];
    float s = 0.f, s2 = 0.f;
#pragma unroll
    for (int j = 0; j < 8; j++) {
        float v = z1[(size_t)p * IHD + lane + j * 32];
        vals[j] = v; s += v; s2 += v * v;
    }
#pragma unroll
    for (int off = 16; off > 0; off >>= 1) {
        s  += __shfl_xor_sync(0xFFFFFFFFu, s,  off);
        s2 += __shfl_xor_sync(0xFFFFFFFFu, s2, off);
    }
    float mu  = s * (1.f / IHD);
    float var = s2 * (1.f / IHD) - mu * mu;
    float inv = rsqrtf(var + 1e-5f);
#pragma unroll
    for (int j = 0; j < 8; j++) {
        int c = lane + j * 32;
        float v = (vals[j] - mu) * inv * ln_g[c] + ln_b[c];
        bf16 h, l; split_bf16(v, h, l);
        zh[(size_t)p * IHD + c] = h; zl[(size_t)p * IHD + c] = l;
    }
}

// ---------------- imp = z2 @ iw3 + ib3 ----------------
__global__ __launch_bounds__(256) void imp_dot(
    const float* __restrict__ z2, const float* __restrict__ iw3,
    const float* __restrict__ ib3, float* __restrict__ imp)
{
    __shared__ float w3s[IHD];
    const int tid = threadIdx.x, w = tid >> 5, lane = tid & 31;
    w3s[tid] = iw3[tid];
    __syncthreads();
    const int p = blockIdx.x * 8 + w;
    float acc = 0.f;
#pragma unroll
    for (int j = 0; j < 8; j++) {
        int c = lane + j * 32;
        acc = fmaf(z2[(size_t)p * IHD + c], w3s[c], acc);
    }
#pragma unroll
    for (int off = 16; off > 0; off >>= 1)
        acc += __shfl_xor_sync(0xFFFFFFFFu, acc, off);
    if (lane == 0) imp[p] = acc + ib3[0];
}

// ---------------- per-batch top-128 via radix select + sort by t ----------------
__global__ __launch_bounds__(1024) void topk_kernel(
    const float* __restrict__ imp, const float* __restrict__ coords,
    const float* __restrict__ noise,
    int* __restrict__ sel_out, float* __restrict__ out_cents,
    float* __restrict__ out_masks)
{
    extern __shared__ uint32_t keys[];          // PP keys
    __shared__ uint32_t hist[256];
    __shared__ int sh_bucket, sh_target, gtCnt;
    __shared__ float selT[MT];
    __shared__ int   selI[MT];
    __shared__ int   red_i[1024];
    const int b   = blockIdx.x;
    const int tid = threadIdx.x;

    // ordering-preserving float->uint keys (temp scaling cannot change order)
    for (int i = tid; i < PP; i += 1024) {
        float v = imp[b * PP + i] + noise[b * PP + i];
        uint32_t u = __float_as_uint(v);
        keys[i] = (u & 0x80000000u) ? ~u : (u | 0x80000000u);
    }
    if (tid == 0) { sh_target = MT; gtCnt = 0; }
    __syncthreads();

    uint32_t pfx = 0, mask = 0;
#pragma unroll
    for (int B = 3; B >= 0; B--) {
        if (tid < 256) hist[tid] = 0u;
        __syncthreads();
        for (int i = tid; i < PP; i += 1024) {
            uint32_t k = keys[i];
            if ((k & mask) == pfx)
                atomicAdd(&hist[(k >> (8 * B)) & 0xFF], 1u);
        }
        __syncthreads();
        if (tid == 0) {
            int tgt = sh_target, cum = 0, bucket = 0;
            for (int v = 255; v >= 0; v--) {
                int h = (int)hist[v];
                if (cum + h >= tgt) { bucket = v; break; }
                cum += h;
            }
            sh_bucket = bucket;
            sh_target = tgt - cum;
        }
        __syncthreads();
        pfx |= ((uint32_t)sh_bucket) << (8 * B);
        mask |= 0xFFu << (8 * B);
        __syncthreads();
    }
    const uint32_t Kt = pfx;
    const int nEq = sh_target;          // how many ==Kt to take (smallest idx first)

    for (int i = tid; i < PP; i += 1024) {
        if (keys[i] > Kt) {
            int pos = atomicAdd(&gtCnt, 1);
            selI[pos] = i;
        }
    }
    __syncthreads();
    int base = gtCnt;
    int last = -1;
    for (int r = 0; r < nEq; r++) {
        int loc = 0x7FFFFFFF;
        for (int i = tid; i < PP; i += 1024)
            if (keys[i] == Kt && i > last && i < loc) loc = i;
        red_i[tid] = loc;
        __syncthreads();
        for (int off = 512; off > 0; off >>= 1) {
            if (tid < off) red_i[tid] = min(red_i[tid], red_i[tid + off]);
            __syncthreads();
        }
        if (tid == 0) selI[base + r] = red_i[0];
        last = red_i[0];
        __syncthreads();
    }

    if (tid < MT) selT[tid] = coords[((size_t)b * PP + selI[tid]) * 5 + 4];
    __syncthreads();

    // bitonic sort 128 selected by t ascending
    for (int kk = 2; kk <= MT; kk <<= 1) {
        for (int j = kk >> 1; j > 0; j >>= 1) {
            if (tid < MT) {
                int ixj = tid ^ j;
                if (ixj > tid) {
                    bool up = ((tid & kk) == 0);
                    float a = selT[tid], c = selT[ixj];
                    if ((a > c) == up) {
                        selT[tid] = c; selT[ixj] = a;
                        int t0 = selI[tid]; selI[tid] = selI[ixj]; selI[ixj] = t0;
                    }
                }
            }
            __syncthreads();
        }
    }

    if (tid < MT) {
        int idx = selI[tid];
        sel_out[b * MT + tid] = idx;
#pragma unroll
        for (int c = 0; c < 4; c++)
            out_cents[((size_t)b * MT + tid) * 4 + c] =
                coords[((size_t)b * PP + idx) * 5 + 1 + c];
        out_masks[b * MT + tid] = 1.0f;
    }
}

// ---------------- per-centroid 16-NN + max-pool of pf (split out) ----------------
__global__ __launch_bounds__(256) void knn_pool_kernel(
    const int* __restrict__ sel, const float* __restrict__ coords,
    const float* __restrict__ pf, bf16* __restrict__ ph, bf16* __restrict__ pl)
{
    extern __shared__ float d2[];
    __shared__ float rv[256];
    __shared__ int   ri[256];
    __shared__ int   knn[KNN];
    const int g   = blockIdx.x;
    const int b   = g >> 7;
    const int tid = threadIdx.x;

    int ci = sel[g];
    const float* cp = &coords[((size_t)b * PP + ci) * 5 + 1];
    float cx = cp[0], cy = cp[1], cz = cp[2], ct = cp[3];

    for (int i = tid; i < PP; i += 256) {
        const float* p = &coords[((size_t)b * PP + i) * 5 + 1];
        float dx = p[0] - cx, dy = p[1] - cy, dz = p[2] - cz, dt = p[3] - ct;
        d2[i] = dx * dx + dy * dy + dz * dz + dt * dt;
    }
    __syncthreads();

    for (int s = 0; s < KNN; s++) {
        float best = INFINITY; int bi = 0x7FFFFFFF;
        for (int i = tid; i < PP; i += 256) {
            float v = d2[i];
            if (v < best) { best = v; bi = i; }
        }
        rv[tid] = best; ri[tid] = bi;
        __syncthreads();
        for (int off = 128; off > 0; off >>= 1) {
            if (tid < off) {
                float ov = rv[tid + off]; int oi = ri[tid + off];
                if (ov < rv[tid] || (ov == rv[tid] && oi < ri[tid])) {
                    rv[tid] = ov; ri[tid] = oi;
                }
            }
            __syncthreads();
        }
        if (tid == 0) { knn[s] = ri[0]; d2[ri[0]] = INFINITY; }
        __syncthreads();
    }

    for (int j = tid; j < TOKD; j += 256) {
        float m = -INFINITY;
#pragma unroll
        for (int s = 0; s < KNN; s++)
            m = fmaxf(m, pf[((size_t)b * PP + knn[s]) * TOKD + j]);
        bf16 h, l; split_bf16(m, h, l);
        ph[(size_t)g * TOKD + j] = h;
        pl[(size_t)g * TOKD + j] = l;
    }
}

// ---------------- launch ----------------
extern "C" void kernel_launch(void* const* d_in, const int* in_sizes, int n_in,
                              void* d_out, int out_size)
{
    const float* coords   = (const float*)d_in[0];
    const float* feats    = (const float*)d_in[1];
    const float* w1 = (const float*)d_in[3];  const float* b1 = (const float*)d_in[4];
    const float* w2 = (const float*)d_in[5];  const float* b2 = (const float*)d_in[6];
    const float* w3 = (const float*)d_in[7];  const float* b3 = (const float*)d_in[8];
    const float* w4 = (const float*)d_in[9];  const float* b4 = (const float*)d_in[10];
    const float* iw1 = (const float*)d_in[11]; const float* ib1 = (const float*)d_in[12];
    const float* ln_g = (const float*)d_in[13]; const float* ln_b = (const float*)d_in[14];
    const float* iw2 = (const float*)d_in[15]; const float* ib2 = (const float*)d_in[16];
    const float* iw3 = (const float*)d_in[17]; const float* ib3 = (const float*)d_in[18];
    const float* nw1 = (const float*)d_in[19]; const float* nb1 = (const float*)d_in[20];
    const float* nw2 = (const float*)d_in[21]; const float* nb2 = (const float*)d_in[22];
    const float* noise = (const float*)d_in[23];

    float* out        = (float*)d_out;
    float* out_tokens = out;
    float* out_cents  = out + (size_t)BSZ * MT * TOKD;
    float* out_masks  = out_cents + (size_t)BSZ * MT * 4;

    bf16 *h1h,*h1l,*h2h,*h2l,*h3h,*h3l,*zinh,*zinl,*ph,*pl,*t1h,*t1l;
    bf16 *w2h,*w2l,*w3h,*w3l,*w4h,*w4l,*iw1h,*iw1l,*iw2h,*iw2l,*nw1h,*nw1l,*nw2h,*nw2l;
    float *pf,*z1,*z2,*imp;
    int* sel;
    cudaGetSymbolAddress((void**)&h1h, g_h1h);  cudaGetSymbolAddress((void**)&h1l, g_h1l);
    cudaGetSymbolAddress((void**)&h2h, g_h2h);  cudaGetSymbolAddress((void**)&h2l, g_h2l);
    cudaGetSymbolAddress((void**)&h3h, g_h3h);  cudaGetSymbolAddress((void**)&h3l, g_h3l);
    cudaGetSymbolAddress((void**)&zinh, g_zinh); cudaGetSymbolAddress((void**)&zinl, g_zinl);
    cudaGetSymbolAddress((void**)&ph, g_ph);    cudaGetSymbolAddress((void**)&pl, g_pl);
    cudaGetSymbolAddress((void**)&t1h, g_t1h);  cudaGetSymbolAddress((void**)&t1l, g_t1l);
    cudaGetSymbolAddress((void**)&w2h, g_w2h);  cudaGetSymbolAddress((void**)&w2l, g_w2l);
    cudaGetSymbolAddress((void**)&w3h, g_w3h);  cudaGetSymbolAddress((void**)&w3l, g_w3l);
    cudaGetSymbolAddress((void**)&w4h, g_w4h);  cudaGetSymbolAddress((void**)&w4l, g_w4l);
    cudaGetSymbolAddress((void**)&iw1h, g_iw1h); cudaGetSymbolAddress((void**)&iw1l, g_iw1l);
    cudaGetSymbolAddress((void**)&iw2h, g_iw2h); cudaGetSymbolAddress((void**)&iw2l, g_iw2l);
    cudaGetSymbolAddress((void**)&nw1h, g_nw1h); cudaGetSymbolAddress((void**)&nw1l, g_nw1l);
    cudaGetSymbolAddress((void**)&nw2h, g_nw2h); cudaGetSymbolAddress((void**)&nw2l, g_nw2l);
    cudaGetSymbolAddress((void**)&pf,  g_pf);
    cudaGetSymbolAddress((void**)&z1,  g_z1);
    cudaGetSymbolAddress((void**)&z2,  g_z2);
    cudaGetSymbolAddress((void**)&imp, g_imp);
    cudaGetSymbolAddress((void**)&sel, g_sel);

    cudaFuncSetAttribute(mma_gemm,
        cudaFuncAttributeMaxDynamicSharedMemorySize, MMA_SMEM);
    cudaFuncSetAttribute(topk_kernel,
        cudaFuncAttributeMaxDynamicSharedMemorySize, PP * sizeof(uint32_t));
    cudaFuncSetAttribute(knn_pool_kernel,
        cudaFuncAttributeMaxDynamicSharedMemorySize, PP * sizeof(float));

    // weight prep
    w_split<<<(512*256 + 255)/256, 256>>>(w2,  w2h,  w2l,  256, 512, 256);
    w_split<<<(768*512 + 255)/256, 256>>>(w3,  w3h,  w3l,  512, 768, 512);
    w_split<<<(768*768 + 255)/256, 256>>>(w4,  w4h,  w4l,  768, 768, 768);
    w_split<<<(256*ZK  + 255)/256, 256>>>(iw1, iw1h, iw1l, 772, 256, ZK);
    w_split<<<(256*256 + 255)/256, 256>>>(iw2, iw2h, iw2l, 256, 256, 256);
    w_split<<<(768*768 + 255)/256, 256>>>(nw1, nw1h, nw1l, 768, 768, 768);
    w_split<<<(768*768 + 255)/256, 256>>>(nw2, nw2h, nw2l, 768, 768, 768);

    // layer 1 (K=6, direct)
    h1_kernel<<<NPT, 256>>>(feats, w1, b1, h1h, h1l);

    // layers 2-4 on tensor cores; L4 writes pf fp32 + zin split (cols 0..767)
    mma_gemm<<<dim3(4, NPT/128), 256, MMA_SMEM>>>(h1h, h1l, w2h, w2l, b2,
        nullptr, h2h, h2l, 512, 256, 512, 1);
    mma_gemm<<<dim3(6, NPT/128), 256, MMA_SMEM>>>(h2h, h2l, w3h, w3l, b3,
        nullptr, h3h, h3l, 768, 512, 768, 1);
    mma_gemm<<<dim3(6, NPT/128), 256, MMA_SMEM>>>(h3h, h3l, w4h, w4l, b4,
        pf, zinh, zinl, ZK, 768, 768, 0);
    zin_tail<<<(NPT*64)/256, 256>>>(coords, zinh, zinl);

    // importance head: iw1 GEMM -> LN -> iw2 GEMM -> dot iw3
    mma_gemm<<<dim3(2, NPT/128), 256, MMA_SMEM>>>(zinh, zinl, iw1h, iw1l, ib1,
        z1, nullptr, nullptr, 0, ZK, 256, 1);
    ln_split<<<NPT/8, 256>>>(z1, ln_g, ln_b, h1h, h1l);     // reuse h1 bufs as zn
    mma_gemm<<<dim3(2, NPT/128), 256, MMA_SMEM>>>(h1h, h1l, iw2h, iw2l, ib2,
        z2, nullptr, nullptr, 0, 256, 256, 1);
    imp_dot<<<NPT/8, 256>>>(z2, iw3, ib3, imp);

    // radix-select top-128 + sort + cents/masks
    topk_kernel<<<BSZ, 1024, PP * sizeof(uint32_t)>>>(
        imp, coords, noise, sel, out_cents, out_masks);
    // knn + max pool (writes split directly)
    knn_pool_kernel<<<BSZ * MT, 256, PP * sizeof(float)>>>(sel, coords, pf, ph, pl);
    // token MLP on tensor cores
    mma_gemm<<<dim3(6, (BSZ*MT)/128), 256, MMA_SMEM>>>(ph, pl, nw1h, nw1l, nb1,
        nullptr, t1h, t1l, 768, 768, 768, 1);
    mma_gemm<<<dim3(6, (BSZ*MT)/128), 256, MMA_SMEM>>>(t1h, t1l, nw2h, nw2l, nb2,
        out_tokens, nullptr, nullptr, 0, 768, 768, 0);
}

// round 7
// speedup vs baseline: 3.7053x; 1.0556x over previous
#include <cuda_runtime.h>
#include <cuda_bf16.h>
#include <math.h>
#include <stdint.h>

#define BSZ 8
#define PP  16384
#define NPT (BSZ*PP)       // 131072
#define TOKD 768
#define MT  128
#define KNN 16
#define IHD 256
#define ZK  832            // zin padded K (772 -> 13*64)

typedef __nv_bfloat16 bf16;

// ---------------- scratch (device globals) ----------------
__device__ bf16  g_h1h[(size_t)NPT*256];     // also reused as zn_hi after LN
__device__ bf16  g_h1l[(size_t)NPT*256];     // also reused as zn_lo
__device__ bf16  g_h2h[(size_t)NPT*512];
__device__ bf16  g_h2l[(size_t)NPT*512];
__device__ bf16  g_h3h[(size_t)NPT*768];
__device__ bf16  g_h3l[(size_t)NPT*768];
__device__ bf16  g_zinh[(size_t)NPT*ZK];
__device__ bf16  g_zinl[(size_t)NPT*ZK];
__device__ float g_pf[(size_t)NPT*768];
__device__ float g_z1[(size_t)NPT*256];
__device__ float g_z2[(size_t)NPT*256];
__device__ float g_imp[NPT];
__device__ int   g_sel[BSZ*MT];
__device__ bf16  g_ph[(size_t)BSZ*MT*768], g_pl[(size_t)BSZ*MT*768];
__device__ bf16  g_t1h[(size_t)BSZ*MT*768], g_t1l[(size_t)BSZ*MT*768];
// transposed split weights: layout [Kout][Kpad]
__device__ bf16  g_w2h[512*256],  g_w2l[512*256];
__device__ bf16  g_w3h[768*512],  g_w3l[768*512];
__device__ bf16  g_w4h[768*768],  g_w4l[768*768];
__device__ bf16  g_iw1h[256*ZK],  g_iw1l[256*ZK];
__device__ bf16  g_iw2h[256*256], g_iw2l[256*256];
__device__ bf16  g_nw1h[768*768], g_nw1l[768*768];
__device__ bf16  g_nw2h[768*768], g_nw2l[768*768];

// ---------------- PTX helpers (baseline ISA only) ----------------
__device__ __forceinline__ uint32_t smem_u32(const void* p) {
    uint32_t a;
    asm("{ .reg .u64 t; cvta.to.shared.u64 t, %1; cvt.u32.u64 %0, t; }"
        : "=r"(a) : "l"(p));
    return a;
}
__device__ __forceinline__ void cp16(uint32_t dst, const void* src) {
    asm volatile("cp.async.cg.shared.global [%0], [%1], 16;"
        :: "r"(dst), "l"(src) : "memory");
}
__device__ __forceinline__ void cp_commit() {
    asm volatile("cp.async.commit_group;" ::: "memory");
}
__device__ __forceinline__ void cp_wait1() {
    asm volatile("cp.async.wait_group 1;" ::: "memory");
}
__device__ __forceinline__ void cp_wait0() {
    asm volatile("cp.async.wait_group 0;" ::: "memory");
}
__device__ __forceinline__ void ldsm4(uint32_t* r, uint32_t a) {
    asm volatile("ldmatrix.sync.aligned.m8n8.x4.shared.b16 {%0,%1,%2,%3}, [%4];"
        : "=r"(r[0]), "=r"(r[1]), "=r"(r[2]), "=r"(r[3]) : "r"(a));
}
__device__ __forceinline__ void mma16816(float* d, const uint32_t* a, const uint32_t* b) {
    asm volatile("mma.sync.aligned.m16n8k16.row.col.f32.bf16.bf16.f32 "
        "{%0,%1,%2,%3}, {%4,%5,%6,%7}, {%8,%9}, {%0,%1,%2,%3};"
        : "+f"(d[0]), "+f"(d[1]), "+f"(d[2]), "+f"(d[3])
        : "r"(a[0]), "r"(a[1]), "r"(a[2]), "r"(a[3]), "r"(b[0]), "r"(b[1]));
}
__device__ __forceinline__ void split_bf16(float v, bf16& h, bf16& l) {
    h = __float2bfloat16(v);
    l = __float2bfloat16(v - __bfloat162float(h));
}

// ---------------- mma.sync split-bf16 GEMM, 128x256 CTA tile ----------------
#define TILE_A   16384          // 128x64 bf16 tile (A hi or lo)
#define TILE_BB  32768          // 256x64 bf16 tile (B hi or lo)
#define STAGE_B  (2*TILE_A + 2*TILE_BB)   // 98304
#define MMA_SMEM (1024 + 2*STAGE_B)       // 197632

extern __shared__ char smem_dyn_c[];

// cp.async one tile (nri*256 16B-chunks) with SW128 swizzle
__device__ __forceinline__ void tile_cp(const bf16* __restrict__ src, int rowBase,
                                        int Kstride, int kc, uint32_t dstBase,
                                        int tid, int nri)
{
#pragma unroll
    for (int j = 0; j < 8; j++) {
        if (j >= nri) break;
        int i = tid + j * 256;
        int r = i >> 3, ck = i & 7;
        const bf16* s = src + (size_t)(rowBase + r) * Kstride + kc * 64 + ck * 8;
        uint32_t off = (uint32_t)(r * 128 + ((ck * 16) ^ ((r & 7) << 4)));
        cp16(dstBase + off, s);
    }
}

__global__ __launch_bounds__(256)
void mma_gemm(const bf16* __restrict__ Ah, const bf16* __restrict__ Al,
              const bf16* __restrict__ Bh, const bf16* __restrict__ Bl,
              const float* __restrict__ bias,
              float* __restrict__ Cf, bf16* __restrict__ Ch, bf16* __restrict__ Cl,
              int strideC, int Kpad, int Kout, int doRelu)
{
    char* smem = smem_dyn_c;
    const uint32_t sbase = smem_u32(smem);
    float* Sb = (float*)smem;                 // 256 bias floats
    const uint32_t tiles0 = sbase + 1024;
    const int tid  = threadIdx.x;
    const int wid  = tid >> 5;
    const int lane = tid & 31;
    const int wm   = wid >> 2;                // 0..1 : 64 rows
    const int wn   = wid & 3;                 // 0..3 : 64 cols
    const int bRow = blockIdx.y * 128;
    const int bCol = blockIdx.x * 256;

    Sb[tid] = bias[bCol + tid];

    uint32_t aOff[4], bOff[4];
    {
        int khalfA = ((lane >> 4) & 1) * 16;
#pragma unroll
        for (int mf = 0; mf < 4; mf++) {
            int r = wm * 64 + mf * 16 + ((lane >> 3) & 1) * 8 + (lane & 7);
            aOff[mf] = (uint32_t)(r * 128 + (khalfA ^ ((r & 7) << 4)));
        }
        int khalfB = ((lane >> 3) & 1) * 16;
#pragma unroll
        for (int nb = 0; nb < 4; nb++) {
            int r = wn * 64 + nb * 16 + ((lane >> 4) & 1) * 8 + (lane & 7);
            bOff[nb] = (uint32_t)(r * 128 + (khalfB ^ ((r & 7) << 4)));
        }
    }

    float acc[4][8][4];
#pragma unroll
    for (int i = 0; i < 4; i++)
#pragma unroll
        for (int j = 0; j < 8; j++)
#pragma unroll
            for (int c = 0; c < 4; c++) acc[i][j][c] = 0.f;

    const int T = Kpad / 64;

    tile_cp(Ah, bRow, Kpad, 0, tiles0,                       tid, 4);
    tile_cp(Al, bRow, Kpad, 0, tiles0 + TILE_A,              tid, 4);
    tile_cp(Bh, bCol, Kpad, 0, tiles0 + 2*TILE_A,            tid, 8);
    tile_cp(Bl, bCol, Kpad, 0, tiles0 + 2*TILE_A + TILE_BB,  tid, 8);
    cp_commit();

    for (int t = 0; t < T; t++) {
        __syncthreads();
        if (t + 1 < T) {
            uint32_t st = tiles0 + ((t + 1) & 1) * STAGE_B;
            tile_cp(Ah, bRow, Kpad, t + 1, st,                      tid, 4);
            tile_cp(Al, bRow, Kpad, t + 1, st + TILE_A,             tid, 4);
            tile_cp(Bh, bCol, Kpad, t + 1, st + 2*TILE_A,           tid, 8);
            tile_cp(Bl, bCol, Kpad, t + 1, st + 2*TILE_A + TILE_BB, tid, 8);
            cp_commit();
            cp_wait1();
        } else {
            cp_wait0();
        }
        __syncthreads();

        const uint32_t st  = tiles0 + (t & 1) * STAGE_B;
        const uint32_t tAh = st, tAl = st + TILE_A;
        const uint32_t tBh = st + 2*TILE_A, tBl = st + 2*TILE_A + TILE_BB;

#pragma unroll
        for (int ks = 0; ks < 4; ks++) {
            const uint32_t kx = (uint32_t)(ks << 5);
            uint32_t ah[4][4], al[4][4], bb[4][4];
#pragma unroll
            for (int mf = 0; mf < 4; mf++) ldsm4(ah[mf], tAh + (aOff[mf] ^ kx));
#pragma unroll
            for (int mf = 0; mf < 4; mf++) ldsm4(al[mf], tAl + (aOff[mf] ^ kx));
#pragma unroll
            for (int nb = 0; nb < 4; nb++) ldsm4(bb[nb], tBh + (bOff[nb] ^ kx));
#pragma unroll
            for (int mf = 0; mf < 4; mf++)
#pragma unroll
                for (int nf = 0; nf < 8; nf++)
                    mma16816(acc[mf][nf], ah[mf], &bb[nf >> 1][(nf & 1) * 2]);
#pragma unroll
            for (int mf = 0; mf < 4; mf++)
#pragma unroll
                for (int nf = 0; nf < 8; nf++)
                    mma16816(acc[mf][nf], al[mf], &bb[nf >> 1][(nf & 1) * 2]);
#pragma unroll
            for (int nb = 0; nb < 4; nb++) ldsm4(bb[nb], tBl + (bOff[nb] ^ kx));
#pragma unroll
            for (int mf = 0; mf < 4; mf++)
#pragma unroll
                for (int nf = 0; nf < 8; nf++)
                    mma16816(acc[mf][nf], ah[mf], &bb[nf >> 1][(nf & 1) * 2]);
        }
    }

    // ---- epilogue ----
#pragma unroll
    for (int mf = 0; mf < 4; mf++) {
        int r0 = bRow + wm * 64 + mf * 16 + (lane >> 2);
#pragma unroll
        for (int nf = 0; nf < 8; nf++) {
            int cloc = wn * 64 + nf * 8 + (lane & 3) * 2;
            int c0 = bCol + cloc;
            float b0 = Sb[cloc], b1 = Sb[cloc + 1];
            float v0 = acc[mf][nf][0] + b0;
            float v1 = acc[mf][nf][1] + b1;
            float v2 = acc[mf][nf][2] + b0;
            float v3 = acc[mf][nf][3] + b1;
            if (doRelu) {
                v0 = fmaxf(v0, 0.f); v1 = fmaxf(v1, 0.f);
                v2 = fmaxf(v2, 0.f); v3 = fmaxf(v3, 0.f);
            }
            if (Cf) {
                size_t o0 = (size_t)r0 * Kout + c0;
                size_t o1 = (size_t)(r0 + 8) * Kout + c0;
                *(float2*)&Cf[o0] = make_float2(v0, v1);
                *(float2*)&Cf[o1] = make_float2(v2, v3);
            }
            if (Ch) {
                size_t o0 = (size_t)r0 * strideC + c0;
                size_t o1 = (size_t)(r0 + 8) * strideC + c0;
                bf16 h0, l0, h1, l1;
                split_bf16(v0, h0, l0); split_bf16(v1, h1, l1);
                __nv_bfloat162 hp, lp;
                hp.x = h0; hp.y = h1; lp.x = l0; lp.y = l1;
                *(__nv_bfloat162*)&Ch[o0] = hp;
                *(__nv_bfloat162*)&Cl[o0] = lp;
                split_bf16(v2, h0, l0); split_bf16(v3, h1, l1);
                hp.x = h0; hp.y = h1; lp.x = l0; lp.y = l1;
                *(__nv_bfloat162*)&Ch[o1] = hp;
                *(__nv_bfloat162*)&Cl[o1] = lp;
            }
        }
    }
}

// ---------------- weight split (transpose + pad + bf16 hi/lo) ----------------
__global__ void w_split(const float* __restrict__ W, bf16* __restrict__ hi,
                        bf16* __restrict__ lo, int Kin, int Kout, int Kpad)
{
    int id = blockIdx.x * 256 + threadIdx.x;
    if (id >= Kout * Kpad) return;
    int n = id / Kpad, k = id - n * Kpad;
    float v = (k < Kin) ? W[(size_t)k * Kout + n] : 0.f;
    bf16 h, l; split_bf16(v, h, l);
    hi[id] = h; lo[id] = l;
}

// ---------------- layer 1: feats(6) -> h1(256) relu, split ----------------
__global__ void h1_kernel(const float* __restrict__ feats, const float* __restrict__ w1,
                          const float* __restrict__ b1, bf16* __restrict__ hh,
                          bf16* __restrict__ hl)
{
    int id = blockIdx.x * 256 + threadIdx.x;
    int p = id >> 8, j = id & 255;
    const float* f = feats + (size_t)p * 6;
    float acc = b1[j];
#pragma unroll
    for (int k = 0; k < 6; k++) acc = fmaf(f[k], w1[k * 256 + j], acc);
    acc = fmaxf(acc, 0.f);
    bf16 h, l; split_bf16(acc, h, l);
    hh[id] = h; hl[id] = l;
}

// ---------------- zin tail: cols 768..831 = coords4 | 0 ----------------
__global__ void zin_tail(const float* __restrict__ coords,
                         bf16* __restrict__ zh, bf16* __restrict__ zl)
{
    int id = blockIdx.x * 256 + threadIdx.x;     // NPT*64
    int n = id >> 6, c = 768 + (id & 63);
    float v = (c < 772) ? coords[(size_t)n * 5 + 1 + (c - 768)] : 0.f;
    bf16 h, l; split_bf16(v, h, l);
    zh[(size_t)n * ZK + c] = h; zl[(size_t)n * ZK + c] = l;
}

// ---------------- LayerNorm + split: z1 fp32 -> zn hi/lo bf16 ----------------
__global__ __launch_bounds__(256) void ln_split(
    const float* __restrict__ z1, const float* __restrict__ ln_g,
    const float* __restrict__ ln_b, bf16* __restrict__ zh, bf16* __restrict__ zl)
{
    const int tid = threadIdx.x, w = tid >> 5, lane = tid & 31;
    const int p = blockIdx.x * 8 + w;
    float vals[8];
    float s = 0.f, s2 = 0.f;
#pragma unroll
    for (int j = 0; j < 8; j++) {
        float v = z1[(size_t)p * IHD + lane + j * 32];
        vals[j] = v; s += v; s2 += v * v;
    }
#pragma unroll
    for (int off = 16; off > 0; off >>= 1) {
        s  += __shfl_xor_sync(0xFFFFFFFFu, s,  off);
        s2 += __shfl_xor_sync(0xFFFFFFFFu, s2, off);
    }
    float mu  = s * (1.f / IHD);
    float var = s2 * (1.f / IHD) - mu * mu;
    float inv = rsqrtf(var + 1e-5f);
#pragma unroll
    for (int j = 0; j < 8; j++) {
        int c = lane + j * 32;
        float v = (vals[j] - mu) * inv * ln_g[c] + ln_b[c];
        bf16 h, l; split_bf16(v, h, l);
        zh[(size_t)p * IHD + c] = h; zl[(size_t)p * IHD + c] = l;
    }
}

// ---------------- imp = z2 @ iw3 + ib3 ----------------
__global__ __launch_bounds__(256) void imp_dot(
    const float* __restrict__ z2, const float* __restrict__ iw3,
    const float* __restrict__ ib3, float* __restrict__ imp)
{
    __shared__ float w3s[IHD];
    const int tid = threadIdx.x, w = tid >> 5, lane = tid & 31;
    w3s[tid] = iw3[tid];
    __syncthreads();
    const int p = blockIdx.x * 8 + w;
    float acc = 0.f;
#pragma unroll
    for (int j = 0; j < 8; j++) {
        int c = lane + j * 32;
        acc = fmaf(z2[(size_t)p * IHD + c], w3s[c], acc);
    }
#pragma unroll
    for (int off = 16; off > 0; off >>= 1)
        acc += __shfl_xor_sync(0xFFFFFFFFu, acc, off);
    if (lane == 0) imp[p] = acc + ib3[0];
}

// ---------------- per-batch top-128 via radix select + sort by t ----------------
__global__ __launch_bounds__(1024) void topk_kernel(
    const float* __restrict__ imp, const float* __restrict__ coords,
    const float* __restrict__ noise,
    int* __restrict__ sel_out, float* __restrict__ out_cents,
    float* __restrict__ out_masks)
{
    extern __shared__ uint32_t keys[];          // PP keys
    __shared__ uint32_t hist[256];
    __shared__ int sh_bucket, sh_target, gtCnt;
    __shared__ float selT[MT];
    __shared__ int   selI[MT];
    __shared__ int   red_i[1024];
    const int b   = blockIdx.x;
    const int tid = threadIdx.x;

    for (int i = tid; i < PP; i += 1024) {
        float v = imp[b * PP + i] + noise[b * PP + i];
        uint32_t u = __float_as_uint(v);
        keys[i] = (u & 0x80000000u) ? ~u : (u | 0x80000000u);
    }
    if (tid == 0) { sh_target = MT; gtCnt = 0; }
    __syncthreads();

    uint32_t pfx = 0, mask = 0;
#pragma unroll
    for (int B = 3; B >= 0; B--) {
        if (tid < 256) hist[tid] = 0u;
        __syncthreads();
        for (int i = tid; i < PP; i += 1024) {
            uint32_t k = keys[i];
            if ((k & mask) == pfx)
                atomicAdd(&hist[(k >> (8 * B)) & 0xFF], 1u);
        }
        __syncthreads();
        if (tid == 0) {
            int tgt = sh_target, cum = 0, bucket = 0;
            for (int v = 255; v >= 0; v--) {
                int h = (int)hist[v];
                if (cum + h >= tgt) { bucket = v; break; }
                cum += h;
            }
            sh_bucket = bucket;
            sh_target = tgt - cum;
        }
        __syncthreads();
        pfx |= ((uint32_t)sh_bucket) << (8 * B);
        mask |= 0xFFu << (8 * B);
        __syncthreads();
    }
    const uint32_t Kt = pfx;
    const int nEq = sh_target;

    for (int i = tid; i < PP; i += 1024) {
        if (keys[i] > Kt) {
            int pos = atomicAdd(&gtCnt, 1);
            selI[pos] = i;
        }
    }
    __syncthreads();
    int base = gtCnt;
    int last = -1;
    for (int r = 0; r < nEq; r++) {
        int loc = 0x7FFFFFFF;
        for (int i = tid; i < PP; i += 1024)
            if (keys[i] == Kt && i > last && i < loc) loc = i;
        red_i[tid] = loc;
        __syncthreads();
        for (int off = 512; off > 0; off >>= 1) {
            if (tid < off) red_i[tid] = min(red_i[tid], red_i[tid + off]);
            __syncthreads();
        }
        if (tid == 0) selI[base + r] = red_i[0];
        last = red_i[0];
        __syncthreads();
    }

    if (tid < MT) selT[tid] = coords[((size_t)b * PP + selI[tid]) * 5 + 4];
    __syncthreads();

    for (int kk = 2; kk <= MT; kk <<= 1) {
        for (int j = kk >> 1; j > 0; j >>= 1) {
            if (tid < MT) {
                int ixj = tid ^ j;
                if (ixj > tid) {
                    bool up = ((tid & kk) == 0);
                    float a = selT[tid], c = selT[ixj];
                    if ((a > c) == up) {
                        selT[tid] = c; selT[ixj] = a;
                        int t0 = selI[tid]; selI[tid] = selI[ixj]; selI[ixj] = t0;
                    }
                }
            }
            __syncthreads();
        }
    }

    if (tid < MT) {
        int idx = selI[tid];
        sel_out[b * MT + tid] = idx;
#pragma unroll
        for (int c = 0; c < 4; c++)
            out_cents[((size_t)b * MT + tid) * 4 + c] =
                coords[((size_t)b * PP + idx) * 5 + 1 + c];
        out_masks[b * MT + tid] = 1.0f;
    }
}

// ---------------- per-centroid 16-NN + max-pool of pf (split out) ----------------
__global__ __launch_bounds__(256) void knn_pool_kernel(
    const int* __restrict__ sel, const float* __restrict__ coords,
    const float* __restrict__ pf, bf16* __restrict__ ph, bf16* __restrict__ pl)
{
    extern __shared__ float d2[];
    __shared__ float rv[256];
    __shared__ int   ri[256];
    __shared__ int   knn[KNN];
    const int g   = blockIdx.x;
    const int b   = g >> 7;
    const int tid = threadIdx.x;

    int ci = sel[g];
    const float* cp = &coords[((size_t)b * PP + ci) * 5 + 1];
    float cx = cp[0], cy = cp[1], cz = cp[2], ct = cp[3];

    for (int i = tid; i < PP; i += 256) {
        const float* p = &coords[((size_t)b * PP + i) * 5 + 1];
        float dx = p[0] - cx, dy = p[1] - cy, dz = p[2] - cz, dt = p[3] - ct;
        d2[i] = dx * dx + dy * dy + dz * dz + dt * dt;
    }
    __syncthreads();

    for (int s = 0; s < KNN; s++) {
        float best = INFINITY; int bi = 0x7FFFFFFF;
        for (int i = tid; i < PP; i += 256) {
            float v = d2[i];
            if (v < best) { best = v; bi = i; }
        }
        rv[tid] = best; ri[tid] = bi;
        __syncthreads();
        for (int off = 128; off > 0; off >>= 1) {
            if (tid < off) {
                float ov = rv[tid + off]; int oi = ri[tid + off];
                if (ov < rv[tid] || (ov == rv[tid] && oi < ri[tid])) {
                    rv[tid] = ov; ri[tid] = oi;
                }
            }
            __syncthreads();
        }
        if (tid == 0) { knn[s] = ri[0]; d2[ri[0]] = INFINITY; }
        __syncthreads();
    }

    for (int j = tid; j < TOKD; j += 256) {
        float m = -INFINITY;
#pragma unroll
        for (int s = 0; s < KNN; s++)
            m = fmaxf(m, pf[((size_t)b * PP + knn[s]) * TOKD + j]);
        bf16 h, l; split_bf16(m, h, l);
        ph[(size_t)g * TOKD + j] = h;
        pl[(size_t)g * TOKD + j] = l;
    }
}

// ---------------- launch ----------------
extern "C" void kernel_launch(void* const* d_in, const int* in_sizes, int n_in,
                              void* d_out, int out_size)
{
    const float* coords   = (const float*)d_in[0];
    const float* feats    = (const float*)d_in[1];
    const float* w1 = (const float*)d_in[3];  const float* b1 = (const float*)d_in[4];
    const float* w2 = (const float*)d_in[5];  const float* b2 = (const float*)d_in[6];
    const float* w3 = (const float*)d_in[7];  const float* b3 = (const float*)d_in[8];
    const float* w4 = (const float*)d_in[9];  const float* b4 = (const float*)d_in[10];
    const float* iw1 = (const float*)d_in[11]; const float* ib1 = (const float*)d_in[12];
    const float* ln_g = (const float*)d_in[13]; const float* ln_b = (const float*)d_in[14];
    const float* iw2 = (const float*)d_in[15]; const float* ib2 = (const float*)d_in[16];
    const float* iw3 = (const float*)d_in[17]; const float* ib3 = (const float*)d_in[18];
    const float* nw1 = (const float*)d_in[19]; const float* nb1 = (const float*)d_in[20];
    const float* nw2 = (const float*)d_in[21]; const float* nb2 = (const float*)d_in[22];
    const float* noise = (const float*)d_in[23];

    float* out        = (float*)d_out;
    float* out_tokens = out;
    float* out_cents  = out + (size_t)BSZ * MT * TOKD;
    float* out_masks  = out_cents + (size_t)BSZ * MT * 4;

    bf16 *h1h,*h1l,*h2h,*h2l,*h3h,*h3l,*zinh,*zinl,*ph,*pl,*t1h,*t1l;
    bf16 *w2h,*w2l,*w3h,*w3l,*w4h,*w4l,*iw1h,*iw1l,*iw2h,*iw2l,*nw1h,*nw1l,*nw2h,*nw2l;
    float *pf,*z1,*z2,*imp;
    int* sel;
    cudaGetSymbolAddress((void**)&h1h, g_h1h);  cudaGetSymbolAddress((void**)&h1l, g_h1l);
    cudaGetSymbolAddress((void**)&h2h, g_h2h);  cudaGetSymbolAddress((void**)&h2l, g_h2l);
    cudaGetSymbolAddress((void**)&h3h, g_h3h);  cudaGetSymbolAddress((void**)&h3l, g_h3l);
    cudaGetSymbolAddress((void**)&zinh, g_zinh); cudaGetSymbolAddress((void**)&zinl, g_zinl);
    cudaGetSymbolAddress((void**)&ph, g_ph);    cudaGetSymbolAddress((void**)&pl, g_pl);
    cudaGetSymbolAddress((void**)&t1h, g_t1h);  cudaGetSymbolAddress((void**)&t1l, g_t1l);
    cudaGetSymbolAddress((void**)&w2h, g_w2h);  cudaGetSymbolAddress((void**)&w2l, g_w2l);
    cudaGetSymbolAddress((void**)&w3h, g_w3h);  cudaGetSymbolAddress((void**)&w3l, g_w3l);
    cudaGetSymbolAddress((void**)&w4h, g_w4h);  cudaGetSymbolAddress((void**)&w4l, g_w4l);
    cudaGetSymbolAddress((void**)&iw1h, g_iw1h); cudaGetSymbolAddress((void**)&iw1l, g_iw1l);
    cudaGetSymbolAddress((void**)&iw2h, g_iw2h); cudaGetSymbolAddress((void**)&iw2l, g_iw2l);
    cudaGetSymbolAddress((void**)&nw1h, g_nw1h); cudaGetSymbolAddress((void**)&nw1l, g_nw1l);
    cudaGetSymbolAddress((void**)&nw2h, g_nw2h); cudaGetSymbolAddress((void**)&nw2l, g_nw2l);
    cudaGetSymbolAddress((void**)&pf,  g_pf);
    cudaGetSymbolAddress((void**)&z1,  g_z1);
    cudaGetSymbolAddress((void**)&z2,  g_z2);
    cudaGetSymbolAddress((void**)&imp, g_imp);
    cudaGetSymbolAddress((void**)&sel, g_sel);

    cudaFuncSetAttribute(mma_gemm,
        cudaFuncAttributeMaxDynamicSharedMemorySize, MMA_SMEM);
    cudaFuncSetAttribute(topk_kernel,
        cudaFuncAttributeMaxDynamicSharedMemorySize, PP * sizeof(uint32_t));
    cudaFuncSetAttribute(knn_pool_kernel,
        cudaFuncAttributeMaxDynamicSharedMemorySize, PP * sizeof(float));

    // weight prep
    w_split<<<(512*256 + 255)/256, 256>>>(w2,  w2h,  w2l,  256, 512, 256);
    w_split<<<(768*512 + 255)/256, 256>>>(w3,  w3h,  w3l,  512, 768, 512);
    w_split<<<(768*768 + 255)/256, 256>>>(w4,  w4h,  w4l,  768, 768, 768);
    w_split<<<(256*ZK  + 255)/256, 256>>>(iw1, iw1h, iw1l, 772, 256, ZK);
    w_split<<<(256*256 + 255)/256, 256>>>(iw2, iw2h, iw2l, 256, 256, 256);
    w_split<<<(768*768 + 255)/256, 256>>>(nw1, nw1h, nw1l, 768, 768, 768);
    w_split<<<(768*768 + 255)/256, 256>>>(nw2, nw2h, nw2l, 768, 768, 768);

    // layer 1 (K=6, direct)
    h1_kernel<<<NPT, 256>>>(feats, w1, b1, h1h, h1l);

    // layers 2-4 on tensor cores; L4 writes pf fp32 + zin split (cols 0..767)
    mma_gemm<<<dim3(2, NPT/128), 256, MMA_SMEM>>>(h1h, h1l, w2h, w2l, b2,
        nullptr, h2h, h2l, 512, 256, 512, 1);
    mma_gemm<<<dim3(3, NPT/128), 256, MMA_SMEM>>>(h2h, h2l, w3h, w3l, b3,
        nullptr, h3h, h3l, 768, 512, 768, 1);
    mma_gemm<<<dim3(3, NPT/128), 256, MMA_SMEM>>>(h3h, h3l, w4h, w4l, b4,
        pf, zinh, zinl, ZK, 768, 768, 0);
    zin_tail<<<(NPT*64)/256, 256>>>(coords, zinh, zinl);

    // importance head: iw1 GEMM -> LN -> iw2 GEMM -> dot iw3
    mma_gemm<<<dim3(1, NPT/128), 256, MMA_SMEM>>>(zinh, zinl, iw1h, iw1l, ib1,
        z1, nullptr, nullptr, 0, ZK, 256, 1);
    ln_split<<<NPT/8, 256>>>(z1, ln_g, ln_b, h1h, h1l);     // reuse h1 bufs as zn
    mma_gemm<<<dim3(1, NPT/128), 256, MMA_SMEM>>>(h1h, h1l, iw2h, iw2l, ib2,
        z2, nullptr, nullptr, 0, 256, 256, 1);
    imp_dot<<<NPT/8, 256>>>(z2, iw3, ib3, imp);

    // radix-select top-128 + sort + cents/masks
    topk_kernel<<<BSZ, 1024, PP * sizeof(uint32_t)>>>(
        imp, coords, noise, sel, out_cents, out_masks);
    // knn + max pool (writes split directly)
    knn_pool_kernel<<<BSZ * MT, 256, PP * sizeof(float)>>>(sel, coords, pf, ph, pl);
    // token MLP on tensor cores
    mma_gemm<<<dim3(3, (BSZ*MT)/128), 256, MMA_SMEM>>>(ph, pl, nw1h, nw1l, nb1,
        nullptr, t1h, t1l, 768, 768, 768, 1);
    mma_gemm<<<dim3(3, (BSZ*MT)/128), 256, MMA_SMEM>>>(t1h, t1l, nw2h, nw2l, nb2,
        out_tokens, nullptr, nullptr, 0, 768, 768, 0);
}

// round 8
// speedup vs baseline: 3.7821x; 1.0207x over previous
#include <cuda_runtime.h>
#include <cuda_bf16.h>
#include <math.h>
#include <stdint.h>

#define BSZ 8
#define PP  16384
#define NPT (BSZ*PP)       // 131072
#define TOKD 768
#define MT  128
#define KNN 16
#define IHD 256
#define ZK  832            // zin padded K (772 -> 13*64)

typedef __nv_bfloat16 bf16;

// ---------------- scratch (device globals) ----------------
__device__ bf16  g_h1h[(size_t)NPT*256];     // also reused as zn_hi after LN
__device__ bf16  g_h1l[(size_t)NPT*256];     // also reused as zn_lo
__device__ bf16  g_h2h[(size_t)NPT*512];
__device__ bf16  g_h2l[(size_t)NPT*512];
__device__ bf16  g_h3h[(size_t)NPT*768];
__device__ bf16  g_h3l[(size_t)NPT*768];
__device__ bf16  g_zinh[(size_t)NPT*ZK];
__device__ bf16  g_zinl[(size_t)NPT*ZK];
__device__ float g_imp[NPT];
__device__ int   g_sel[BSZ*MT];
__device__ bf16  g_ph[(size_t)BSZ*MT*768], g_pl[(size_t)BSZ*MT*768];
__device__ bf16  g_t1h[(size_t)BSZ*MT*768], g_t1l[(size_t)BSZ*MT*768];
// transposed split weights: layout [Kout][Kpad]
__device__ bf16  g_w2h[512*256],  g_w2l[512*256];
__device__ bf16  g_w3h[768*512],  g_w3l[768*512];
__device__ bf16  g_w4h[768*768],  g_w4l[768*768];
__device__ bf16  g_iw1h[256*ZK],  g_iw1l[256*ZK];
__device__ bf16  g_iw2h[256*256], g_iw2l[256*256];
__device__ bf16  g_nw1h[768*768], g_nw1l[768*768];
__device__ bf16  g_nw2h[768*768], g_nw2l[768*768];

// ---------------- PTX helpers (baseline ISA only) ----------------
__device__ __forceinline__ uint32_t smem_u32(const void* p) {
    uint32_t a;
    asm("{ .reg .u64 t; cvta.to.shared.u64 t, %1; cvt.u32.u64 %0, t; }"
        : "=r"(a) : "l"(p));
    return a;
}
__device__ __forceinline__ void cp16(uint32_t dst, const void* src) {
    asm volatile("cp.async.cg.shared.global [%0], [%1], 16;"
        :: "r"(dst), "l"(src) : "memory");
}
__device__ __forceinline__ void cp_commit() {
    asm volatile("cp.async.commit_group;" ::: "memory");
}
__device__ __forceinline__ void cp_wait1() {
    asm volatile("cp.async.wait_group 1;" ::: "memory");
}
__device__ __forceinline__ void cp_wait0() {
    asm volatile("cp.async.wait_group 0;" ::: "memory");
}
__device__ __forceinline__ void ldsm4(uint32_t* r, uint32_t a) {
    asm volatile("ldmatrix.sync.aligned.m8n8.x4.shared.b16 {%0,%1,%2,%3}, [%4];"
        : "=r"(r[0]), "=r"(r[1]), "=r"(r[2]), "=r"(r[3]) : "r"(a));
}
__device__ __forceinline__ void mma16816(float* d, const uint32_t* a, const uint32_t* b) {
    asm volatile("mma.sync.aligned.m16n8k16.row.col.f32.bf16.bf16.f32 "
        "{%0,%1,%2,%3}, {%4,%5,%6,%7}, {%8,%9}, {%0,%1,%2,%3};"
        : "+f"(d[0]), "+f"(d[1]), "+f"(d[2]), "+f"(d[3])
        : "r"(a[0]), "r"(a[1]), "r"(a[2]), "r"(a[3]), "r"(b[0]), "r"(b[1]));
}
__device__ __forceinline__ void split_bf16(float v, bf16& h, bf16& l) {
    h = __float2bfloat16(v);
    l = __float2bfloat16(v - __bfloat162float(h));
}

// ---------------- mma.sync split-bf16 GEMM, 128x256 CTA tile ----------------
#define TILE_A   16384          // 128x64 bf16 tile (A hi or lo)
#define TILE_BB  32768          // 256x64 bf16 tile (B hi or lo)
#define STAGE_B  (2*TILE_A + 2*TILE_BB)   // 98304
#define MMA_SMEM (1024 + 2*STAGE_B)       // 197632
#define RS 264                  // stash row stride (floats)

extern __shared__ char smem_dyn_c[];

// cp.async one tile (nri*256 16B-chunks) with SW128 swizzle
__device__ __forceinline__ void tile_cp(const bf16* __restrict__ src, int rowBase,
                                        int Kstride, int kc, uint32_t dstBase,
                                        int tid, int nri)
{
#pragma unroll
    for (int j = 0; j < 8; j++) {
        if (j >= nri) break;
        int i = tid + j * 256;
        int r = i >> 3, ck = i & 7;
        const bf16* s = src + (size_t)(rowBase + r) * Kstride + kc * 64 + ck * 8;
        uint32_t off = (uint32_t)(r * 128 + ((ck * 16) ^ ((r & 7) << 4)));
        cp16(dstBase + off, s);
    }
}

// mode: 0 = normal (Cf/Ch/Cl), 1 = LN+split (Ch/Cl = zn out), 2 = relu-dot-iw3 (impOut)
__global__ __launch_bounds__(256)
void mma_gemm(const bf16* __restrict__ Ah, const bf16* __restrict__ Al,
              const bf16* __restrict__ Bh, const bf16* __restrict__ Bl,
              const float* __restrict__ bias,
              float* __restrict__ Cf, bf16* __restrict__ Ch, bf16* __restrict__ Cl,
              int strideC, int Kpad, int Kout, int doRelu, int mode,
              const float* __restrict__ ln_g, const float* __restrict__ ln_b,
              const float* __restrict__ iw3, const float* __restrict__ ib3,
              float* __restrict__ impOut)
{
    char* smem = smem_dyn_c;
    const uint32_t sbase = smem_u32(smem);
    float* Sb = (float*)smem;                 // 256 bias floats
    const uint32_t tiles0 = sbase + 1024;
    const int tid  = threadIdx.x;
    const int wid  = tid >> 5;
    const int lane = tid & 31;
    const int wm   = wid >> 2;                // 0..1 : 64 rows
    const int wn   = wid & 3;                 // 0..3 : 64 cols
    const int bRow = blockIdx.y * 128;
    const int bCol = blockIdx.x * 256;

    Sb[tid] = bias[bCol + tid];

    uint32_t aOff[4], bOff[4];
    {
        int khalfA = ((lane >> 4) & 1) * 16;
#pragma unroll
        for (int mf = 0; mf < 4; mf++) {
            int r = wm * 64 + mf * 16 + ((lane >> 3) & 1) * 8 + (lane & 7);
            aOff[mf] = (uint32_t)(r * 128 + (khalfA ^ ((r & 7) << 4)));
        }
        int khalfB = ((lane >> 3) & 1) * 16;
#pragma unroll
        for (int nb = 0; nb < 4; nb++) {
            int r = wn * 64 + nb * 16 + ((lane >> 4) & 1) * 8 + (lane & 7);
            bOff[nb] = (uint32_t)(r * 128 + (khalfB ^ ((r & 7) << 4)));
        }
    }

    float acc[4][8][4];
#pragma unroll
    for (int i = 0; i < 4; i++)
#pragma unroll
        for (int j = 0; j < 8; j++)
#pragma unroll
            for (int c = 0; c < 4; c++) acc[i][j][c] = 0.f;

    const int T = Kpad / 64;

    tile_cp(Ah, bRow, Kpad, 0, tiles0,                       tid, 4);
    tile_cp(Al, bRow, Kpad, 0, tiles0 + TILE_A,              tid, 4);
    tile_cp(Bh, bCol, Kpad, 0, tiles0 + 2*TILE_A,            tid, 8);
    tile_cp(Bl, bCol, Kpad, 0, tiles0 + 2*TILE_A + TILE_BB,  tid, 8);
    cp_commit();

    for (int t = 0; t < T; t++) {
        __syncthreads();
        if (t + 1 < T) {
            uint32_t st = tiles0 + ((t + 1) & 1) * STAGE_B;
            tile_cp(Ah, bRow, Kpad, t + 1, st,                      tid, 4);
            tile_cp(Al, bRow, Kpad, t + 1, st + TILE_A,             tid, 4);
            tile_cp(Bh, bCol, Kpad, t + 1, st + 2*TILE_A,           tid, 8);
            tile_cp(Bl, bCol, Kpad, t + 1, st + 2*TILE_A + TILE_BB, tid, 8);
            cp_commit();
            cp_wait1();
        } else {
            cp_wait0();
        }
        __syncthreads();

        const uint32_t st  = tiles0 + (t & 1) * STAGE_B;
        const uint32_t tAh = st, tAl = st + TILE_A;
        const uint32_t tBh = st + 2*TILE_A, tBl = st + 2*TILE_A + TILE_BB;

#pragma unroll
        for (int ks = 0; ks < 4; ks++) {
            const uint32_t kx = (uint32_t)(ks << 5);
            uint32_t ah[4][4], al[4][4], bb[4][4];
#pragma unroll
            for (int mf = 0; mf < 4; mf++) ldsm4(ah[mf], tAh + (aOff[mf] ^ kx));
#pragma unroll
            for (int mf = 0; mf < 4; mf++) ldsm4(al[mf], tAl + (aOff[mf] ^ kx));
#pragma unroll
            for (int nb = 0; nb < 4; nb++) ldsm4(bb[nb], tBh + (bOff[nb] ^ kx));
#pragma unroll
            for (int mf = 0; mf < 4; mf++)
#pragma unroll
                for (int nf = 0; nf < 8; nf++)
                    mma16816(acc[mf][nf], ah[mf], &bb[nf >> 1][(nf & 1) * 2]);
#pragma unroll
            for (int mf = 0; mf < 4; mf++)
#pragma unroll
                for (int nf = 0; nf < 8; nf++)
                    mma16816(acc[mf][nf], al[mf], &bb[nf >> 1][(nf & 1) * 2]);
#pragma unroll
            for (int nb = 0; nb < 4; nb++) ldsm4(bb[nb], tBl + (bOff[nb] ^ kx));
#pragma unroll
            for (int mf = 0; mf < 4; mf++)
#pragma unroll
                for (int nf = 0; nf < 8; nf++)
                    mma16816(acc[mf][nf], ah[mf], &bb[nf >> 1][(nf & 1) * 2]);
        }
    }

    if (mode == 0) {
        // ---- normal epilogue ----
#pragma unroll
        for (int mf = 0; mf < 4; mf++) {
            int r0 = bRow + wm * 64 + mf * 16 + (lane >> 2);
#pragma unroll
            for (int nf = 0; nf < 8; nf++) {
                int cloc = wn * 64 + nf * 8 + (lane & 3) * 2;
                int c0 = bCol + cloc;
                float b0 = Sb[cloc], b1 = Sb[cloc + 1];
                float v0 = acc[mf][nf][0] + b0;
                float v1 = acc[mf][nf][1] + b1;
                float v2 = acc[mf][nf][2] + b0;
                float v3 = acc[mf][nf][3] + b1;
                if (doRelu) {
                    v0 = fmaxf(v0, 0.f); v1 = fmaxf(v1, 0.f);
                    v2 = fmaxf(v2, 0.f); v3 = fmaxf(v3, 0.f);
                }
                if (Cf) {
                    size_t o0 = (size_t)r0 * Kout + c0;
                    size_t o1 = (size_t)(r0 + 8) * Kout + c0;
                    *(float2*)&Cf[o0] = make_float2(v0, v1);
                    *(float2*)&Cf[o1] = make_float2(v2, v3);
                }
                if (Ch) {
                    size_t o0 = (size_t)r0 * strideC + c0;
                    size_t o1 = (size_t)(r0 + 8) * strideC + c0;
                    bf16 h0, l0, h1, l1;
                    split_bf16(v0, h0, l0); split_bf16(v1, h1, l1);
                    __nv_bfloat162 hp, lp;
                    hp.x = h0; hp.y = h1; lp.x = l0; lp.y = l1;
                    *(__nv_bfloat162*)&Ch[o0] = hp;
                    *(__nv_bfloat162*)&Cl[o0] = lp;
                    split_bf16(v2, h0, l0); split_bf16(v3, h1, l1);
                    hp.x = h0; hp.y = h1; lp.x = l0; lp.y = l1;
                    *(__nv_bfloat162*)&Ch[o1] = hp;
                    *(__nv_bfloat162*)&Cl[o1] = lp;
                }
            }
        }
    } else {
        // ---- fused epilogues: stash post-bias(+relu) tile in smem ----
        __syncthreads();     // all warps done reading tile smem
        float* St = (float*)(smem + 1024);           // [128][RS]
        float* w3s = (float*)(smem + 1024 + 128 * RS * 4);  // 256 floats (mode 2)
#pragma unroll
        for (int mf = 0; mf < 4; mf++) {
            int rl = wm * 64 + mf * 16 + (lane >> 2);
#pragma unroll
            for (int nf = 0; nf < 8; nf++) {
                int cloc = wn * 64 + nf * 8 + (lane & 3) * 2;
                float b0 = Sb[cloc], b1 = Sb[cloc + 1];
                St[rl * RS + cloc]           = fmaxf(acc[mf][nf][0] + b0, 0.f);
                St[rl * RS + cloc + 1]       = fmaxf(acc[mf][nf][1] + b1, 0.f);
                St[(rl + 8) * RS + cloc]     = fmaxf(acc[mf][nf][2] + b0, 0.f);
                St[(rl + 8) * RS + cloc + 1] = fmaxf(acc[mf][nf][3] + b1, 0.f);
            }
        }
        if (mode == 2) w3s[tid] = iw3[tid];
        __syncthreads();

        if (mode == 1) {
            // LayerNorm each of my warp's 16 rows, write split zn
#pragma unroll
            for (int rr = 0; rr < 16; rr++) {
                int r = wid * 16 + rr;
                float vals[8];
                float s = 0.f, s2 = 0.f;
#pragma unroll
                for (int j = 0; j < 8; j++) {
                    float v = St[r * RS + lane + j * 32];
                    vals[j] = v; s += v; s2 += v * v;
                }
#pragma unroll
                for (int off = 16; off > 0; off >>= 1) {
                    s  += __shfl_xor_sync(0xFFFFFFFFu, s,  off);
                    s2 += __shfl_xor_sync(0xFFFFFFFFu, s2, off);
                }
                float mu  = s * (1.f / IHD);
                float var = s2 * (1.f / IHD) - mu * mu;
                float inv = rsqrtf(var + 1e-5f);
                size_t base = (size_t)(bRow + r) * IHD;
#pragma unroll
                for (int j = 0; j < 8; j++) {
                    int c = lane + j * 32;
                    float v = (vals[j] - mu) * inv * ln_g[c] + ln_b[c];
                    bf16 h, l; split_bf16(v, h, l);
                    Ch[base + c] = h; Cl[base + c] = l;
                }
            }
        } else {
            // dot each row with iw3, write imp
#pragma unroll
            for (int rr = 0; rr < 16; rr++) {
                int r = wid * 16 + rr;
                float a = 0.f;
#pragma unroll
                for (int j = 0; j < 8; j++) {
                    int c = lane + j * 32;
                    a = fmaf(St[r * RS + c], w3s[c], a);
                }
#pragma unroll
                for (int off = 16; off > 0; off >>= 1)
                    a += __shfl_xor_sync(0xFFFFFFFFu, a, off);
                if (lane == 0) impOut[bRow + r] = a + ib3[0];
            }
        }
    }
}

// ---------------- weight split (transpose + pad + bf16 hi/lo) ----------------
__global__ void w_split(const float* __restrict__ W, bf16* __restrict__ hi,
                        bf16* __restrict__ lo, int Kin, int Kout, int Kpad)
{
    int id = blockIdx.x * 256 + threadIdx.x;
    if (id >= Kout * Kpad) return;
    int n = id / Kpad, k = id - n * Kpad;
    float v = (k < Kin) ? W[(size_t)k * Kout + n] : 0.f;
    bf16 h, l; split_bf16(v, h, l);
    hi[id] = h; lo[id] = l;
}

// ---------------- layer 1: feats(6) -> h1(256) relu, split ----------------
__global__ void h1_kernel(const float* __restrict__ feats, const float* __restrict__ w1,
                          const float* __restrict__ b1, bf16* __restrict__ hh,
                          bf16* __restrict__ hl)
{
    int id = blockIdx.x * 256 + threadIdx.x;
    int p = id >> 8, j = id & 255;
    const float* f = feats + (size_t)p * 6;
    float acc = b1[j];
#pragma unroll
    for (int k = 0; k < 6; k++) acc = fmaf(f[k], w1[k * 256 + j], acc);
    acc = fmaxf(acc, 0.f);
    bf16 h, l; split_bf16(acc, h, l);
    hh[id] = h; hl[id] = l;
}

// ---------------- zin tail: cols 768..831 = coords4 | 0 ----------------
__global__ void zin_tail(const float* __restrict__ coords,
                         bf16* __restrict__ zh, bf16* __restrict__ zl)
{
    int id = blockIdx.x * 256 + threadIdx.x;     // NPT*64
    int n = id >> 6, c = 768 + (id & 63);
    float v = (c < 772) ? coords[(size_t)n * 5 + 1 + (c - 768)] : 0.f;
    bf16 h, l; split_bf16(v, h, l);
    zh[(size_t)n * ZK + c] = h; zl[(size_t)n * ZK + c] = l;
}

// ---------------- per-batch top-128 via radix select + sort by t ----------------
__global__ __launch_bounds__(1024) void topk_kernel(
    const float* __restrict__ imp, const float* __restrict__ coords,
    const float* __restrict__ noise,
    int* __restrict__ sel_out, float* __restrict__ out_cents,
    float* __restrict__ out_masks)
{
    extern __shared__ uint32_t keys[];          // PP keys
    __shared__ uint32_t hist[256];
    __shared__ int sh_bucket, sh_target, gtCnt;
    __shared__ float selT[MT];
    __shared__ int   selI[MT];
    __shared__ int   red_i[1024];
    const int b   = blockIdx.x;
    const int tid = threadIdx.x;

    for (int i = tid; i < PP; i += 1024) {
        float v = imp[b * PP + i] + noise[b * PP + i];
        uint32_t u = __float_as_uint(v);
        keys[i] = (u & 0x80000000u) ? ~u : (u | 0x80000000u);
    }
    if (tid == 0) { sh_target = MT; gtCnt = 0; }
    __syncthreads();

    uint32_t pfx = 0, mask = 0;
#pragma unroll
    for (int B = 3; B >= 0; B--) {
        if (tid < 256) hist[tid] = 0u;
        __syncthreads();
        for (int i = tid; i < PP; i += 1024) {
            uint32_t k = keys[i];
            if ((k & mask) == pfx)
                atomicAdd(&hist[(k >> (8 * B)) & 0xFF], 1u);
        }
        __syncthreads();
        if (tid == 0) {
            int tgt = sh_target, cum = 0, bucket = 0;
            for (int v = 255; v >= 0; v--) {
                int h = (int)hist[v];
                if (cum + h >= tgt) { bucket = v; break; }
                cum += h;
            }
            sh_bucket = bucket;
            sh_target = tgt - cum;
        }
        __syncthreads();
        pfx |= ((uint32_t)sh_bucket) << (8 * B);
        mask |= 0xFFu << (8 * B);
        __syncthreads();
    }
    const uint32_t Kt = pfx;
    const int nEq = sh_target;

    for (int i = tid; i < PP; i += 1024) {
        if (keys[i] > Kt) {
            int pos = atomicAdd(&gtCnt, 1);
            selI[pos] = i;
        }
    }
    __syncthreads();
    int base = gtCnt;
    int last = -1;
    for (int r = 0; r < nEq; r++) {
        int loc = 0x7FFFFFFF;
        for (int i = tid; i < PP; i += 1024)
            if (keys[i] == Kt && i > last && i < loc) loc = i;
        red_i[tid] = loc;
        __syncthreads();
        for (int off = 512; off > 0; off >>= 1) {
            if (tid < off) red_i[tid] = min(red_i[tid], red_i[tid + off]);
            __syncthreads();
        }
        if (tid == 0) selI[base + r] = red_i[0];
        last = red_i[0];
        __syncthreads();
    }

    if (tid < MT) selT[tid] = coords[((size_t)b * PP + selI[tid]) * 5 + 4];
    __syncthreads();

    for (int kk = 2; kk <= MT; kk <<= 1) {
        for (int j = kk >> 1; j > 0; j >>= 1) {
            if (tid < MT) {
                int ixj = tid ^ j;
                if (ixj > tid) {
                    bool up = ((tid & kk) == 0);
                    float a = selT[tid], c = selT[ixj];
                    if ((a > c) == up) {
                        selT[tid] = c; selT[ixj] = a;
                        int t0 = selI[tid]; selI[tid] = selI[ixj]; selI[ixj] = t0;
                    }
                }
            }
            __syncthreads();
        }
    }

    if (tid < MT) {
        int idx = selI[tid];
        sel_out[b * MT + tid] = idx;
#pragma unroll
        for (int c = 0; c < 4; c++)
            out_cents[((size_t)b * MT + tid) * 4 + c] =
                coords[((size_t)b * PP + idx) * 5 + 1 + c];
        out_masks[b * MT + tid] = 1.0f;
    }
}

// ---------------- per-centroid 16-NN + max-pool of zin (split out) ----------------
__global__ __launch_bounds__(256) void knn_pool_kernel(
    const int* __restrict__ sel, const float* __restrict__ coords,
    const bf16* __restrict__ zh, const bf16* __restrict__ zl,
    bf16* __restrict__ ph, bf16* __restrict__ pl)
{
    extern __shared__ float d2[];
    __shared__ float rv[256], lminS[256];
    __shared__ int   ri[256], largS[256];
    __shared__ int   knn[KNN];
    const int g   = blockIdx.x;
    const int b   = g >> 7;
    const int tid = threadIdx.x;

    int ci = sel[g];
    const float* cp = &coords[((size_t)b * PP + ci) * 5 + 1];
    float cx = cp[0], cy = cp[1], cz = cp[2], ct = cp[3];

    {
        float bm = INFINITY; int ba = 0x7FFFFFFF;
        for (int i = tid; i < PP; i += 256) {
            const float* p = &coords[((size_t)b * PP + i) * 5 + 1];
            float dx = p[0] - cx, dy = p[1] - cy, dz = p[2] - cz, dt = p[3] - ct;
            float v = dx * dx + dy * dy + dz * dz + dt * dt;
            d2[i] = v;
            if (v < bm) { bm = v; ba = i; }
        }
        lminS[tid] = bm; largS[tid] = ba;
    }
    __syncthreads();

    for (int s = 0; s < KNN; s++) {
        rv[tid] = lminS[tid]; ri[tid] = largS[tid];
        __syncthreads();
        for (int off = 128; off > 0; off >>= 1) {
            if (tid < off) {
                float ov = rv[tid + off]; int oi = ri[tid + off];
                if (ov < rv[tid] || (ov == rv[tid] && oi < ri[tid])) {
                    rv[tid] = ov; ri[tid] = oi;
                }
            }
            __syncthreads();
        }
        int win = ri[0];
        if (tid == 0) { knn[s] = win; d2[win] = INFINITY; }
        __syncthreads();
        if (tid == (win & 255)) {
            float bm = INFINITY; int ba = 0x7FFFFFFF;
            for (int i = tid; i < PP; i += 256) {
                float v = d2[i];
                if (v < bm) { bm = v; ba = i; }
            }
            lminS[tid] = bm; largS[tid] = ba;
        }
        __syncthreads();
    }

    for (int j = tid; j < TOKD; j += 256) {
        float m = -INFINITY;
#pragma unroll
        for (int s = 0; s < KNN; s++) {
            size_t o = (size_t)(b * PP + knn[s]) * ZK + j;
            m = fmaxf(m, __bfloat162float(zh[o]) + __bfloat162float(zl[o]));
        }
        bf16 h, l; split_bf16(m, h, l);
        ph[(size_t)g * TOKD + j] = h;
        pl[(size_t)g * TOKD + j] = l;
    }
}

// ---------------- launch ----------------
extern "C" void kernel_launch(void* const* d_in, const int* in_sizes, int n_in,
                              void* d_out, int out_size)
{
    const float* coords   = (const float*)d_in[0];
    const float* feats    = (const float*)d_in[1];
    const float* w1 = (const float*)d_in[3];  const float* b1 = (const float*)d_in[4];
    const float* w2 = (const float*)d_in[5];  const float* b2 = (const float*)d_in[6];
    const float* w3 = (const float*)d_in[7];  const float* b3 = (const float*)d_in[8];
    const float* w4 = (const float*)d_in[9];  const float* b4 = (const float*)d_in[10];
    const float* iw1 = (const float*)d_in[11]; const float* ib1 = (const float*)d_in[12];
    const float* ln_g = (const float*)d_in[13]; const float* ln_b = (const float*)d_in[14];
    const float* iw2 = (const float*)d_in[15]; const float* ib2 = (const float*)d_in[16];
    const float* iw3 = (const float*)d_in[17]; const float* ib3 = (const float*)d_in[18];
    const float* nw1 = (const float*)d_in[19]; const float* nb1 = (const float*)d_in[20];
    const float* nw2 = (const float*)d_in[21]; const float* nb2 = (const float*)d_in[22];
    const float* noise = (const float*)d_in[23];

    float* out        = (float*)d_out;
    float* out_tokens = out;
    float* out_cents  = out + (size_t)BSZ * MT * TOKD;
    float* out_masks  = out_cents + (size_t)BSZ * MT * 4;

    bf16 *h1h,*h1l,*h2h,*h2l,*h3h,*h3l,*zinh,*zinl,*ph,*pl,*t1h,*t1l;
    bf16 *w2h,*w2l,*w3h,*w3l,*w4h,*w4l,*iw1h,*iw1l,*iw2h,*iw2l,*nw1h,*nw1l,*nw2h,*nw2l;
    float *imp;
    int* sel;
    cudaGetSymbolAddress((void**)&h1h, g_h1h);  cudaGetSymbolAddress((void**)&h1l, g_h1l);
    cudaGetSymbolAddress((void**)&h2h, g_h2h);  cudaGetSymbolAddress((void**)&h2l, g_h2l);
    cudaGetSymbolAddress((void**)&h3h, g_h3h);  cudaGetSymbolAddress((void**)&h3l, g_h3l);
    cudaGetSymbolAddress((void**)&zinh, g_zinh); cudaGetSymbolAddress((void**)&zinl, g_zinl);
    cudaGetSymbolAddress((void**)&ph, g_ph);    cudaGetSymbolAddress((void**)&pl, g_pl);
    cudaGetSymbolAddress((void**)&t1h, g_t1h);  cudaGetSymbolAddress((void**)&t1l, g_t1l);
    cudaGetSymbolAddress((void**)&w2h, g_w2h);  cudaGetSymbolAddress((void**)&w2l, g_w2l);
    cudaGetSymbolAddress((void**)&w3h, g_w3h);  cudaGetSymbolAddress((void**)&w3l, g_w3l);
    cudaGetSymbolAddress((void**)&w4h, g_w4h);  cudaGetSymbolAddress((void**)&w4l, g_w4l);
    cudaGetSymbolAddress((void**)&iw1h, g_iw1h); cudaGetSymbolAddress((void**)&iw1l, g_iw1l);
    cudaGetSymbolAddress((void**)&iw2h, g_iw2h); cudaGetSymbolAddress((void**)&iw2l, g_iw2l);
    cudaGetSymbolAddress((void**)&nw1h, g_nw1h); cudaGetSymbolAddress((void**)&nw1l, g_nw1l);
    cudaGetSymbolAddress((void**)&nw2h, g_nw2h); cudaGetSymbolAddress((void**)&nw2l, g_nw2l);
    cudaGetSymbolAddress((void**)&imp, g_imp);
    cudaGetSymbolAddress((void**)&sel, g_sel);

    cudaFuncSetAttribute(mma_gemm,
        cudaFuncAttributeMaxDynamicSharedMemorySize, MMA_SMEM);
    cudaFuncSetAttribute(topk_kernel,
        cudaFuncAttributeMaxDynamicSharedMemorySize, PP * sizeof(uint32_t));
    cudaFuncSetAttribute(knn_pool_kernel,
        cudaFuncAttributeMaxDynamicSharedMemorySize, PP * sizeof(float));

    // weight prep
    w_split<<<(512*256 + 255)/256, 256>>>(w2,  w2h,  w2l,  256, 512, 256);
    w_split<<<(768*512 + 255)/256, 256>>>(w3,  w3h,  w3l,  512, 768, 512);
    w_split<<<(768*768 + 255)/256, 256>>>(w4,  w4h,  w4l,  768, 768, 768);
    w_split<<<(256*ZK  + 255)/256, 256>>>(iw1, iw1h, iw1l, 772, 256, ZK);
    w_split<<<(256*256 + 255)/256, 256>>>(iw2, iw2h, iw2l, 256, 256, 256);
    w_split<<<(768*768 + 255)/256, 256>>>(nw1, nw1h, nw1l, 768, 768, 768);
    w_split<<<(768*768 + 255)/256, 256>>>(nw2, nw2h, nw2l, 768, 768, 768);

    // layer 1 (K=6, direct)
    h1_kernel<<<NPT, 256>>>(feats, w1, b1, h1h, h1l);

    // layers 2-4 on tensor cores; L4 writes zin split (cols 0..767) directly
    mma_gemm<<<dim3(2, NPT/128), 256, MMA_SMEM>>>(h1h, h1l, w2h, w2l, b2,
        nullptr, h2h, h2l, 512, 256, 512, 1, 0, nullptr, nullptr, nullptr, nullptr, nullptr);
    mma_gemm<<<dim3(3, NPT/128), 256, MMA_SMEM>>>(h2h, h2l, w3h, w3l, b3,
        nullptr, h3h, h3l, 768, 512, 768, 1, 0, nullptr, nullptr, nullptr, nullptr, nullptr);
    mma_gemm<<<dim3(3, NPT/128), 256, MMA_SMEM>>>(h3h, h3l, w4h, w4l, b4,
        nullptr, zinh, zinl, ZK, 768, 768, 0, 0, nullptr, nullptr, nullptr, nullptr, nullptr);
    zin_tail<<<(NPT*64)/256, 256>>>(coords, zinh, zinl);

    // importance head: iw1 GEMM (fused LN+split) -> iw2 GEMM (fused iw3 dot)
    mma_gemm<<<dim3(1, NPT/128), 256, MMA_SMEM>>>(zinh, zinl, iw1h, iw1l, ib1,
        nullptr, h1h, h1l, IHD, ZK, 256, 1, 1, ln_g, ln_b, nullptr, nullptr, nullptr);
    mma_gemm<<<dim3(1, NPT/128), 256, MMA_SMEM>>>(h1h, h1l, iw2h, iw2l, ib2,
        nullptr, nullptr, nullptr, 0, 256, 256, 1, 2, nullptr, nullptr, iw3, ib3, imp);

    // radix-select top-128 + sort + cents/masks
    topk_kernel<<<BSZ, 1024, PP * sizeof(uint32_t)>>>(
        imp, coords, noise, sel, out_cents, out_masks);
    // knn + max pool (reads zin split, writes split directly)
    knn_pool_kernel<<<BSZ * MT, 256, PP * sizeof(float)>>>(
        sel, coords, zinh, zinl, ph, pl);
    // token MLP on tensor cores
    mma_gemm<<<dim3(3, (BSZ*MT)/128), 256, MMA_SMEM>>>(ph, pl, nw1h, nw1l, nb1,
        nullptr, t1h, t1l, 768, 768, 768, 1, 0, nullptr, nullptr, nullptr, nullptr, nullptr);
    mma_gemm<<<dim3(3, (BSZ*MT)/128), 256, MMA_SMEM>>>(t1h, t1l, nw2h, nw2l, nb2,
        out_tokens, nullptr, nullptr, 0, 768, 768, 0, 0, nullptr, nullptr, nullptr, nullptr, nullptr);
}

// round 9
// speedup vs baseline: 5.3599x; 1.4172x over previous
#include <cuda_runtime.h>
#include <cuda_bf16.h>
#include <math.h>
#include <stdint.h>

#define BSZ 8
#define PP  16384
#define NPT (BSZ*PP)       // 131072
#define TOKD 768
#define MT  128
#define KNN 16
#define IHD 256
#define NGRP (BSZ*MT)      // 1024 centroids
#define NGATH (NGRP*KNN)   // 16384 gathered rows

typedef __nv_bfloat16 bf16;

// ---------------- scratch (device globals) ----------------
__device__ bf16  g_h1h[(size_t)NPT*256];     // h1, later reused as zn_hi
__device__ bf16  g_h1l[(size_t)NPT*256];
__device__ bf16  g_h2h[(size_t)NPT*512];
__device__ bf16  g_h2l[(size_t)NPT*512];
__device__ bf16  g_h3h[(size_t)NPT*768];
__device__ bf16  g_h3l[(size_t)NPT*768];
__device__ float g_imp[NPT];
__device__ int   g_sel[NGRP];
__device__ int   g_knn[NGATH];
__device__ bf16  g_ph[(size_t)NGRP*768], g_pl[(size_t)NGRP*768];
__device__ bf16  g_t1h[(size_t)NGRP*768], g_t1l[(size_t)NGRP*768];
// transposed split weights: layout [Kout][Kpad]
__device__ bf16  g_w2h[512*256],  g_w2l[512*256];
__device__ bf16  g_w3h[768*512],  g_w3l[768*512];
__device__ bf16  g_w4h[768*768],  g_w4l[768*768];
__device__ bf16  g_wih[256*768],  g_wil[256*768];   // W4i = w4 @ iw1[0:768]
__device__ float g_b2[256];                          // ib1 + b4 @ iw1[0:768]
__device__ bf16  g_iw2h[256*256], g_iw2l[256*256];
__device__ bf16  g_nw1h[768*768], g_nw1l[768*768];
__device__ bf16  g_nw2h[768*768], g_nw2l[768*768];

// ---------------- PTX helpers (baseline ISA only) ----------------
__device__ __forceinline__ uint32_t smem_u32(const void* p) {
    uint32_t a;
    asm("{ .reg .u64 t; cvta.to.shared.u64 t, %1; cvt.u32.u64 %0, t; }"
        : "=r"(a) : "l"(p));
    return a;
}
__device__ __forceinline__ void cp16(uint32_t dst, const void* src) {
    asm volatile("cp.async.cg.shared.global [%0], [%1], 16;"
        :: "r"(dst), "l"(src) : "memory");
}
__device__ __forceinline__ void cp_commit() {
    asm volatile("cp.async.commit_group;" ::: "memory");
}
__device__ __forceinline__ void cp_wait1() {
    asm volatile("cp.async.wait_group 1;" ::: "memory");
}
__device__ __forceinline__ void cp_wait0() {
    asm volatile("cp.async.wait_group 0;" ::: "memory");
}
__device__ __forceinline__ void ldsm4(uint32_t* r, uint32_t a) {
    asm volatile("ldmatrix.sync.aligned.m8n8.x4.shared.b16 {%0,%1,%2,%3}, [%4];"
        : "=r"(r[0]), "=r"(r[1]), "=r"(r[2]), "=r"(r[3]) : "r"(a));
}
__device__ __forceinline__ void mma16816(float* d, const uint32_t* a, const uint32_t* b) {
    asm volatile("mma.sync.aligned.m16n8k16.row.col.f32.bf16.bf16.f32 "
        "{%0,%1,%2,%3}, {%4,%5,%6,%7}, {%8,%9}, {%0,%1,%2,%3};"
        : "+f"(d[0]), "+f"(d[1]), "+f"(d[2]), "+f"(d[3])
        : "r"(a[0]), "r"(a[1]), "r"(a[2]), "r"(a[3]), "r"(b[0]), "r"(b[1]));
}
__device__ __forceinline__ void split_bf16(float v, bf16& h, bf16& l) {
    h = __float2bfloat16(v);
    l = __float2bfloat16(v - __bfloat162float(h));
}

// ---------------- mma.sync split-bf16 GEMM, 128x256 CTA tile ----------------
#define TILE_A   16384          // 128x64 bf16 tile (A hi or lo)
#define TILE_BB  32768          // 256x64 bf16 tile (B hi or lo)
#define STAGE_B  (2*TILE_A + 2*TILE_BB)   // 98304
#define MMA_SMEM (1024 + 2*STAGE_B)       // 197632
#define RS 264                  // stash row stride (floats)

extern __shared__ char smem_dyn_c[];

// cp.async one tile (nri*256 16B-chunks) with SW128 swizzle; optional row indirection
__device__ __forceinline__ void tile_cp(const bf16* __restrict__ src, int rowBase,
                                        int Kstride, int kc, uint32_t dstBase,
                                        int tid, int nri, const int* __restrict__ rowIdx)
{
#pragma unroll
    for (int j = 0; j < 8; j++) {
        if (j >= nri) break;
        int i = tid + j * 256;
        int r = i >> 3, ck = i & 7;
        int gr = rowIdx ? rowIdx[rowBase + r] : (rowBase + r);
        const bf16* s = src + (size_t)gr * Kstride + kc * 64 + ck * 8;
        uint32_t off = (uint32_t)(r * 128 + ((ck * 16) ^ ((r & 7) << 4)));
        cp16(dstBase + off, s);
    }
}

// mode: 0 = normal (Cf/Ch/Cl out), 1 = coords-term + relu + LN + split (Ch/Cl = zn),
//       2 = relu + dot iw3 (impOut), 3 = 16-row max-pool + split (Ch/Cl = pooled)
__global__ __launch_bounds__(256)
void mma_gemm(const bf16* __restrict__ Ah, const bf16* __restrict__ Al,
              const bf16* __restrict__ Bh, const bf16* __restrict__ Bl,
              const float* __restrict__ bias,
              float* __restrict__ Cf, bf16* __restrict__ Ch, bf16* __restrict__ Cl,
              int strideC, int Kpad, int Kout, int doRelu, int mode,
              const float* __restrict__ ln_g, const float* __restrict__ ln_b,
              const float* __restrict__ iw3, const float* __restrict__ ib3,
              float* __restrict__ impOut,
              const int* __restrict__ rowIdx, const float* __restrict__ coords,
              const float* __restrict__ iw1full)
{
    char* smem = smem_dyn_c;
    const uint32_t sbase = smem_u32(smem);
    float* Sb = (float*)smem;                 // 256 bias floats
    const uint32_t tiles0 = sbase + 1024;
    const int tid  = threadIdx.x;
    const int wid  = tid >> 5;
    const int lane = tid & 31;
    const int wm   = wid >> 2;                // 0..1 : 64 rows
    const int wn   = wid & 3;                 // 0..3 : 64 cols
    const int bRow = blockIdx.y * 128;
    const int bCol = blockIdx.x * 256;

    Sb[tid] = bias[bCol + tid];

    uint32_t aOff[4], bOff[4];
    {
        int khalfA = ((lane >> 4) & 1) * 16;
#pragma unroll
        for (int mf = 0; mf < 4; mf++) {
            int r = wm * 64 + mf * 16 + ((lane >> 3) & 1) * 8 + (lane & 7);
            aOff[mf] = (uint32_t)(r * 128 + (khalfA ^ ((r & 7) << 4)));
        }
        int khalfB = ((lane >> 3) & 1) * 16;
#pragma unroll
        for (int nb = 0; nb < 4; nb++) {
            int r = wn * 64 + nb * 16 + ((lane >> 4) & 1) * 8 + (lane & 7);
            bOff[nb] = (uint32_t)(r * 128 + (khalfB ^ ((r & 7) << 4)));
        }
    }

    float acc[4][8][4];
#pragma unroll
    for (int i = 0; i < 4; i++)
#pragma unroll
        for (int j = 0; j < 8; j++)
#pragma unroll
            for (int c = 0; c < 4; c++) acc[i][j][c] = 0.f;

    const int T = Kpad / 64;

    tile_cp(Ah, bRow, Kpad, 0, tiles0,                       tid, 4, rowIdx);
    tile_cp(Al, bRow, Kpad, 0, tiles0 + TILE_A,              tid, 4, rowIdx);
    tile_cp(Bh, bCol, Kpad, 0, tiles0 + 2*TILE_A,            tid, 8, nullptr);
    tile_cp(Bl, bCol, Kpad, 0, tiles0 + 2*TILE_A + TILE_BB,  tid, 8, nullptr);
    cp_commit();

    for (int t = 0; t < T; t++) {
        __syncthreads();
        if (t + 1 < T) {
            uint32_t st = tiles0 + ((t + 1) & 1) * STAGE_B;
            tile_cp(Ah, bRow, Kpad, t + 1, st,                      tid, 4, rowIdx);
            tile_cp(Al, bRow, Kpad, t + 1, st + TILE_A,             tid, 4, rowIdx);
            tile_cp(Bh, bCol, Kpad, t + 1, st + 2*TILE_A,           tid, 8, nullptr);
            tile_cp(Bl, bCol, Kpad, t + 1, st + 2*TILE_A + TILE_BB, tid, 8, nullptr);
            cp_commit();
            cp_wait1();
        } else {
            cp_wait0();
        }
        __syncthreads();

        const uint32_t st  = tiles0 + (t & 1) * STAGE_B;
        const uint32_t tAh = st, tAl = st + TILE_A;
        const uint32_t tBh = st + 2*TILE_A, tBl = st + 2*TILE_A + TILE_BB;

#pragma unroll
        for (int ks = 0; ks < 4; ks++) {
            const uint32_t kx = (uint32_t)(ks << 5);
            uint32_t ah[4][4], al[4][4], bb[4][4];
#pragma unroll
            for (int mf = 0; mf < 4; mf++) ldsm4(ah[mf], tAh + (aOff[mf] ^ kx));
#pragma unroll
            for (int mf = 0; mf < 4; mf++) ldsm4(al[mf], tAl + (aOff[mf] ^ kx));
#pragma unroll
            for (int nb = 0; nb < 4; nb++) ldsm4(bb[nb], tBh + (bOff[nb] ^ kx));
#pragma unroll
            for (int mf = 0; mf < 4; mf++)
#pragma unroll
                for (int nf = 0; nf < 8; nf++)
                    mma16816(acc[mf][nf], ah[mf], &bb[nf >> 1][(nf & 1) * 2]);
#pragma unroll
            for (int mf = 0; mf < 4; mf++)
#pragma unroll
                for (int nf = 0; nf < 8; nf++)
                    mma16816(acc[mf][nf], al[mf], &bb[nf >> 1][(nf & 1) * 2]);
#pragma unroll
            for (int nb = 0; nb < 4; nb++) ldsm4(bb[nb], tBl + (bOff[nb] ^ kx));
#pragma unroll
            for (int mf = 0; mf < 4; mf++)
#pragma unroll
                for (int nf = 0; nf < 8; nf++)
                    mma16816(acc[mf][nf], ah[mf], &bb[nf >> 1][(nf & 1) * 2]);
        }
    }

    if (mode == 0) {
        // ---- normal epilogue ----
#pragma unroll
        for (int mf = 0; mf < 4; mf++) {
            int r0 = bRow + wm * 64 + mf * 16 + (lane >> 2);
#pragma unroll
            for (int nf = 0; nf < 8; nf++) {
                int cloc = wn * 64 + nf * 8 + (lane & 3) * 2;
                int c0 = bCol + cloc;
                float b0 = Sb[cloc], b1 = Sb[cloc + 1];
                float v0 = acc[mf][nf][0] + b0;
                float v1 = acc[mf][nf][1] + b1;
                float v2 = acc[mf][nf][2] + b0;
                float v3 = acc[mf][nf][3] + b1;
                if (doRelu) {
                    v0 = fmaxf(v0, 0.f); v1 = fmaxf(v1, 0.f);
                    v2 = fmaxf(v2, 0.f); v3 = fmaxf(v3, 0.f);
                }
                if (Cf) {
                    size_t o0 = (size_t)r0 * Kout + c0;
                    size_t o1 = (size_t)(r0 + 8) * Kout + c0;
                    *(float2*)&Cf[o0] = make_float2(v0, v1);
                    *(float2*)&Cf[o1] = make_float2(v2, v3);
                }
                if (Ch) {
                    size_t o0 = (size_t)r0 * strideC + c0;
                    size_t o1 = (size_t)(r0 + 8) * strideC + c0;
                    bf16 h0, l0, h1, l1;
                    split_bf16(v0, h0, l0); split_bf16(v1, h1, l1);
                    __nv_bfloat162 hp, lp;
                    hp.x = h0; hp.y = h1; lp.x = l0; lp.y = l1;
                    *(__nv_bfloat162*)&Ch[o0] = hp;
                    *(__nv_bfloat162*)&Cl[o0] = lp;
                    split_bf16(v2, h0, l0); split_bf16(v3, h1, l1);
                    hp.x = h0; hp.y = h1; lp.x = l0; lp.y = l1;
                    *(__nv_bfloat162*)&Ch[o1] = hp;
                    *(__nv_bfloat162*)&Cl[o1] = lp;
                }
            }
        }
    } else {
        // ---- fused epilogues: stash acc+bias (raw) tile in smem ----
        __syncthreads();     // all warps done reading tile smem
        float* St  = (float*)(smem + 1024);                       // [128][RS]
        float* Xs  = (float*)(smem + 1024 + 128 * RS * 4);        // 256 (mode 2: iw3)
        float* ciw = (float*)(smem + 1024 + 128 * RS * 4 + 1024); // [4][256] (mode 1)
        float* crd = ciw + 4 * 256;                               // [128][4] (mode 1)
#pragma unroll
        for (int mf = 0; mf < 4; mf++) {
            int rl = wm * 64 + mf * 16 + (lane >> 2);
#pragma unroll
            for (int nf = 0; nf < 8; nf++) {
                int cloc = wn * 64 + nf * 8 + (lane & 3) * 2;
                float b0 = Sb[cloc], b1 = Sb[cloc + 1];
                St[rl * RS + cloc]           = acc[mf][nf][0] + b0;
                St[rl * RS + cloc + 1]       = acc[mf][nf][1] + b1;
                St[(rl + 8) * RS + cloc]     = acc[mf][nf][2] + b0;
                St[(rl + 8) * RS + cloc + 1] = acc[mf][nf][3] + b1;
            }
        }
        if (mode == 2) Xs[tid] = iw3[tid];
        if (mode == 1) {
#pragma unroll
            for (int k = 0; k < 4; k++)
                ciw[k * 256 + tid] = iw1full[(768 + k) * 256 + tid];
            if (tid < 128) {
#pragma unroll
                for (int k = 0; k < 4; k++)
                    crd[tid * 4 + k] = coords[(size_t)(bRow + tid) * 5 + 1 + k];
            }
        }
        __syncthreads();

        if (mode == 1) {
            // coords-term + relu + LayerNorm per row, write split zn
#pragma unroll
            for (int rr = 0; rr < 16; rr++) {
                int r = wid * 16 + rr;
                float c0 = crd[r*4], c1 = crd[r*4+1], c2 = crd[r*4+2], c3 = crd[r*4+3];
                float vals[8];
                float s = 0.f, s2 = 0.f;
#pragma unroll
                for (int j = 0; j < 8; j++) {
                    int c = lane + j * 32;
                    float v = St[r * RS + c]
                        + c0 * ciw[c] + c1 * ciw[256 + c]
                        + c2 * ciw[512 + c] + c3 * ciw[768 + c];
                    v = fmaxf(v, 0.f);
                    vals[j] = v; s += v; s2 += v * v;
                }
#pragma unroll
                for (int off = 16; off > 0; off >>= 1) {
                    s  += __shfl_xor_sync(0xFFFFFFFFu, s,  off);
                    s2 += __shfl_xor_sync(0xFFFFFFFFu, s2, off);
                }
                float mu  = s * (1.f / IHD);
                float var = s2 * (1.f / IHD) - mu * mu;
                float inv = rsqrtf(var + 1e-5f);
                size_t base = (size_t)(bRow + r) * IHD;
#pragma unroll
                for (int j = 0; j < 8; j++) {
                    int c = lane + j * 32;
                    float v = (vals[j] - mu) * inv * ln_g[c] + ln_b[c];
                    bf16 h, l; split_bf16(v, h, l);
                    Ch[base + c] = h; Cl[base + c] = l;
                }
            }
        } else if (mode == 2) {
            // relu + dot each row with iw3, write imp
#pragma unroll
            for (int rr = 0; rr < 16; rr++) {
                int r = wid * 16 + rr;
                float a = 0.f;
#pragma unroll
                for (int j = 0; j < 8; j++) {
                    int c = lane + j * 32;
                    a = fmaf(fmaxf(St[r * RS + c], 0.f), Xs[c], a);
                }
#pragma unroll
                for (int off = 16; off > 0; off >>= 1)
                    a += __shfl_xor_sync(0xFFFFFFFFu, a, off);
                if (lane == 0) impOut[bRow + r] = a + ib3[0];
            }
        } else {
            // mode 3: max-pool each 16-row group, split, write pooled
#pragma unroll
            for (int gi = 0; gi < 8; gi++) {
                float m = -INFINITY;
#pragma unroll
                for (int s = 0; s < KNN; s++)
                    m = fmaxf(m, St[(gi * 16 + s) * RS + tid]);
                int grp = blockIdx.y * 8 + gi;
                bf16 h, l; split_bf16(m, h, l);
                Ch[(size_t)grp * TOKD + bCol + tid] = h;
                Cl[(size_t)grp * TOKD + bCol + tid] = l;
            }
        }
    }
}

// ---------------- weight split (transpose + pad + bf16 hi/lo) ----------------
__global__ void w_split(const float* __restrict__ W, bf16* __restrict__ hi,
                        bf16* __restrict__ lo, int Kin, int Kout, int Kpad)
{
    int id = blockIdx.x * 256 + threadIdx.x;
    if (id >= Kout * Kpad) return;
    int n = id / Kpad, k = id - n * Kpad;
    float v = (k < Kin) ? W[(size_t)k * Kout + n] : 0.f;
    bf16 h, l; split_bf16(v, h, l);
    hi[id] = h; lo[id] = l;
}

// ---------------- W4i = w4 @ iw1[0:768] (fp32), split to B layout ----------------
__global__ void wi_contract(const float* __restrict__ w4, const float* __restrict__ iw1,
                            bf16* __restrict__ wih, bf16* __restrict__ wil)
{
    int id = blockIdx.x * 256 + threadIdx.x;    // 768*256
    int j = id >> 8, cp = id & 255;
    float s = 0.f;
    for (int c = 0; c < 768; c++)
        s = fmaf(w4[j * 768 + c], iw1[c * 256 + cp], s);
    bf16 h, l; split_bf16(s, h, l);
    wih[cp * 768 + j] = h; wil[cp * 768 + j] = l;
}

__global__ void bias2_kernel(const float* __restrict__ b4, const float* __restrict__ iw1,
                             const float* __restrict__ ib1, float* __restrict__ b2)
{
    int cp = threadIdx.x;
    float s = ib1[cp];
    for (int c = 0; c < 768; c++)
        s = fmaf(b4[c], iw1[c * 256 + cp], s);
    b2[cp] = s;
}

// ---------------- layer 1: feats(6) -> h1(256) relu, split ----------------
__global__ void h1_kernel(const float* __restrict__ feats, const float* __restrict__ w1,
                          const float* __restrict__ b1, bf16* __restrict__ hh,
                          bf16* __restrict__ hl)
{
    int id = blockIdx.x * 256 + threadIdx.x;
    int p = id >> 8, j = id & 255;
    const float* f = feats + (size_t)p * 6;
    float acc = b1[j];
#pragma unroll
    for (int k = 0; k < 6; k++) acc = fmaf(f[k], w1[k * 256 + j], acc);
    acc = fmaxf(acc, 0.f);
    bf16 h, l; split_bf16(acc, h, l);
    hh[id] = h; hl[id] = l;
}

// ---------------- per-batch top-128 via radix select + sort by t ----------------
__global__ __launch_bounds__(1024) void topk_kernel(
    const float* __restrict__ imp, const float* __restrict__ coords,
    const float* __restrict__ noise,
    int* __restrict__ sel_out, float* __restrict__ out_cents,
    float* __restrict__ out_masks)
{
    extern __shared__ uint32_t keys[];          // PP keys
    __shared__ uint32_t hist[256];
    __shared__ int sh_bucket, sh_target, gtCnt;
    __shared__ float selT[MT];
    __shared__ int   selI[MT];
    __shared__ int   red_i[1024];
    const int b   = blockIdx.x;
    const int tid = threadIdx.x;

    for (int i = tid; i < PP; i += 1024) {
        float v = imp[b * PP + i] + noise[b * PP + i];
        uint32_t u = __float_as_uint(v);
        keys[i] = (u & 0x80000000u) ? ~u : (u | 0x80000000u);
    }
    if (tid == 0) { sh_target = MT; gtCnt = 0; }
    __syncthreads();

    uint32_t pfx = 0, mask = 0;
#pragma unroll
    for (int B = 3; B >= 0; B--) {
        if (tid < 256) hist[tid] = 0u;
        __syncthreads();
        for (int i = tid; i < PP; i += 1024) {
            uint32_t k = keys[i];
            if ((k & mask) == pfx)
                atomicAdd(&hist[(k >> (8 * B)) & 0xFF], 1u);
        }
        __syncthreads();
        if (tid == 0) {
            int tgt = sh_target, cum = 0, bucket = 0;
            for (int v = 255; v >= 0; v--) {
                int h = (int)hist[v];
                if (cum + h >= tgt) { bucket = v; break; }
                cum += h;
            }
            sh_bucket = bucket;
            sh_target = tgt - cum;
        }
        __syncthreads();
        pfx |= ((uint32_t)sh_bucket) << (8 * B);
        mask |= 0xFFu << (8 * B);
        __syncthreads();
    }
    const uint32_t Kt = pfx;
    const int nEq = sh_target;

    for (int i = tid; i < PP; i += 1024) {
        if (keys[i] > Kt) {
            int pos = atomicAdd(&gtCnt, 1);
            selI[pos] = i;
        }
    }
    __syncthreads();
    int base = gtCnt;
    int last = -1;
    for (int r = 0; r < nEq; r++) {
        int loc = 0x7FFFFFFF;
        for (int i = tid; i < PP; i += 1024)
            if (keys[i] == Kt && i > last && i < loc) loc = i;
        red_i[tid] = loc;
        __syncthreads();
        for (int off = 512; off > 0; off >>= 1) {
            if (tid < off) red_i[tid] = min(red_i[tid], red_i[tid + off]);
            __syncthreads();
        }
        if (tid == 0) selI[base + r] = red_i[0];
        last = red_i[0];
        __syncthreads();
    }

    if (tid < MT) selT[tid] = coords[((size_t)b * PP + selI[tid]) * 5 + 4];
    __syncthreads();

    for (int kk = 2; kk <= MT; kk <<= 1) {
        for (int j = kk >> 1; j > 0; j >>= 1) {
            if (tid < MT) {
                int ixj = tid ^ j;
                if (ixj > tid) {
                    bool up = ((tid & kk) == 0);
                    float a = selT[tid], c = selT[ixj];
                    if ((a > c) == up) {
                        selT[tid] = c; selT[ixj] = a;
                        int t0 = selI[tid]; selI[tid] = selI[ixj]; selI[ixj] = t0;
                    }
                }
            }
            __syncthreads();
        }
    }

    if (tid < MT) {
        int idx = selI[tid];
        sel_out[b * MT + tid] = idx;
#pragma unroll
        for (int c = 0; c < 4; c++)
            out_cents[((size_t)b * MT + tid) * 4 + c] =
                coords[((size_t)b * PP + idx) * 5 + 1 + c];
        out_masks[b * MT + tid] = 1.0f;
    }
}

// ---------------- per-centroid 16-NN (indices only) ----------------
__global__ __launch_bounds__(256) void knn_kernel(
    const int* __restrict__ sel, const float* __restrict__ coords,
    int* __restrict__ knnOut)
{
    extern __shared__ float d2[];
    __shared__ float rv[256], lminS[256];
    __shared__ int   ri[256], largS[256];
    __shared__ int   knn[KNN];
    const int g   = blockIdx.x;
    const int b   = g >> 7;
    const int tid = threadIdx.x;

    int ci = sel[g];
    const float* cp = &coords[((size_t)b * PP + ci) * 5 + 1];
    float cx = cp[0], cy = cp[1], cz = cp[2], ct = cp[3];

    {
        float bm = INFINITY; int ba = 0x7FFFFFFF;
        for (int i = tid; i < PP; i += 256) {
            const float* p = &coords[((size_t)b * PP + i) * 5 + 1];
            float dx = p[0] - cx, dy = p[1] - cy, dz = p[2] - cz, dt = p[3] - ct;
            float v = dx * dx + dy * dy + dz * dz + dt * dt;
            d2[i] = v;
            if (v < bm) { bm = v; ba = i; }
        }
        lminS[tid] = bm; largS[tid] = ba;
    }
    __syncthreads();

    for (int s = 0; s < KNN; s++) {
        rv[tid] = lminS[tid]; ri[tid] = largS[tid];
        __syncthreads();
        for (int off = 128; off > 0; off >>= 1) {
            if (tid < off) {
                float ov = rv[tid + off]; int oi = ri[tid + off];
                if (ov < rv[tid] || (ov == rv[tid] && oi < ri[tid])) {
                    rv[tid] = ov; ri[tid] = oi;
                }
            }
            __syncthreads();
        }
        int win = ri[0];
        if (tid == 0) { knn[s] = win; d2[win] = INFINITY; }
        __syncthreads();
        if (tid == (win & 255)) {
            float bm = INFINITY; int ba = 0x7FFFFFFF;
            for (int i = tid; i < PP; i += 256) {
                float v = d2[i];
                if (v < bm) { bm = v; ba = i; }
            }
            lminS[tid] = bm; largS[tid] = ba;
        }
        __syncthreads();
    }

    if (tid < KNN)
        knnOut[g * KNN + tid] = b * PP + knn[tid];
}

// ---------------- launch ----------------
extern "C" void kernel_launch(void* const* d_in, const int* in_sizes, int n_in,
                              void* d_out, int out_size)
{
    const float* coords   = (const float*)d_in[0];
    const float* feats    = (const float*)d_in[1];
    const float* w1 = (const float*)d_in[3];  const float* b1 = (const float*)d_in[4];
    const float* w2 = (const float*)d_in[5];  const float* b2in = (const float*)d_in[6];
    const float* w3 = (const float*)d_in[7];  const float* b3 = (const float*)d_in[8];
    const float* w4 = (const float*)d_in[9];  const float* b4 = (const float*)d_in[10];
    const float* iw1 = (const float*)d_in[11]; const float* ib1 = (const float*)d_in[12];
    const float* ln_g = (const float*)d_in[13]; const float* ln_b = (const float*)d_in[14];
    const float* iw2 = (const float*)d_in[15]; const float* ib2 = (const float*)d_in[16];
    const float* iw3 = (const float*)d_in[17]; const float* ib3 = (const float*)d_in[18];
    const float* nw1 = (const float*)d_in[19]; const float* nb1 = (const float*)d_in[20];
    const float* nw2 = (const float*)d_in[21]; const float* nb2 = (const float*)d_in[22];
    const float* noise = (const float*)d_in[23];

    float* out        = (float*)d_out;
    float* out_tokens = out;
    float* out_cents  = out + (size_t)NGRP * TOKD;
    float* out_masks  = out_cents + (size_t)NGRP * 4;

    bf16 *h1h,*h1l,*h2h,*h2l,*h3h,*h3l,*ph,*pl,*t1h,*t1l;
    bf16 *w2h,*w2l,*w3h,*w3l,*w4h,*w4l,*wih,*wil,*iw2h,*iw2l,*nw1h,*nw1l,*nw2h,*nw2l;
    float *imp,*b2;
    int *sel,*knnidx;
    cudaGetSymbolAddress((void**)&h1h, g_h1h);  cudaGetSymbolAddress((void**)&h1l, g_h1l);
    cudaGetSymbolAddress((void**)&h2h, g_h2h);  cudaGetSymbolAddress((void**)&h2l, g_h2l);
    cudaGetSymbolAddress((void**)&h3h, g_h3h);  cudaGetSymbolAddress((void**)&h3l, g_h3l);
    cudaGetSymbolAddress((void**)&ph, g_ph);    cudaGetSymbolAddress((void**)&pl, g_pl);
    cudaGetSymbolAddress((void**)&t1h, g_t1h);  cudaGetSymbolAddress((void**)&t1l, g_t1l);
    cudaGetSymbolAddress((void**)&w2h, g_w2h);  cudaGetSymbolAddress((void**)&w2l, g_w2l);
    cudaGetSymbolAddress((void**)&w3h, g_w3h);  cudaGetSymbolAddress((void**)&w3l, g_w3l);
    cudaGetSymbolAddress((void**)&w4h, g_w4h);  cudaGetSymbolAddress((void**)&w4l, g_w4l);
    cudaGetSymbolAddress((void**)&wih, g_wih);  cudaGetSymbolAddress((void**)&wil, g_wil);
    cudaGetSymbolAddress((void**)&iw2h, g_iw2h); cudaGetSymbolAddress((void**)&iw2l, g_iw2l);
    cudaGetSymbolAddress((void**)&nw1h, g_nw1h); cudaGetSymbolAddress((void**)&nw1l, g_nw1l);
    cudaGetSymbolAddress((void**)&nw2h, g_nw2h); cudaGetSymbolAddress((void**)&nw2l, g_nw2l);
    cudaGetSymbolAddress((void**)&imp, g_imp);
    cudaGetSymbolAddress((void**)&b2,  g_b2);
    cudaGetSymbolAddress((void**)&sel, g_sel);
    cudaGetSymbolAddress((void**)&knnidx, g_knn);

    cudaFuncSetAttribute(mma_gemm,
        cudaFuncAttributeMaxDynamicSharedMemorySize, MMA_SMEM);
    cudaFuncSetAttribute(topk_kernel,
        cudaFuncAttributeMaxDynamicSharedMemorySize, PP * sizeof(uint32_t));
    cudaFuncSetAttribute(knn_kernel,
        cudaFuncAttributeMaxDynamicSharedMemorySize, PP * sizeof(float));

    // launches 1-5 (so launch #6 = L2 GEMM gets profiled by ncu -s 5 -c 1)
    h1_kernel<<<NPT, 256>>>(feats, w1, b1, h1h, h1l);
    w_split<<<(512*256 + 255)/256, 256>>>(w2, w2h, w2l, 256, 512, 256);
    w_split<<<(768*512 + 255)/256, 256>>>(w3, w3h, w3l, 512, 768, 512);
    w_split<<<(768*768 + 255)/256, 256>>>(w4, w4h, w4l, 768, 768, 768);
    wi_contract<<<768, 256>>>(w4, iw1, wih, wil);

    // #6: L2 GEMM  (h1 -> h2)
    mma_gemm<<<dim3(2, NPT/128), 256, MMA_SMEM>>>(h1h, h1l, w2h, w2l, b2in,
        nullptr, h2h, h2l, 512, 256, 512, 1, 0,
        nullptr, nullptr, nullptr, nullptr, nullptr, nullptr, nullptr, nullptr);

    bias2_kernel<<<1, 256>>>(b4, iw1, ib1, b2);
    w_split<<<(256*256 + 255)/256, 256>>>(iw2, iw2h, iw2l, 256, 256, 256);
    w_split<<<(768*768 + 255)/256, 256>>>(nw1, nw1h, nw1l, 768, 768, 768);
    w_split<<<(768*768 + 255)/256, 256>>>(nw2, nw2h, nw2l, 768, 768, 768);

    // L3 GEMM (h2 -> h3)
    mma_gemm<<<dim3(3, NPT/128), 256, MMA_SMEM>>>(h2h, h2l, w3h, w3l, b3,
        nullptr, h3h, h3l, 768, 512, 768, 1, 0,
        nullptr, nullptr, nullptr, nullptr, nullptr, nullptr, nullptr, nullptr);

    // importance head: h3 @ W4i + coords term, fused relu+LN+split -> zn (reuse h1 bufs)
    mma_gemm<<<dim3(1, NPT/128), 256, MMA_SMEM>>>(h3h, h3l, wih, wil, b2,
        nullptr, h1h, h1l, 0, 768, 256, 0, 1,
        ln_g, ln_b, nullptr, nullptr, nullptr, nullptr, coords, iw1);
    // zn @ iw2, fused relu + iw3 dot -> imp
    mma_gemm<<<dim3(1, NPT/128), 256, MMA_SMEM>>>(h1h, h1l, iw2h, iw2l, ib2,
        nullptr, nullptr, nullptr, 0, 256, 256, 0, 2,
        nullptr, nullptr, iw3, ib3, imp, nullptr, nullptr, nullptr);

    // radix-select top-128 + sort + cents/masks
    topk_kernel<<<BSZ, 1024, PP * sizeof(uint32_t)>>>(
        imp, coords, noise, sel, out_cents, out_masks);
    // knn indices (coords only)
    knn_kernel<<<NGRP, 256, PP * sizeof(float)>>>(sel, coords, knnidx);

    // gathered L4 over neighbor rows only, fused 16-row max-pool + split -> pooled
    mma_gemm<<<dim3(3, NGATH/128), 256, MMA_SMEM>>>(h3h, h3l, w4h, w4l, b4,
        nullptr, ph, pl, 0, 768, 768, 0, 3,
        nullptr, nullptr, nullptr, nullptr, nullptr, knnidx, nullptr, nullptr);

    // token MLP
    mma_gemm<<<dim3(3, NGRP/128), 256, MMA_SMEM>>>(ph, pl, nw1h, nw1l, nb1,
        nullptr, t1h, t1l, 768, 768, 768, 1, 0,
        nullptr, nullptr, nullptr, nullptr, nullptr, nullptr, nullptr, nullptr);
    mma_gemm<<<dim3(3, NGRP/128), 256, MMA_SMEM>>>(t1h, t1l, nw2h, nw2l, nb2,
        out_tokens, nullptr, nullptr, 0, 768, 768, 0, 0,
        nullptr, nullptr, nullptr, nullptr, nullptr, nullptr, nullptr, nullptr);
}

// round 10
// speedup vs baseline: 5.3693x; 1.0018x over previous
#include <cuda_runtime.h>
#include <cuda_bf16.h>
#include <math.h>
#include <stdint.h>

#define BSZ 8
#define PP  16384
#define NPT (BSZ*PP)       // 131072
#define TOKD 768
#define MT  128
#define KNN 16
#define IHD 256
#define NGRP (BSZ*MT)      // 1024 centroids
#define NGATH (NGRP*KNN)   // 16384 gathered rows

typedef __nv_bfloat16 bf16;

// ---------------- scratch (device globals) ----------------
__device__ bf16  g_znh[(size_t)NPT*256];     // zn hi (post-LN)
__device__ bf16  g_znl[(size_t)NPT*256];
__device__ bf16  g_h2h[(size_t)NPT*512];
__device__ bf16  g_h2l[(size_t)NPT*512];
__device__ bf16  g_h3h[(size_t)NPT*768];
__device__ bf16  g_h3l[(size_t)NPT*768];
__device__ float g_imp[NPT];
__device__ float4 g_c4[NPT];
__device__ int   g_sel[NGRP];
__device__ int   g_knn[NGATH];
__device__ bf16  g_ph[(size_t)NGRP*768], g_pl[(size_t)NGRP*768];
__device__ bf16  g_t1h[(size_t)NGRP*768], g_t1l[(size_t)NGRP*768];
// transposed split weights: layout [Kout][Kpad]
__device__ bf16  g_w2h[512*256],  g_w2l[512*256];
__device__ bf16  g_w3h[768*512],  g_w3l[768*512];
__device__ bf16  g_w4h[768*768],  g_w4l[768*768];
__device__ bf16  g_wih[256*768],  g_wil[256*768];   // W4i = w4 @ iw1[0:768]
__device__ float g_b2[256];                          // ib1 + b4 @ iw1[0:768]
__device__ bf16  g_iw2h[256*256], g_iw2l[256*256];
__device__ bf16  g_nw1h[768*768], g_nw1l[768*768];
__device__ bf16  g_nw2h[768*768], g_nw2l[768*768];

// ---------------- PTX helpers (baseline ISA only) ----------------
__device__ __forceinline__ uint32_t smem_u32(const void* p) {
    uint32_t a;
    asm("{ .reg .u64 t; cvta.to.shared.u64 t, %1; cvt.u32.u64 %0, t; }"
        : "=r"(a) : "l"(p));
    return a;
}
__device__ __forceinline__ void cp16(uint32_t dst, const void* src) {
    asm volatile("cp.async.cg.shared.global [%0], [%1], 16;"
        :: "r"(dst), "l"(src) : "memory");
}
__device__ __forceinline__ void cp_commit() {
    asm volatile("cp.async.commit_group;" ::: "memory");
}
__device__ __forceinline__ void cp_wait1() {
    asm volatile("cp.async.wait_group 1;" ::: "memory");
}
__device__ __forceinline__ void cp_wait0() {
    asm volatile("cp.async.wait_group 0;" ::: "memory");
}
__device__ __forceinline__ void ldsm4(uint32_t* r, uint32_t a) {
    asm volatile("ldmatrix.sync.aligned.m8n8.x4.shared.b16 {%0,%1,%2,%3}, [%4];"
        : "=r"(r[0]), "=r"(r[1]), "=r"(r[2]), "=r"(r[3]) : "r"(a));
}
__device__ __forceinline__ void mma16816(float* d, const uint32_t* a, const uint32_t* b) {
    asm volatile("mma.sync.aligned.m16n8k16.row.col.f32.bf16.bf16.f32 "
        "{%0,%1,%2,%3}, {%4,%5,%6,%7}, {%8,%9}, {%0,%1,%2,%3};"
        : "+f"(d[0]), "+f"(d[1]), "+f"(d[2]), "+f"(d[3])
        : "r"(a[0]), "r"(a[1]), "r"(a[2]), "r"(a[3]), "r"(b[0]), "r"(b[1]));
}
__device__ __forceinline__ void split_bf16(float v, bf16& h, bf16& l) {
    h = __float2bfloat16(v);
    l = __float2bfloat16(v - __bfloat162float(h));
}
__device__ __forceinline__ uint32_t pack2(bf16 a, bf16 b) {
    __nv_bfloat162 t; t.x = a; t.y = b;
    return *(uint32_t*)&t;
}

// ---------------- mma.sync split-bf16 GEMM, 128x256 CTA tile ----------------
#define TILE_A   16384          // 128x64 bf16 tile (A hi or lo)
#define TILE_BB  32768          // 256x64 bf16 tile (B hi or lo)
#define STAGE_B  (2*TILE_A + 2*TILE_BB)   // 98304
#define EXTRA_OFF (1024 + 2*STAGE_B)      // 197632
#define MMA_SMEM (EXTRA_OFF + 10240)      // 207872 (w1s 6144 + b1s 1024 + fs 3072)
#define RS 264                  // stash row stride (floats)

extern __shared__ char smem_dyn_c[];

// cp.async one tile (nri*256 16B-chunks) with SW128 swizzle; optional row indirection
__device__ __forceinline__ void tile_cp(const bf16* __restrict__ src, int rowBase,
                                        int Kstride, int kc, uint32_t dstBase,
                                        int tid, int nri, const int* __restrict__ rowIdx)
{
#pragma unroll
    for (int j = 0; j < 8; j++) {
        if (j >= nri) break;
        int i = tid + j * 256;
        int r = i >> 3, ck = i & 7;
        int gr = rowIdx ? rowIdx[rowBase + r] : (rowBase + r);
        const bf16* s = src + (size_t)gr * Kstride + kc * 64 + ck * 8;
        uint32_t off = (uint32_t)(r * 128 + ((ck * 16) ^ ((r & 7) << 4)));
        cp16(dstBase + off, s);
    }
}

// generate h1 chunk (128 rows x 64 cols starting at kc*64) straight into smem tiles
__device__ __forceinline__ void gen_h1_tile(char* smem, char* dstAh, char* dstAl,
                                            int kc, int tid)
{
    const float* w1s = (const float*)(smem + EXTRA_OFF);
    const float* b1s = (const float*)(smem + EXTRA_OFF + 6144);
    const float* fs  = (const float*)(smem + EXTRA_OFF + 7168);
#pragma unroll
    for (int j = 0; j < 4; j++) {
        int i = tid + j * 256;
        int r = i >> 3, ck = i & 7;
        int c0 = kc * 64 + ck * 8;
        const float* fr = &fs[r * 6];
        float f0 = fr[0], f1 = fr[1], f2 = fr[2], f3 = fr[3], f4 = fr[4], f5 = fr[5];
        uint32_t hp[4], lp[4];
#pragma unroll
        for (int m = 0; m < 4; m++) {
            int ca = c0 + m * 2, cb = c0 + m * 2 + 1;
            float va = b1s[ca] + f0 * w1s[ca] + f1 * w1s[256 + ca] + f2 * w1s[512 + ca]
                     + f3 * w1s[768 + ca] + f4 * w1s[1024 + ca] + f5 * w1s[1280 + ca];
            float vb = b1s[cb] + f0 * w1s[cb] + f1 * w1s[256 + cb] + f2 * w1s[512 + cb]
                     + f3 * w1s[768 + cb] + f4 * w1s[1024 + cb] + f5 * w1s[1280 + cb];
            va = fmaxf(va, 0.f); vb = fmaxf(vb, 0.f);
            bf16 ha, la, hb, lb;
            split_bf16(va, ha, la); split_bf16(vb, hb, lb);
            hp[m] = pack2(ha, hb); lp[m] = pack2(la, lb);
        }
        uint32_t off = (uint32_t)(r * 128 + ((ck * 16) ^ ((r & 7) << 4)));
        *(uint4*)(dstAh + off) = make_uint4(hp[0], hp[1], hp[2], hp[3]);
        *(uint4*)(dstAl + off) = make_uint4(lp[0], lp[1], lp[2], lp[3]);
    }
}

// mode: 0 = normal (Cf/Ch/Cl out), 1 = coords-term + relu + LN + split (Ch/Cl = zn),
//       2 = relu + dot iw3 (impOut), 3 = 16-row max-pool + split (Ch/Cl = pooled)
__global__ __launch_bounds__(256)
void mma_gemm(const bf16* __restrict__ Ah, const bf16* __restrict__ Al,
              const bf16* __restrict__ Bh, const bf16* __restrict__ Bl,
              const float* __restrict__ bias,
              float* __restrict__ Cf, bf16* __restrict__ Ch, bf16* __restrict__ Cl,
              int strideC, int Kpad, int Kout, int doRelu, int mode,
              const float* __restrict__ ln_g, const float* __restrict__ ln_b,
              const float* __restrict__ iw3, const float* __restrict__ ib3,
              float* __restrict__ impOut,
              const int* __restrict__ rowIdx, const float* __restrict__ coords,
              const float* __restrict__ iw1full,
              const float* __restrict__ gAf, const float* __restrict__ gAw,
              const float* __restrict__ gAb)
{
    char* smem = smem_dyn_c;
    const uint32_t sbase = smem_u32(smem);
    float* Sb = (float*)smem;                 // 256 bias floats
    const uint32_t tiles0 = sbase + 1024;
    char* tiles0p = smem + 1024;
    const int tid  = threadIdx.x;
    const int wid  = tid >> 5;
    const int lane = tid & 31;
    const int wm   = wid >> 2;                // 0..1 : 64 rows
    const int wn   = wid & 3;                 // 0..3 : 64 cols
    const int bRow = blockIdx.y * 128;
    const int bCol = blockIdx.x * 256;

    Sb[tid] = bias[bCol + tid];

    // stage h1-generator operands (genA path)
    if (gAw) {
        float* w1s = (float*)(smem + EXTRA_OFF);
        float* b1s = (float*)(smem + EXTRA_OFF + 6144);
        float* fs  = (float*)(smem + EXTRA_OFF + 7168);
        for (int i = tid; i < 1536; i += 256) w1s[i] = gAw[i];
        b1s[tid] = gAb[tid];
        for (int i = tid; i < 768; i += 256) {
            int r = i / 6, k = i - r * 6;
            fs[i] = gAf[(size_t)(bRow + r) * 6 + k];
        }
        __syncthreads();
    }

    uint32_t aOff[4], bOff[4];
    {
        int khalfA = ((lane >> 4) & 1) * 16;
#pragma unroll
        for (int mf = 0; mf < 4; mf++) {
            int r = wm * 64 + mf * 16 + ((lane >> 3) & 1) * 8 + (lane & 7);
            aOff[mf] = (uint32_t)(r * 128 + (khalfA ^ ((r & 7) << 4)));
        }
        int khalfB = ((lane >> 3) & 1) * 16;
#pragma unroll
        for (int nb = 0; nb < 4; nb++) {
            int r = wn * 64 + nb * 16 + ((lane >> 4) & 1) * 8 + (lane & 7);
            bOff[nb] = (uint32_t)(r * 128 + (khalfB ^ ((r & 7) << 4)));
        }
    }

    float acc[4][8][4];
#pragma unroll
    for (int i = 0; i < 4; i++)
#pragma unroll
        for (int j = 0; j < 8; j++)
#pragma unroll
            for (int c = 0; c < 4; c++) acc[i][j][c] = 0.f;

    const int T = Kpad / 64;

    if (gAw) {
        gen_h1_tile(smem, tiles0p, tiles0p + TILE_A, 0, tid);
    } else {
        tile_cp(Ah, bRow, Kpad, 0, tiles0,            tid, 4, rowIdx);
        tile_cp(Al, bRow, Kpad, 0, tiles0 + TILE_A,   tid, 4, rowIdx);
    }
    tile_cp(Bh, bCol, Kpad, 0, tiles0 + 2*TILE_A,            tid, 8, nullptr);
    tile_cp(Bl, bCol, Kpad, 0, tiles0 + 2*TILE_A + TILE_BB,  tid, 8, nullptr);
    cp_commit();

    for (int t = 0; t < T; t++) {
        __syncthreads();
        if (t + 1 < T) {
            uint32_t st = tiles0 + ((t + 1) & 1) * STAGE_B;
            char*    sp = tiles0p + ((t + 1) & 1) * STAGE_B;
            if (gAw) {
                gen_h1_tile(smem, sp, sp + TILE_A, t + 1, tid);
            } else {
                tile_cp(Ah, bRow, Kpad, t + 1, st,            tid, 4, rowIdx);
                tile_cp(Al, bRow, Kpad, t + 1, st + TILE_A,   tid, 4, rowIdx);
            }
            tile_cp(Bh, bCol, Kpad, t + 1, st + 2*TILE_A,           tid, 8, nullptr);
            tile_cp(Bl, bCol, Kpad, t + 1, st + 2*TILE_A + TILE_BB, tid, 8, nullptr);
            cp_commit();
            cp_wait1();
        } else {
            cp_wait0();
        }
        __syncthreads();

        const uint32_t st  = tiles0 + (t & 1) * STAGE_B;
        const uint32_t tAh = st, tAl = st + TILE_A;
        const uint32_t tBh = st + 2*TILE_A, tBl = st + 2*TILE_A + TILE_BB;

#pragma unroll
        for (int ks = 0; ks < 4; ks++) {
            const uint32_t kx = (uint32_t)(ks << 5);
            uint32_t ah[4][4], al[4][4], bb[4][4];
#pragma unroll
            for (int mf = 0; mf < 4; mf++) ldsm4(ah[mf], tAh + (aOff[mf] ^ kx));
#pragma unroll
            for (int mf = 0; mf < 4; mf++) ldsm4(al[mf], tAl + (aOff[mf] ^ kx));
#pragma unroll
            for (int nb = 0; nb < 4; nb++) ldsm4(bb[nb], tBh + (bOff[nb] ^ kx));
#pragma unroll
            for (int mf = 0; mf < 4; mf++)
#pragma unroll
                for (int nf = 0; nf < 8; nf++)
                    mma16816(acc[mf][nf], ah[mf], &bb[nf >> 1][(nf & 1) * 2]);
#pragma unroll
            for (int mf = 0; mf < 4; mf++)
#pragma unroll
                for (int nf = 0; nf < 8; nf++)
                    mma16816(acc[mf][nf], al[mf], &bb[nf >> 1][(nf & 1) * 2]);
#pragma unroll
            for (int nb = 0; nb < 4; nb++) ldsm4(bb[nb], tBl + (bOff[nb] ^ kx));
#pragma unroll
            for (int mf = 0; mf < 4; mf++)
#pragma unroll
                for (int nf = 0; nf < 8; nf++)
                    mma16816(acc[mf][nf], ah[mf], &bb[nf >> 1][(nf & 1) * 2]);
        }
    }

    if (mode == 0) {
        // ---- normal epilogue ----
#pragma unroll
        for (int mf = 0; mf < 4; mf++) {
            int r0 = bRow + wm * 64 + mf * 16 + (lane >> 2);
#pragma unroll
            for (int nf = 0; nf < 8; nf++) {
                int cloc = wn * 64 + nf * 8 + (lane & 3) * 2;
                int c0 = bCol + cloc;
                float b0 = Sb[cloc], b1 = Sb[cloc + 1];
                float v0 = acc[mf][nf][0] + b0;
                float v1 = acc[mf][nf][1] + b1;
                float v2 = acc[mf][nf][2] + b0;
                float v3 = acc[mf][nf][3] + b1;
                if (doRelu) {
                    v0 = fmaxf(v0, 0.f); v1 = fmaxf(v1, 0.f);
                    v2 = fmaxf(v2, 0.f); v3 = fmaxf(v3, 0.f);
                }
                if (Cf) {
                    size_t o0 = (size_t)r0 * Kout + c0;
                    size_t o1 = (size_t)(r0 + 8) * Kout + c0;
                    *(float2*)&Cf[o0] = make_float2(v0, v1);
                    *(float2*)&Cf[o1] = make_float2(v2, v3);
                }
                if (Ch) {
                    size_t o0 = (size_t)r0 * strideC + c0;
                    size_t o1 = (size_t)(r0 + 8) * strideC + c0;
                    bf16 h0, l0, h1, l1;
                    split_bf16(v0, h0, l0); split_bf16(v1, h1, l1);
                    *(uint32_t*)&Ch[o0] = pack2(h0, h1);
                    *(uint32_t*)&Cl[o0] = pack2(l0, l1);
                    split_bf16(v2, h0, l0); split_bf16(v3, h1, l1);
                    *(uint32_t*)&Ch[o1] = pack2(h0, h1);
                    *(uint32_t*)&Cl[o1] = pack2(l0, l1);
                }
            }
        }
    } else {
        // ---- fused epilogues: stash acc+bias (raw) tile in smem ----
        __syncthreads();     // all warps done reading tile smem
        float* St  = (float*)(smem + 1024);                       // [128][RS]
        float* Xs  = (float*)(smem + 1024 + 128 * RS * 4);        // 256 (mode 2: iw3)
        float* ciw = (float*)(smem + 1024 + 128 * RS * 4 + 1024); // [4][256] (mode 1)
        float* crd = ciw + 4 * 256;                               // [128][4] (mode 1)
#pragma unroll
        for (int mf = 0; mf < 4; mf++) {
            int rl = wm * 64 + mf * 16 + (lane >> 2);
#pragma unroll
            for (int nf = 0; nf < 8; nf++) {
                int cloc = wn * 64 + nf * 8 + (lane & 3) * 2;
                float b0 = Sb[cloc], b1 = Sb[cloc + 1];
                St[rl * RS + cloc]           = acc[mf][nf][0] + b0;
                St[rl * RS + cloc + 1]       = acc[mf][nf][1] + b1;
                St[(rl + 8) * RS + cloc]     = acc[mf][nf][2] + b0;
                St[(rl + 8) * RS + cloc + 1] = acc[mf][nf][3] + b1;
            }
        }
        if (mode == 2) Xs[tid] = iw3[tid];
        if (mode == 1) {
#pragma unroll
            for (int k = 0; k < 4; k++)
                ciw[k * 256 + tid] = iw1full[(768 + k) * 256 + tid];
            if (tid < 128) {
#pragma unroll
                for (int k = 0; k < 4; k++)
                    crd[tid * 4 + k] = coords[(size_t)(bRow + tid) * 5 + 1 + k];
            }
        }
        __syncthreads();

        if (mode == 1) {
            // coords-term + relu + LayerNorm per row, write split zn
#pragma unroll
            for (int rr = 0; rr < 16; rr++) {
                int r = wid * 16 + rr;
                float c0 = crd[r*4], c1 = crd[r*4+1], c2 = crd[r*4+2], c3 = crd[r*4+3];
                float vals[8];
                float s = 0.f, s2 = 0.f;
#pragma unroll
                for (int j = 0; j < 8; j++) {
                    int c = lane + j * 32;
                    float v = St[r * RS + c]
                        + c0 * ciw[c] + c1 * ciw[256 + c]
                        + c2 * ciw[512 + c] + c3 * ciw[768 + c];
                    v = fmaxf(v, 0.f);
                    vals[j] = v; s += v; s2 += v * v;
                }
#pragma unroll
                for (int off = 16; off > 0; off >>= 1) {
                    s  += __shfl_xor_sync(0xFFFFFFFFu, s,  off);
                    s2 += __shfl_xor_sync(0xFFFFFFFFu, s2, off);
                }
                float mu  = s * (1.f / IHD);
                float var = s2 * (1.f / IHD) - mu * mu;
                float inv = rsqrtf(var + 1e-5f);
                size_t base = (size_t)(bRow + r) * IHD;
#pragma unroll
                for (int j = 0; j < 8; j++) {
                    int c = lane + j * 32;
                    float v = (vals[j] - mu) * inv * ln_g[c] + ln_b[c];
                    bf16 h, l; split_bf16(v, h, l);
                    Ch[base + c] = h; Cl[base + c] = l;
                }
            }
        } else if (mode == 2) {
            // relu + dot each row with iw3, write imp
#pragma unroll
            for (int rr = 0; rr < 16; rr++) {
                int r = wid * 16 + rr;
                float a = 0.f;
#pragma unroll
                for (int j = 0; j < 8; j++) {
                    int c = lane + j * 32;
                    a = fmaf(fmaxf(St[r * RS + c], 0.f), Xs[c], a);
                }
#pragma unroll
                for (int off = 16; off > 0; off >>= 1)
                    a += __shfl_xor_sync(0xFFFFFFFFu, a, off);
                if (lane == 0) impOut[bRow + r] = a + ib3[0];
            }
        } else {
            // mode 3: max-pool each 16-row group, split, write pooled
#pragma unroll
            for (int gi = 0; gi < 8; gi++) {
                float m = -INFINITY;
#pragma unroll
                for (int s = 0; s < KNN; s++)
                    m = fmaxf(m, St[(gi * 16 + s) * RS + tid]);
                int grp = blockIdx.y * 8 + gi;
                bf16 h, l; split_bf16(m, h, l);
                Ch[(size_t)grp * TOKD + bCol + tid] = h;
                Cl[(size_t)grp * TOKD + bCol + tid] = l;
            }
        }
    }
}

// ---------------- weight split (transpose + pad + bf16 hi/lo) ----------------
__global__ void w_split(const float* __restrict__ W, bf16* __restrict__ hi,
                        bf16* __restrict__ lo, int Kin, int Kout, int Kpad)
{
    int id = blockIdx.x * 256 + threadIdx.x;
    if (id >= Kout * Kpad) return;
    int n = id / Kpad, k = id - n * Kpad;
    float v = (k < Kin) ? W[(size_t)k * Kout + n] : 0.f;
    bf16 h, l; split_bf16(v, h, l);
    hi[id] = h; lo[id] = l;
}

// ---------------- W4i = w4 @ iw1[0:768] (fp32), split to B layout ----------------
__global__ void wi_contract(const float* __restrict__ w4, const float* __restrict__ iw1,
                            bf16* __restrict__ wih, bf16* __restrict__ wil)
{
    int id = blockIdx.x * 256 + threadIdx.x;    // 768*256
    int j = id >> 8, cp = id & 255;
    float s = 0.f;
    for (int c = 0; c < 768; c++)
        s = fmaf(w4[j * 768 + c], iw1[c * 256 + cp], s);
    bf16 h, l; split_bf16(s, h, l);
    wih[cp * 768 + j] = h; wil[cp * 768 + j] = l;
}

__global__ void bias2_kernel(const float* __restrict__ b4, const float* __restrict__ iw1,
                             const float* __restrict__ ib1, float* __restrict__ b2)
{
    int cp = threadIdx.x;
    float s = ib1[cp];
    for (int c = 0; c < 768; c++)
        s = fmaf(b4[c], iw1[c * 256 + cp], s);
    b2[cp] = s;
}

// ---------------- pack coords -> float4 ----------------
__global__ void c4_pack(const float* __restrict__ coords, float4* __restrict__ c4)
{
    int i = blockIdx.x * 256 + threadIdx.x;
    const float* p = coords + (size_t)i * 5 + 1;
    c4[i] = make_float4(p[0], p[1], p[2], p[3]);
}

// ---------------- per-batch top-128 via radix select + sort by t ----------------
__global__ __launch_bounds__(1024) void topk_kernel(
    const float* __restrict__ imp, const float* __restrict__ coords,
    const float* __restrict__ noise,
    int* __restrict__ sel_out, float* __restrict__ out_cents,
    float* __restrict__ out_masks)
{
    extern __shared__ uint32_t keys[];          // PP keys
    __shared__ uint32_t hist[256];
    __shared__ int sh_bucket, sh_target, gtCnt;
    __shared__ float selT[MT];
    __shared__ int   selI[MT];
    __shared__ int   red_i[1024];
    const int b   = blockIdx.x;
    const int tid = threadIdx.x;

    for (int i = tid; i < PP; i += 1024) {
        float v = imp[b * PP + i] + noise[b * PP + i];
        uint32_t u = __float_as_uint(v);
        keys[i] = (u & 0x80000000u) ? ~u : (u | 0x80000000u);
    }
    if (tid == 0) { sh_target = MT; gtCnt = 0; }
    __syncthreads();

    uint32_t pfx = 0, mask = 0;
#pragma unroll
    for (int B = 3; B >= 0; B--) {
        if (tid < 256) hist[tid] = 0u;
        __syncthreads();
        for (int i = tid; i < PP; i += 1024) {
            uint32_t k = keys[i];
            if ((k & mask) == pfx)
                atomicAdd(&hist[(k >> (8 * B)) & 0xFF], 1u);
        }
        __syncthreads();
        if (tid == 0) {
            int tgt = sh_target, cum = 0, bucket = 0;
            for (int v = 255; v >= 0; v--) {
                int h = (int)hist[v];
                if (cum + h >= tgt) { bucket = v; break; }
                cum += h;
            }
            sh_bucket = bucket;
            sh_target = tgt - cum;
        }
        __syncthreads();
        pfx |= ((uint32_t)sh_bucket) << (8 * B);
        mask |= 0xFFu << (8 * B);
        __syncthreads();
    }
    const uint32_t Kt = pfx;
    const int nEq = sh_target;

    for (int i = tid; i < PP; i += 1024) {
        if (keys[i] > Kt) {
            int pos = atomicAdd(&gtCnt, 1);
            selI[pos] = i;
        }
    }
    __syncthreads();
    int base = gtCnt;
    int last = -1;
    for (int r = 0; r < nEq; r++) {
        int loc = 0x7FFFFFFF;
        for (int i = tid; i < PP; i += 1024)
            if (keys[i] == Kt && i > last && i < loc) loc = i;
        red_i[tid] = loc;
        __syncthreads();
        for (int off = 512; off > 0; off >>= 1) {
            if (tid < off) red_i[tid] = min(red_i[tid], red_i[tid + off]);
            __syncthreads();
        }
        if (tid == 0) selI[base + r] = red_i[0];
        last = red_i[0];
        __syncthreads();
    }

    if (tid < MT) selT[tid] = coords[((size_t)b * PP + selI[tid]) * 5 + 4];
    __syncthreads();

    for (int kk = 2; kk <= MT; kk <<= 1) {
        for (int j = kk >> 1; j > 0; j >>= 1) {
            if (tid < MT) {
                int ixj = tid ^ j;
                if (ixj > tid) {
                    bool up = ((tid & kk) == 0);
                    float a = selT[tid], c = selT[ixj];
                    if ((a > c) == up) {
                        selT[tid] = c; selT[ixj] = a;
                        int t0 = selI[tid]; selI[tid] = selI[ixj]; selI[ixj] = t0;
                    }
                }
            }
            __syncthreads();
        }
    }

    if (tid < MT) {
        int idx = selI[tid];
        sel_out[b * MT + tid] = idx;
#pragma unroll
        for (int c = 0; c < 4; c++)
            out_cents[((size_t)b * MT + tid) * 4 + c] =
                coords[((size_t)b * PP + idx) * 5 + 1 + c];
        out_masks[b * MT + tid] = 1.0f;
    }
}

// ---------------- per-centroid 16-NN (indices only, float4 coords) ----------------
__global__ __launch_bounds__(256) void knn_kernel(
    const int* __restrict__ sel, const float4* __restrict__ c4,
    int* __restrict__ knnOut)
{
    extern __shared__ float d2[];
    __shared__ float rv[256], lminS[256];
    __shared__ int   ri[256], largS[256];
    __shared__ int   knn[KNN];
    const int g   = blockIdx.x;
    const int b   = g >> 7;
    const int tid = threadIdx.x;

    int ci = sel[g];
    float4 cc = c4[(size_t)b * PP + ci];

    {
        float bm = INFINITY; int ba = 0x7FFFFFFF;
        for (int i = tid; i < PP; i += 256) {
            float4 p = c4[(size_t)b * PP + i];
            float dx = p.x - cc.x, dy = p.y - cc.y, dz = p.z - cc.z, dt = p.w - cc.w;
            float v = dx * dx + dy * dy + dz * dz + dt * dt;
            d2[i] = v;
            if (v < bm) { bm = v; ba = i; }
        }
        lminS[tid] = bm; largS[tid] = ba;
    }
    __syncthreads();

    for (int s = 0; s < KNN; s++) {
        rv[tid] = lminS[tid]; ri[tid] = largS[tid];
        __syncthreads();
        for (int off = 128; off > 0; off >>= 1) {
            if (tid < off) {
                float ov = rv[tid + off]; int oi = ri[tid + off];
                if (ov < rv[tid] || (ov == rv[tid] && oi < ri[tid])) {
                    rv[tid] = ov; ri[tid] = oi;
                }
            }
            __syncthreads();
        }
        int win = ri[0];
        if (tid == 0) { knn[s] = win; d2[win] = INFINITY; }
        __syncthreads();
        if (tid == (win & 255)) {
            float bm = INFINITY; int ba = 0x7FFFFFFF;
            for (int i = tid; i < PP; i += 256) {
                float v = d2[i];
                if (v < bm) { bm = v; ba = i; }
            }
            lminS[tid] = bm; largS[tid] = ba;
        }
        __syncthreads();
    }

    if (tid < KNN)
        knnOut[g * KNN + tid] = b * PP + knn[tid];
}

// ---------------- launch ----------------
extern "C" void kernel_launch(void* const* d_in, const int* in_sizes, int n_in,
                              void* d_out, int out_size)
{
    const float* coords   = (const float*)d_in[0];
    const float* feats    = (const float*)d_in[1];
    const float* w1 = (const float*)d_in[3];  const float* b1 = (const float*)d_in[4];
    const float* w2 = (const float*)d_in[5];  const float* b2in = (const float*)d_in[6];
    const float* w3 = (const float*)d_in[7];  const float* b3 = (const float*)d_in[8];
    const float* w4 = (const float*)d_in[9];  const float* b4 = (const float*)d_in[10];
    const float* iw1 = (const float*)d_in[11]; const float* ib1 = (const float*)d_in[12];
    const float* ln_g = (const float*)d_in[13]; const float* ln_b = (const float*)d_in[14];
    const float* iw2 = (const float*)d_in[15]; const float* ib2 = (const float*)d_in[16];
    const float* iw3 = (const float*)d_in[17]; const float* ib3 = (const float*)d_in[18];
    const float* nw1 = (const float*)d_in[19]; const float* nb1 = (const float*)d_in[20];
    const float* nw2 = (const float*)d_in[21]; const float* nb2 = (const float*)d_in[22];
    const float* noise = (const float*)d_in[23];

    float* out        = (float*)d_out;
    float* out_tokens = out;
    float* out_cents  = out + (size_t)NGRP * TOKD;
    float* out_masks  = out_cents + (size_t)NGRP * 4;

    bf16 *znh,*znl,*h2h,*h2l,*h3h,*h3l,*ph,*pl,*t1h,*t1l;
    bf16 *w2h,*w2l,*w3h,*w3l,*w4h,*w4l,*wih,*wil,*iw2h,*iw2l,*nw1h,*nw1l,*nw2h,*nw2l;
    float *imp,*b2;
    float4* c4;
    int *sel,*knnidx;
    cudaGetSymbolAddress((void**)&znh, g_znh);  cudaGetSymbolAddress((void**)&znl, g_znl);
    cudaGetSymbolAddress((void**)&h2h, g_h2h);  cudaGetSymbolAddress((void**)&h2l, g_h2l);
    cudaGetSymbolAddress((void**)&h3h, g_h3h);  cudaGetSymbolAddress((void**)&h3l, g_h3l);
    cudaGetSymbolAddress((void**)&ph, g_ph);    cudaGetSymbolAddress((void**)&pl, g_pl);
    cudaGetSymbolAddress((void**)&t1h, g_t1h);  cudaGetSymbolAddress((void**)&t1l, g_t1l);
    cudaGetSymbolAddress((void**)&w2h, g_w2h);  cudaGetSymbolAddress((void**)&w2l, g_w2l);
    cudaGetSymbolAddress((void**)&w3h, g_w3h);  cudaGetSymbolAddress((void**)&w3l, g_w3l);
    cudaGetSymbolAddress((void**)&w4h, g_w4h);  cudaGetSymbolAddress((void**)&w4l, g_w4l);
    cudaGetSymbolAddress((void**)&wih, g_wih);  cudaGetSymbolAddress((void**)&wil, g_wil);
    cudaGetSymbolAddress((void**)&iw2h, g_iw2h); cudaGetSymbolAddress((void**)&iw2l, g_iw2l);
    cudaGetSymbolAddress((void**)&nw1h, g_nw1h); cudaGetSymbolAddress((void**)&nw1l, g_nw1l);
    cudaGetSymbolAddress((void**)&nw2h, g_nw2h); cudaGetSymbolAddress((void**)&nw2l, g_nw2l);
    cudaGetSymbolAddress((void**)&imp, g_imp);
    cudaGetSymbolAddress((void**)&b2,  g_b2);
    cudaGetSymbolAddress((void**)&c4,  g_c4);
    cudaGetSymbolAddress((void**)&sel, g_sel);
    cudaGetSymbolAddress((void**)&knnidx, g_knn);

    cudaFuncSetAttribute(mma_gemm,
        cudaFuncAttributeMaxDynamicSharedMemorySize, MMA_SMEM);
    cudaFuncSetAttribute(topk_kernel,
        cudaFuncAttributeMaxDynamicSharedMemorySize, PP * sizeof(uint32_t));
    cudaFuncSetAttribute(knn_kernel,
        cudaFuncAttributeMaxDynamicSharedMemorySize, PP * sizeof(float));

    // prep
    c4_pack<<<NPT/256, 256>>>(coords, c4);
    w_split<<<(512*256 + 255)/256, 256>>>(w2, w2h, w2l, 256, 512, 256);
    w_split<<<(768*512 + 255)/256, 256>>>(w3, w3h, w3l, 512, 768, 512);
    w_split<<<(768*768 + 255)/256, 256>>>(w4, w4h, w4l, 768, 768, 768);
    wi_contract<<<768, 256>>>(w4, iw1, wih, wil);

    // L2 GEMM with fused h1 generation (feats -> h1 -> h2)
    mma_gemm<<<dim3(2, NPT/128), 256, MMA_SMEM>>>(nullptr, nullptr, w2h, w2l, b2in,
        nullptr, h2h, h2l, 512, 256, 512, 1, 0,
        nullptr, nullptr, nullptr, nullptr, nullptr, nullptr, nullptr, nullptr,
        feats, w1, b1);

    bias2_kernel<<<1, 256>>>(b4, iw1, ib1, b2);
    w_split<<<(256*256 + 255)/256, 256>>>(iw2, iw2h, iw2l, 256, 256, 256);
    w_split<<<(768*768 + 255)/256, 256>>>(nw1, nw1h, nw1l, 768, 768, 768);
    w_split<<<(768*768 + 255)/256, 256>>>(nw2, nw2h, nw2l, 768, 768, 768);

    // L3 GEMM (h2 -> h3)
    mma_gemm<<<dim3(3, NPT/128), 256, MMA_SMEM>>>(h2h, h2l, w3h, w3l, b3,
        nullptr, h3h, h3l, 768, 512, 768, 1, 0,
        nullptr, nullptr, nullptr, nullptr, nullptr, nullptr, nullptr, nullptr,
        nullptr, nullptr, nullptr);

    // importance head: h3 @ W4i + coords term, fused relu+LN+split -> zn
    mma_gemm<<<dim3(1, NPT/128), 256, MMA_SMEM>>>(h3h, h3l, wih, wil, b2,
        nullptr, znh, znl, 0, 768, 256, 0, 1,
        ln_g, ln_b, nullptr, nullptr, nullptr, nullptr, coords, iw1,
        nullptr, nullptr, nullptr);
    // zn @ iw2, fused relu + iw3 dot -> imp
    mma_gemm<<<dim3(1, NPT/128), 256, MMA_SMEM>>>(znh, znl, iw2h, iw2l, ib2,
        nullptr, nullptr, nullptr, 0, 256, 256, 0, 2,
        nullptr, nullptr, iw3, ib3, imp, nullptr, nullptr, nullptr,
        nullptr, nullptr, nullptr);

    // radix-select top-128 + sort + cents/masks
    topk_kernel<<<BSZ, 1024, PP * sizeof(uint32_t)>>>(
        imp, coords, noise, sel, out_cents, out_masks);
    // knn indices (packed coords)
    knn_kernel<<<NGRP, 256, PP * sizeof(float)>>>(sel, c4, knnidx);

    // gathered L4 over neighbor rows only, fused 16-row max-pool + split -> pooled
    mma_gemm<<<dim3(3, NGATH/128), 256, MMA_SMEM>>>(h3h, h3l, w4h, w4l, b4,
        nullptr, ph, pl, 0, 768, 768, 0, 3,
        nullptr, nullptr, nullptr, nullptr, nullptr, knnidx, nullptr, nullptr,
        nullptr, nullptr, nullptr);

    // token MLP
    mma_gemm<<<dim3(3, NGRP/128), 256, MMA_SMEM>>>(ph, pl, nw1h, nw1l, nb1,
        nullptr, t1h, t1l, 768, 768, 768, 1, 0,
        nullptr, nullptr, nullptr, nullptr, nullptr, nullptr, nullptr, nullptr,
        nullptr, nullptr, nullptr);
    mma_gemm<<<dim3(3, NGRP/128), 256, MMA_SMEM>>>(t1h, t1l, nw2h, nw2l, nb2,
        out_tokens, nullptr, nullptr, 0, 768, 768, 0, 0,
        nullptr, nullptr, nullptr, nullptr, nullptr, nullptr, nullptr, nullptr,
        nullptr, nullptr, nullptr);
}